// round 8
// baseline (speedup 1.0000x reference)
#include <cuda_runtime.h>
#include <cuda_bf16.h>
#include <math.h>
#include <stdint.h>

#define BB 4
#define LL 2048
#define DD 1024
#define HH 16
#define HDIM 64
#define NROWS (BB * LL)   // 8192

// ---------------- scratch ----------------
__device__ float g_h[NROWS * DD];     // LN(x) fp32 (residual)
__device__ float g_y[NROWS * DD];     // O-proj out
__device__ unsigned char g_mask[NROWS];
__device__ __nv_bfloat16 g_hHi[NROWS * DD];
__device__ __nv_bfloat16 g_hLo[NROWS * DD];
__device__ __nv_bfloat16 g_aHi[NROWS * DD];   // attention out hi/lo (B,L,D)
__device__ __nv_bfloat16 g_aLo[NROWS * DD];
__device__ __nv_bfloat16 g_wHi[4][DD * DD];
__device__ __nv_bfloat16 g_wLo[4][DD * DD];
__device__ __nv_bfloat16 g_qHi[NROWS * DD];   // (B,H,L,HD)
__device__ __nv_bfloat16 g_qLo[NROWS * DD];
__device__ __nv_bfloat16 g_kHi[NROWS * DD];
__device__ __nv_bfloat16 g_kLo[NROWS * DD];
__device__ __nv_bfloat16 g_vHi[NROWS * DD];
__device__ __nv_bfloat16 g_vLo[NROWS * DD];

// ---------------- helpers ----------------
__device__ __forceinline__ uint32_t smem_u32(const void* p) {
    uint32_t a;
    asm("{ .reg .u64 t; cvta.to.shared.u64 t, %1; cvt.u32.u64 %0, t; }" : "=r"(a) : "l"(p));
    return a;
}
__device__ __forceinline__ void ldsm_x4(uint32_t& d0, uint32_t& d1, uint32_t& d2, uint32_t& d3,
                                        uint32_t addr) {
    asm volatile("ldmatrix.sync.aligned.m8n8.x4.shared.b16 {%0,%1,%2,%3}, [%4];"
                 : "=r"(d0), "=r"(d1), "=r"(d2), "=r"(d3) : "r"(addr));
}
__device__ __forceinline__ void ldsm_x4t(uint32_t& d0, uint32_t& d1, uint32_t& d2, uint32_t& d3,
                                         uint32_t addr) {
    asm volatile("ldmatrix.sync.aligned.m8n8.x4.trans.shared.b16 {%0,%1,%2,%3}, [%4];"
                 : "=r"(d0), "=r"(d1), "=r"(d2), "=r"(d3) : "r"(addr));
}
__device__ __forceinline__ void mma16816(float* c, const uint32_t* a, const uint32_t* b) {
    asm volatile(
        "mma.sync.aligned.m16n8k16.row.col.f32.bf16.bf16.f32 "
        "{%0,%1,%2,%3}, {%4,%5,%6,%7}, {%8,%9}, {%0,%1,%2,%3};"
        : "+f"(c[0]), "+f"(c[1]), "+f"(c[2]), "+f"(c[3])
        : "r"(a[0]), "r"(a[1]), "r"(a[2]), "r"(a[3]), "r"(b[0]), "r"(b[1]));
}
__device__ __forceinline__ float ex2(float x) {
    float y;
    asm("ex2.approx.ftz.f32 %0, %1;" : "=f"(y) : "f"(x));
    return y;
}
#define CP_ASYNC16(dst, src) \
    asm volatile("cp.async.cg.shared.global [%0], [%1], 16;" :: "r"(dst), "l"(src))
#define CP_COMMIT() asm volatile("cp.async.commit_group;")
#define CP_WAIT1()  asm volatile("cp.async.wait_group 1;")
#define CP_WAIT0()  asm volatile("cp.async.wait_group 0;")

__device__ __forceinline__ uint32_t sw128(uint32_t off) {
    return off ^ ((off >> 3) & 0x70u);
}
__device__ __forceinline__ void split2(float a, float b, uint32_t& hi, uint32_t& lo) {
    __nv_bfloat16 ha = __float2bfloat16_rn(a), hb = __float2bfloat16_rn(b);
    float ra = a - __bfloat162float(ha), rb = b - __bfloat162float(hb);
    __nv_bfloat162 h2; h2.x = ha; h2.y = hb;
    __nv_bfloat162 l2; l2.x = __float2bfloat16_rn(ra); l2.y = __float2bfloat16_rn(rb);
    hi = *(uint32_t*)&h2;
    lo = *(uint32_t*)&l2;
}

// ---------------- padding-mask canonicalization ----------------
__global__ void convert_mask_kernel(const unsigned char* __restrict__ pm) {
    __shared__ int fz0, fz3;
    int tid = threadIdx.x;
    if (tid == 0) { fz0 = 0; fz3 = 0; }
    __syncthreads();
    int z0 = 0, z3 = 0;
    for (int j = tid; j < NROWS; j += blockDim.x) {
        unsigned char v = pm[j];
        if (v) {
            if ((j & 3) == 0) z0 = 1;
            if ((j & 3) == 3) z3 = 1;
        }
    }
    if (z0) atomicOr(&fz0, 1);
    if (z3) atomicOr(&fz3, 1);
    __syncthreads();
    int mode;
    if (!fz3) mode = fz0 ? 3 : 0;
    else      mode = fz0 ? 1 : 2;
    for (int i = tid; i < NROWS; i += blockDim.x) {
        unsigned char r;
        if (mode == 0)      r = 0;
        else if (mode == 1) r = (pm[i] != 0);
        else if (mode == 2) r = (((const float*)pm)[i] != 0.0f);
        else                r = (((const int*)pm)[i] != 0);
        g_mask[i] = r;
    }
}

// ---------------- fp32 -> bf16 hi/lo split, 4 weights in one launch ----------------
__global__ void split_w_kernel(const float* __restrict__ s0, const float* __restrict__ s1,
                               const float* __restrict__ s2, const float* __restrict__ s3,
                               __nv_bfloat16* __restrict__ hiB,
                               __nv_bfloat16* __restrict__ loB) {
    int w = blockIdx.y;
    const float* src = (w == 0) ? s0 : (w == 1) ? s1 : (w == 2) ? s2 : s3;
    size_t off = (size_t)w * DD * DD;
    int i = (blockIdx.x * blockDim.x + threadIdx.x) * 4;
    float4 v = *(const float4*)(src + i);
    uint32_t h01, l01, h23, l23;
    split2(v.x, v.y, h01, l01);
    split2(v.z, v.w, h23, l23);
    *(uint32_t*)(hiB + off + i) = h01; *(uint32_t*)(hiB + off + i + 2) = h23;
    *(uint32_t*)(loB + off + i) = l01; *(uint32_t*)(loB + off + i + 2) = l23;
}

// ---------------- LayerNorm (optional residual; optional fused hi/lo split) ----------------
__global__ void ln_kernel(const float* __restrict__ x, const float* __restrict__ res,
                          const float* __restrict__ gamma, const float* __restrict__ beta,
                          float* __restrict__ out,
                          __nv_bfloat16* __restrict__ outHi,
                          __nv_bfloat16* __restrict__ outLo) {
    int row = blockIdx.x;
    int tid = threadIdx.x;
    const float4* xr = (const float4*)(x + (size_t)row * DD);
    float4 v = xr[tid];
    if (res) {
        const float4* rr = (const float4*)(res + (size_t)row * DD);
        float4 r2 = rr[tid];
        v.x += r2.x; v.y += r2.y; v.z += r2.z; v.w += r2.w;
    }
    float s  = v.x + v.y + v.z + v.w;
    float ss = v.x * v.x + v.y * v.y + v.z * v.z + v.w * v.w;
    for (int off = 16; off > 0; off >>= 1) {
        s  += __shfl_down_sync(0xffffffffu, s, off);
        ss += __shfl_down_sync(0xffffffffu, ss, off);
    }
    __shared__ float rs[8], rss[8];
    __shared__ float s_mu, s_rsig;
    int wid = tid >> 5, lane = tid & 31;
    if (lane == 0) { rs[wid] = s; rss[wid] = ss; }
    __syncthreads();
    if (tid == 0) {
        float S = 0.f, SS = 0.f;
        #pragma unroll
        for (int i = 0; i < 8; i++) { S += rs[i]; SS += rss[i]; }
        float mu  = S * (1.0f / DD);
        float var = SS * (1.0f / DD) - mu * mu;
        s_mu = mu;
        s_rsig = rsqrtf(var + 1e-5f);
    }
    __syncthreads();
    float mu = s_mu, rsig = s_rsig;
    float4 gv = ((const float4*)gamma)[tid];
    float4 bv = ((const float4*)beta)[tid];
    float4 o;
    o.x = (v.x - mu) * rsig * gv.x + bv.x;
    o.y = (v.y - mu) * rsig * gv.y + bv.y;
    o.z = (v.z - mu) * rsig * gv.z + bv.z;
    o.w = (v.w - mu) * rsig * gv.w + bv.w;
    ((float4*)(out + (size_t)row * DD))[tid] = o;
    if (outHi) {
        size_t i = (size_t)row * DD + tid * 4;
        uint32_t h01, l01, h23, l23;
        split2(o.x, o.y, h01, l01);
        split2(o.z, o.w, h23, l23);
        *(uint32_t*)(outHi + i) = h01; *(uint32_t*)(outHi + i + 2) = h23;
        *(uint32_t*)(outLo + i) = l01; *(uint32_t*)(outLo + i + 2) = l23;
    }
}

// ---------------- mma.sync split-bf16 GEMM, 3-stage, single-sync mainloop ----------------
#define GSMEM (96 * 1024)

template <int MODE>
__global__ __launch_bounds__(256, 2)
void gemm_mma(const __nv_bfloat16* __restrict__ Ahi, const __nv_bfloat16* __restrict__ Alo,
              const __nv_bfloat16* __restrict__ WHiB, const __nv_bfloat16* __restrict__ WLoB,
              const float* __restrict__ b0, const float* __restrict__ b1, const float* __restrict__ b2,
              float* __restrict__ C,
              __nv_bfloat16* __restrict__ h0, __nv_bfloat16* __restrict__ l0_,
              __nv_bfloat16* __restrict__ h1, __nv_bfloat16* __restrict__ l1_,
              __nv_bfloat16* __restrict__ h2, __nv_bfloat16* __restrict__ l2_) {
    extern __shared__ char dsm[];
    __shared__ float s_bias[128];

    int tid = threadIdx.x;
    int wid = tid >> 5;
    int lane = tid & 31;
    int warp_m = wid & 3;
    int warp_n = wid >> 2;
    int rowA0 = blockIdx.y * 128;
    int colB0 = blockIdx.x * 128;
    int z = blockIdx.z;

    const __nv_bfloat16* Bhi = WHiB + (size_t)z * DD * DD;
    const __nv_bfloat16* Blo = WLoB + (size_t)z * DD * DD;
    const float* bias = (z == 0) ? b0 : (z == 1) ? b1 : b2;
    __nv_bfloat16* CHi = (z == 0) ? h0 : (z == 1) ? h1 : h2;
    __nv_bfloat16* CLo = (z == 0) ? l0_ : (z == 1) ? l1_ : l2_;

    uint32_t base = smem_u32(dsm);
    uint32_t aBase[3] = { base, base + 32768u, base + 65536u };
    uint32_t bBase[3] = { base + 16384u, base + 49152u, base + 81920u };

    if (tid < 128) s_bias[tid] = bias[colB0 + tid];

    const __nv_bfloat16* TA[3] = { Ahi, Ahi, Alo };
    const __nv_bfloat16* TB[3] = { Bhi, Blo, Bhi };

    int ldR[4], ldC[4];
    uint32_t ldSw[4];
    #pragma unroll
    for (int it = 0; it < 4; it++) {
        int lin = it * 256 + tid;
        ldR[it] = lin >> 3;
        ldC[it] = (lin & 7) * 8;
        ldSw[it] = sw128((uint32_t)(ldR[it] * 128 + (lin & 7) * 16));
    }

    auto issue = [&](int i, int s) {
        int term = i >> 4;
        int k0 = (i & 15) * 64;
        const __nv_bfloat16* Ag = TA[term];
        const __nv_bfloat16* Bg = TB[term];
        #pragma unroll
        for (int it = 0; it < 4; it++) {
            CP_ASYNC16(aBase[s] + ldSw[it], Ag + (size_t)(rowA0 + ldR[it]) * DD + k0 + ldC[it]);
            CP_ASYNC16(bBase[s] + ldSw[it], Bg + (size_t)(colB0 + ldR[it]) * DD + k0 + ldC[it]);
        }
        CP_COMMIT();
    };

    float acc[2][8][4];
    #pragma unroll
    for (int mt = 0; mt < 2; mt++)
        #pragma unroll
        for (int nt = 0; nt < 8; nt++)
            #pragma unroll
            for (int q = 0; q < 4; q++) acc[mt][nt][q] = 0.f;

    int aRow = warp_m * 32 + (lane & 15);
    int aChunkHalf = lane >> 4;
    int bRow = warp_n * 64 + (lane >> 4) * 8 + (lane & 7);
    int bChunkHalf = (lane >> 3) & 1;

    issue(0, 0);
    issue(1, 1);

    int s = 0;
    for (int i = 0; i < 48; i++) {
        if (i < 47) { CP_WAIT1(); } else { CP_WAIT0(); }
        __syncthreads();
        if (i + 2 < 48) {
            int s2 = s + 2; if (s2 >= 3) s2 -= 3;
            issue(i + 2, s2);
        }

        #pragma unroll
        for (int ks = 0; ks < 4; ks++) {
            uint32_t af[2][4];
            #pragma unroll
            for (int mt = 0; mt < 2; mt++) {
                uint32_t off = (uint32_t)((aRow + mt * 16) * 128 + (ks * 2 + aChunkHalf) * 16);
                ldsm_x4(af[mt][0], af[mt][1], af[mt][2], af[mt][3], aBase[s] + sw128(off));
            }
            uint32_t bf[8][2];
            #pragma unroll
            for (int j2 = 0; j2 < 4; j2++) {
                uint32_t off = (uint32_t)((bRow + j2 * 16) * 128 + (ks * 2 + bChunkHalf) * 16);
                uint32_t r0, r1, r2, r3;
                ldsm_x4(r0, r1, r2, r3, bBase[s] + sw128(off));
                bf[j2 * 2][0] = r0; bf[j2 * 2][1] = r1;
                bf[j2 * 2 + 1][0] = r2; bf[j2 * 2 + 1][1] = r3;
            }
            #pragma unroll
            for (int mt = 0; mt < 2; mt++)
                #pragma unroll
                for (int nt = 0; nt < 8; nt++)
                    mma16816(acc[mt][nt], af[mt], bf[nt]);
        }
        s = (s == 2) ? 0 : s + 1;
    }

    int gid = lane >> 2, tig = lane & 3;
    #pragma unroll
    for (int mt = 0; mt < 2; mt++) {
        #pragma unroll
        for (int half = 0; half < 2; half++) {
            int m = rowA0 + warp_m * 32 + mt * 16 + gid + half * 8;
            #pragma unroll
            for (int nt = 0; nt < 8; nt++) {
                int col = colB0 + warp_n * 64 + nt * 8 + tig * 2;
                float vx = acc[mt][nt][half * 2 + 0] + s_bias[col - colB0];
                float vy = acc[mt][nt][half * 2 + 1] + s_bias[col - colB0 + 1];
                if (MODE == 0) {
                    float2 v; v.x = vx; v.y = vy;
                    *(float2*)(C + (size_t)m * DD + col) = v;
                } else {
                    int b = m >> 11, l = m & 2047;
                    int hh = col >> 6, hd = col & 63;
                    size_t idx = (((size_t)(b * HH + hh)) * LL + l) * HDIM + hd;
                    uint32_t hi2, lo2;
                    split2(vx, vy, hi2, lo2);
                    *(uint32_t*)(CHi + idx) = hi2;
                    *(uint32_t*)(CLo + idx) = lo2;
                }
            }
        }
    }
}

// ---------------- tensor-core flash attention, 3-stage, single-sync ----------------
#define ASMEM (96 * 1024)

__global__ __launch_bounds__(256, 1)
void attn_mma() {
    extern __shared__ char dsm[];
    __shared__ unsigned char s_mk[3][64];

    int tid = threadIdx.x;
    int wid = tid >> 5;
    int lane = tid & 31;
    int gid = lane >> 2, tig = lane & 3;
    int qt = blockIdx.x;
    int bh = blockIdx.y;
    int b = bh >> 4, h = bh & 15;
    int qbase = qt * 128;

    uint32_t base = smem_u32(dsm);
    // stage s @ base + s*32768: Khi, Klo +8192, Vhi +16384, Vlo +24576

    const __nv_bfloat16* qHi = g_qHi + ((size_t)bh * LL + qbase) * HDIM;
    const __nv_bfloat16* qLo = g_qLo + ((size_t)bh * LL + qbase) * HDIM;

    // ---- stage Q (hi @ base, lo @ base+16384), extract to registers ----
    #pragma unroll
    for (int it = 0; it < 4; it++) {
        int c = it * 256 + tid;
        int row = c >> 3, col16 = c & 7;
        uint32_t sw = sw128((uint32_t)(row * 128 + col16 * 16));
        CP_ASYNC16(base + sw, qHi + row * HDIM + col16 * 8);
        CP_ASYNC16(base + 16384u + sw, qLo + row * HDIM + col16 * 8);
    }
    CP_COMMIT();
    CP_WAIT0();
    __syncthreads();

    uint32_t qh[4][4], ql[4][4];
    {
        int arow = wid * 16 + (lane & 15);
        int ahalf = lane >> 4;
        #pragma unroll
        for (int ks = 0; ks < 4; ks++) {
            uint32_t off = (uint32_t)(arow * 128 + (ks * 2 + ahalf) * 16);
            ldsm_x4(qh[ks][0], qh[ks][1], qh[ks][2], qh[ks][3], base + sw128(off));
            ldsm_x4(ql[ks][0], ql[ks][1], ql[ks][2], ql[ks][3], base + 16384u + sw128(off));
        }
    }
    __syncthreads();

    int ntiles = 2 * qt + 2;

    auto issue = [&](int j, int s) {
        uint32_t st = base + (uint32_t)s * 32768u;
        size_t goff = ((size_t)bh * LL + j * 64) * HDIM;
        #pragma unroll
        for (int it = 0; it < 2; it++) {
            int c = it * 256 + tid;
            int row = c >> 3, col16 = c & 7;
            uint32_t sw = sw128((uint32_t)(row * 128 + col16 * 16));
            size_t so = goff + row * HDIM + col16 * 8;
            CP_ASYNC16(st + sw,          g_kHi + so);
            CP_ASYNC16(st + 8192u + sw,  g_kLo + so);
            CP_ASYNC16(st + 16384u + sw, g_vHi + so);
            CP_ASYNC16(st + 24576u + sw, g_vLo + so);
        }
        if (tid < 64) s_mk[s][tid] = g_mask[b * LL + j * 64 + tid];
        CP_COMMIT();
    };

    float o[8][4];
    #pragma unroll
    for (int nt = 0; nt < 8; nt++)
        #pragma unroll
        for (int q = 0; q < 4; q++) o[nt][q] = 0.f;
    float m0 = -1e30f, m1 = -1e30f, l0 = 0.f, l1 = 0.f;

    const float cs = 0.125f * 1.4426950408889634f;  // 1/sqrt(HD) * log2(e)
    int qg0 = qbase + wid * 16 + gid;
    int qg1 = qg0 + 8;

    issue(0, 0);
    int issued = 1;
    if (ntiles > 1) { issue(1, 1); issued = 2; }

    int kRow = (lane >> 4) * 8 + (lane & 7);
    int kHalf = (lane >> 3) & 1;
    int vRowL = lane & 15;
    int vHalf = lane >> 4;

    int s = 0;
    for (int j = 0; j < ntiles; j++) {
        if (issued > j + 1) { CP_WAIT1(); } else { CP_WAIT0(); }
        __syncthreads();
        if (j + 2 < ntiles) {
            int s2 = s + 2; if (s2 >= 3) s2 -= 3;
            issue(j + 2, s2);
            issued++;
        }

        uint32_t stK = base + (uint32_t)s * 32768u;
        uint32_t stV = stK + 16384u;

        // ---- S = Q K^T (3-term split) ----
        float sa[8][4];
        #pragma unroll
        for (int nt = 0; nt < 8; nt++)
            #pragma unroll
            for (int q = 0; q < 4; q++) sa[nt][q] = 0.f;

        #pragma unroll
        for (int ks = 0; ks < 4; ks++) {
            uint32_t bh_[8][2], bl_[8][2];
            #pragma unroll
            for (int j2 = 0; j2 < 4; j2++) {
                uint32_t off = (uint32_t)((kRow + j2 * 16) * 128 + (ks * 2 + kHalf) * 16);
                uint32_t r0, r1, r2, r3;
                ldsm_x4(r0, r1, r2, r3, stK + sw128(off));
                bh_[j2 * 2][0] = r0; bh_[j2 * 2][1] = r1;
                bh_[j2 * 2 + 1][0] = r2; bh_[j2 * 2 + 1][1] = r3;
                ldsm_x4(r0, r1, r2, r3, stK + 8192u + sw128(off));
                bl_[j2 * 2][0] = r0; bl_[j2 * 2][1] = r1;
                bl_[j2 * 2 + 1][0] = r2; bl_[j2 * 2 + 1][1] = r3;
            }
            #pragma unroll
            for (int nt = 0; nt < 8; nt++) {
                mma16816(sa[nt], qh[ks], bh_[nt]);
                mma16816(sa[nt], qh[ks], bl_[nt]);
                mma16816(sa[nt], ql[ks], bh_[nt]);
            }
        }

        // ---- scale + masks ----
        int jbase = j * 64;
        #pragma unroll
        for (int nt = 0; nt < 8; nt++) {
            int cl = nt * 8 + tig * 2;
            int kg = jbase + cl;
            int msk0 = s_mk[s][cl];
            int msk1 = s_mk[s][cl + 1];
            float v0 = sa[nt][0] * cs, v1 = sa[nt][1] * cs;
            float v2 = sa[nt][2] * cs, v3 = sa[nt][3] * cs;
            if (kg > qg0 || msk0)     v0 = -1e30f;
            if (kg + 1 > qg0 || msk1) v1 = -1e30f;
            if (kg > qg1 || msk0)     v2 = -1e30f;
            if (kg + 1 > qg1 || msk1) v3 = -1e30f;
            sa[nt][0] = v0; sa[nt][1] = v1; sa[nt][2] = v2; sa[nt][3] = v3;
        }

        // ---- online softmax ----
        float rmax0 = -1e30f, rmax1 = -1e30f;
        #pragma unroll
        for (int nt = 0; nt < 8; nt++) {
            rmax0 = fmaxf(rmax0, fmaxf(sa[nt][0], sa[nt][1]));
            rmax1 = fmaxf(rmax1, fmaxf(sa[nt][2], sa[nt][3]));
        }
        rmax0 = fmaxf(rmax0, __shfl_xor_sync(0xffffffffu, rmax0, 1));
        rmax0 = fmaxf(rmax0, __shfl_xor_sync(0xffffffffu, rmax0, 2));
        rmax1 = fmaxf(rmax1, __shfl_xor_sync(0xffffffffu, rmax1, 1));
        rmax1 = fmaxf(rmax1, __shfl_xor_sync(0xffffffffu, rmax1, 2));
        float mn0 = fmaxf(m0, rmax0), mn1 = fmaxf(m1, rmax1);
        float f0 = ex2(m0 - mn0), f1 = ex2(m1 - mn1);
        float ps0 = 0.f, ps1 = 0.f;
        #pragma unroll
        for (int nt = 0; nt < 8; nt++) {
            float p0 = ex2(sa[nt][0] - mn0);
            float p1 = ex2(sa[nt][1] - mn0);
            float p2 = ex2(sa[nt][2] - mn1);
            float p3 = ex2(sa[nt][3] - mn1);
            ps0 += p0 + p1; ps1 += p2 + p3;
            sa[nt][0] = p0; sa[nt][1] = p1; sa[nt][2] = p2; sa[nt][3] = p3;
        }
        ps0 += __shfl_xor_sync(0xffffffffu, ps0, 1);
        ps0 += __shfl_xor_sync(0xffffffffu, ps0, 2);
        ps1 += __shfl_xor_sync(0xffffffffu, ps1, 1);
        ps1 += __shfl_xor_sync(0xffffffffu, ps1, 2);
        l0 = l0 * f0 + ps0; m0 = mn0;
        l1 = l1 * f1 + ps1; m1 = mn1;
        #pragma unroll
        for (int nt = 0; nt < 8; nt++) {
            o[nt][0] *= f0; o[nt][1] *= f0;
            o[nt][2] *= f1; o[nt][3] *= f1;
        }

        // ---- repack P to bf16 hi/lo A-fragments ----
        uint32_t phi[4][4], plo[4][4];
        #pragma unroll
        for (int ks = 0; ks < 4; ks++) {
            split2(sa[2 * ks][0],     sa[2 * ks][1],     phi[ks][0], plo[ks][0]);
            split2(sa[2 * ks][2],     sa[2 * ks][3],     phi[ks][1], plo[ks][1]);
            split2(sa[2 * ks + 1][0], sa[2 * ks + 1][1], phi[ks][2], plo[ks][2]);
            split2(sa[2 * ks + 1][2], sa[2 * ks + 1][3], phi[ks][3], plo[ks][3]);
        }

        // ---- O += P V (3-term split, V via trans ldmatrix) ----
        #pragma unroll
        for (int ks = 0; ks < 4; ks++) {
            int vrow = ks * 16 + vRowL;
            uint32_t vh_[8][2], vl_[8][2];
            #pragma unroll
            for (int g = 0; g < 4; g++) {
                uint32_t off = (uint32_t)(vrow * 128 + g * 32 + vHalf * 16);
                uint32_t r0, r1, r2, r3;
                ldsm_x4t(r0, r1, r2, r3, stV + sw128(off));
                vh_[g * 2][0] = r0; vh_[g * 2][1] = r1;
                vh_[g * 2 + 1][0] = r2; vh_[g * 2 + 1][1] = r3;
                ldsm_x4t(r0, r1, r2, r3, stV + 8192u + sw128(off));
                vl_[g * 2][0] = r0; vl_[g * 2][1] = r1;
                vl_[g * 2 + 1][0] = r2; vl_[g * 2 + 1][1] = r3;
            }
            #pragma unroll
            for (int nt = 0; nt < 8; nt++) {
                mma16816(o[nt], phi[ks], vh_[nt]);
                mma16816(o[nt], phi[ks], vl_[nt]);
                mma16816(o[nt], plo[ks], vh_[nt]);
            }
        }

        s = (s == 2) ? 0 : s + 1;
    }

    // ---- epilogue: normalize + fused hi/lo split ----
    float inv0 = 1.0f / l0, inv1 = 1.0f / l1;
    #pragma unroll
    for (int nt = 0; nt < 8; nt++) {
        int d = nt * 8 + tig * 2;
        int col = h * HDIM + d;
        size_t i0 = ((size_t)b * LL + qg0) * DD + col;
        size_t i1 = ((size_t)b * LL + qg1) * DD + col;
        uint32_t hi2, lo2;
        split2(o[nt][0] * inv0, o[nt][1] * inv0, hi2, lo2);
        *(uint32_t*)(g_aHi + i0) = hi2;
        *(uint32_t*)(g_aLo + i0) = lo2;
        split2(o[nt][2] * inv1, o[nt][3] * inv1, hi2, lo2);
        *(uint32_t*)(g_aHi + i1) = hi2;
        *(uint32_t*)(g_aLo + i1) = lo2;
    }
}

// ---------------- launch ----------------
extern "C" void kernel_launch(void* const* d_in, const int* in_sizes, int n_in,
                              void* d_out, int out_size) {
    const float* x  = (const float*)d_in[0];
    const unsigned char* pm = (const unsigned char*)d_in[1];
    const float* Wq = (const float*)d_in[3];
    const float* bq = (const float*)d_in[4];
    const float* Wk = (const float*)d_in[5];
    const float* bk = (const float*)d_in[6];
    const float* Wv = (const float*)d_in[7];
    const float* bv = (const float*)d_in[8];
    const float* Wo = (const float*)d_in[9];
    const float* bo = (const float*)d_in[10];
    const float* g_pre = (const float*)d_in[11];
    const float* b_pre = (const float*)d_in[12];
    const float* g_ln  = (const float*)d_in[13];
    const float* b_ln  = (const float*)d_in[14];
    float* out = (float*)d_out;

    float *ph, *py;
    __nv_bfloat16 *phHi, *phLo, *paHi, *paLo, *pwHi, *pwLo;
    __nv_bfloat16 *pqHi, *pqLo, *pkHi, *pkLo, *pvHi, *pvLo;
    cudaGetSymbolAddress((void**)&ph,   g_h);
    cudaGetSymbolAddress((void**)&py,   g_y);
    cudaGetSymbolAddress((void**)&phHi, g_hHi);
    cudaGetSymbolAddress((void**)&phLo, g_hLo);
    cudaGetSymbolAddress((void**)&paHi, g_aHi);
    cudaGetSymbolAddress((void**)&paLo, g_aLo);
    cudaGetSymbolAddress((void**)&pwHi, g_wHi);
    cudaGetSymbolAddress((void**)&pwLo, g_wLo);
    cudaGetSymbolAddress((void**)&pqHi, g_qHi);
    cudaGetSymbolAddress((void**)&pqLo, g_qLo);
    cudaGetSymbolAddress((void**)&pkHi, g_kHi);
    cudaGetSymbolAddress((void**)&pkLo, g_kLo);
    cudaGetSymbolAddress((void**)&pvHi, g_vHi);
    cudaGetSymbolAddress((void**)&pvLo, g_vLo);

    cudaFuncSetAttribute(gemm_mma<0>, cudaFuncAttributeMaxDynamicSharedMemorySize, GSMEM);
    cudaFuncSetAttribute(gemm_mma<1>, cudaFuncAttributeMaxDynamicSharedMemorySize, GSMEM);
    cudaFuncSetAttribute(attn_mma, cudaFuncAttributeMaxDynamicSharedMemorySize, ASMEM);

    convert_mask_kernel<<<1, 256>>>(pm);

    // pre-LN with fused hi/lo split
    ln_kernel<<<NROWS, 256>>>(x, (const float*)nullptr, g_pre, b_pre, ph, phHi, phLo);

    // weight splits, single launch: y = {Wq, Wk, Wv, Wo}
    const int nW = DD * DD;
    split_w_kernel<<<dim3(nW / 1024, 4), 256>>>(Wq, Wk, Wv, Wo, pwHi, pwLo);

    // QKV projections -> bf16 hi/lo (B,H,L,HD), single launch over z = {q,k,v}
    dim3 gqkv(DD / 128, NROWS / 128, 3);
    gemm_mma<1><<<gqkv, 256, GSMEM>>>(phHi, phLo, pwHi, pwLo,
                                      bq, bk, bv, nullptr,
                                      pqHi, pqLo, pkHi, pkLo, pvHi, pvLo);

    // tensor-core flash attention (writes aHi/aLo directly)
    attn_mma<<<dim3(LL / 128, BB * HH), 256, ASMEM>>>();

    // output projection (z=0 selects Wo slice at offset 3)
    dim3 gproj(DD / 128, NROWS / 128, 1);
    gemm_mma<0><<<gproj, 256, GSMEM>>>(paHi, paLo, pwHi + 3 * (size_t)nW, pwLo + 3 * (size_t)nW,
                                       bo, bo, bo, py,
                                       nullptr, nullptr, nullptr, nullptr, nullptr, nullptr);

    // residual + final LN
    ln_kernel<<<NROWS, 256>>>(py, ph, g_ln, b_ln, out, nullptr, nullptr);
}

// round 10
// speedup vs baseline: 1.5690x; 1.5690x over previous
#include <cuda_runtime.h>
#include <cuda_bf16.h>
#include <math.h>
#include <stdint.h>

#define BB 4
#define LL 2048
#define DD 1024
#define HH 16
#define HDIM 64
#define NROWS (BB * LL)   // 8192

// ---------------- scratch ----------------
__device__ float g_h[NROWS * DD];     // LN(x) fp32 (residual)
__device__ float g_y[NROWS * DD];     // O-proj out
__device__ unsigned char g_mask[NROWS];
__device__ __nv_bfloat16 g_hHi[NROWS * DD];
__device__ __nv_bfloat16 g_hLo[NROWS * DD];
__device__ __nv_bfloat16 g_aHi[NROWS * DD];   // attention out hi/lo (B,L,D)
__device__ __nv_bfloat16 g_aLo[NROWS * DD];
__device__ __nv_bfloat16 g_wHi[4][DD * DD];
__device__ __nv_bfloat16 g_wLo[4][DD * DD];
__device__ __nv_bfloat16 g_qHi[NROWS * DD];   // (B,H,L,HD)
__device__ __nv_bfloat16 g_qLo[NROWS * DD];
__device__ __nv_bfloat16 g_kHi[NROWS * DD];
__device__ __nv_bfloat16 g_kLo[NROWS * DD];
__device__ __nv_bfloat16 g_vHi[NROWS * DD];
__device__ __nv_bfloat16 g_vLo[NROWS * DD];

// ---------------- helpers ----------------
__device__ __forceinline__ uint32_t smem_u32(const void* p) {
    uint32_t a;
    asm("{ .reg .u64 t; cvta.to.shared.u64 t, %1; cvt.u32.u64 %0, t; }" : "=r"(a) : "l"(p));
    return a;
}
__device__ __forceinline__ void ldsm_x4(uint32_t& d0, uint32_t& d1, uint32_t& d2, uint32_t& d3,
                                        uint32_t addr) {
    asm volatile("ldmatrix.sync.aligned.m8n8.x4.shared.b16 {%0,%1,%2,%3}, [%4];"
                 : "=r"(d0), "=r"(d1), "=r"(d2), "=r"(d3) : "r"(addr));
}
__device__ __forceinline__ void ldsm_x4t(uint32_t& d0, uint32_t& d1, uint32_t& d2, uint32_t& d3,
                                         uint32_t addr) {
    asm volatile("ldmatrix.sync.aligned.m8n8.x4.trans.shared.b16 {%0,%1,%2,%3}, [%4];"
                 : "=r"(d0), "=r"(d1), "=r"(d2), "=r"(d3) : "r"(addr));
}
__device__ __forceinline__ void mma16816(float* c, const uint32_t* a, const uint32_t* b) {
    asm volatile(
        "mma.sync.aligned.m16n8k16.row.col.f32.bf16.bf16.f32 "
        "{%0,%1,%2,%3}, {%4,%5,%6,%7}, {%8,%9}, {%0,%1,%2,%3};"
        : "+f"(c[0]), "+f"(c[1]), "+f"(c[2]), "+f"(c[3])
        : "r"(a[0]), "r"(a[1]), "r"(a[2]), "r"(a[3]), "r"(b[0]), "r"(b[1]));
}
__device__ __forceinline__ float ex2(float x) {
    float y;
    asm("ex2.approx.ftz.f32 %0, %1;" : "=f"(y) : "f"(x));
    return y;
}
#define CP_ASYNC16(dst, src) \
    asm volatile("cp.async.cg.shared.global [%0], [%1], 16;" :: "r"(dst), "l"(src))
#define CP_COMMIT() asm volatile("cp.async.commit_group;")
#define CP_WAIT1()  asm volatile("cp.async.wait_group 1;")
#define CP_WAIT0()  asm volatile("cp.async.wait_group 0;")

__device__ __forceinline__ uint32_t sw128(uint32_t off) {
    return off ^ ((off >> 3) & 0x70u);
}
__device__ __forceinline__ void split2(float a, float b, uint32_t& hi, uint32_t& lo) {
    __nv_bfloat16 ha = __float2bfloat16_rn(a), hb = __float2bfloat16_rn(b);
    float ra = a - __bfloat162float(ha), rb = b - __bfloat162float(hb);
    __nv_bfloat162 h2; h2.x = ha; h2.y = hb;
    __nv_bfloat162 l2; l2.x = __float2bfloat16_rn(ra); l2.y = __float2bfloat16_rn(rb);
    hi = *(uint32_t*)&h2;
    lo = *(uint32_t*)&l2;
}

// ---------------- padding-mask canonicalization ----------------
__global__ void convert_mask_kernel(const unsigned char* __restrict__ pm) {
    __shared__ int fz0, fz3;
    int tid = threadIdx.x;
    if (tid == 0) { fz0 = 0; fz3 = 0; }
    __syncthreads();
    int z0 = 0, z3 = 0;
    for (int j = tid; j < NROWS; j += blockDim.x) {
        unsigned char v = pm[j];
        if (v) {
            if ((j & 3) == 0) z0 = 1;
            if ((j & 3) == 3) z3 = 1;
        }
    }
    if (z0) atomicOr(&fz0, 1);
    if (z3) atomicOr(&fz3, 1);
    __syncthreads();
    int mode;
    if (!fz3) mode = fz0 ? 3 : 0;
    else      mode = fz0 ? 1 : 2;
    for (int i = tid; i < NROWS; i += blockDim.x) {
        unsigned char r;
        if (mode == 0)      r = 0;
        else if (mode == 1) r = (pm[i] != 0);
        else if (mode == 2) r = (((const float*)pm)[i] != 0.0f);
        else                r = (((const int*)pm)[i] != 0);
        g_mask[i] = r;
    }
}

// ---------------- fp32 -> bf16 hi/lo split, 4 weights in one launch ----------------
__global__ void split_w_kernel(const float* __restrict__ s0, const float* __restrict__ s1,
                               const float* __restrict__ s2, const float* __restrict__ s3,
                               __nv_bfloat16* __restrict__ hiB,
                               __nv_bfloat16* __restrict__ loB) {
    int w = blockIdx.y;
    const float* src = (w == 0) ? s0 : (w == 1) ? s1 : (w == 2) ? s2 : s3;
    size_t off = (size_t)w * DD * DD;
    int i = (blockIdx.x * blockDim.x + threadIdx.x) * 4;
    float4 v = *(const float4*)(src + i);
    uint32_t h01, l01, h23, l23;
    split2(v.x, v.y, h01, l01);
    split2(v.z, v.w, h23, l23);
    *(uint32_t*)(hiB + off + i) = h01; *(uint32_t*)(hiB + off + i + 2) = h23;
    *(uint32_t*)(loB + off + i) = l01; *(uint32_t*)(loB + off + i + 2) = l23;
}

// ---------------- LayerNorm (optional residual; optional fused hi/lo split) ----------------
__global__ void ln_kernel(const float* __restrict__ x, const float* __restrict__ res,
                          const float* __restrict__ gamma, const float* __restrict__ beta,
                          float* __restrict__ out,
                          __nv_bfloat16* __restrict__ outHi,
                          __nv_bfloat16* __restrict__ outLo) {
    int row = blockIdx.x;
    int tid = threadIdx.x;
    const float4* xr = (const float4*)(x + (size_t)row * DD);
    float4 v = xr[tid];
    if (res) {
        const float4* rr = (const float4*)(res + (size_t)row * DD);
        float4 r2 = rr[tid];
        v.x += r2.x; v.y += r2.y; v.z += r2.z; v.w += r2.w;
    }
    float s  = v.x + v.y + v.z + v.w;
    float ss = v.x * v.x + v.y * v.y + v.z * v.z + v.w * v.w;
    for (int off = 16; off > 0; off >>= 1) {
        s  += __shfl_down_sync(0xffffffffu, s, off);
        ss += __shfl_down_sync(0xffffffffu, ss, off);
    }
    __shared__ float rs[8], rss[8];
    __shared__ float s_mu, s_rsig;
    int wid = tid >> 5, lane = tid & 31;
    if (lane == 0) { rs[wid] = s; rss[wid] = ss; }
    __syncthreads();
    if (tid == 0) {
        float S = 0.f, SS = 0.f;
        #pragma unroll
        for (int i = 0; i < 8; i++) { S += rs[i]; SS += rss[i]; }
        float mu  = S * (1.0f / DD);
        float var = SS * (1.0f / DD) - mu * mu;
        s_mu = mu;
        s_rsig = rsqrtf(var + 1e-5f);
    }
    __syncthreads();
    float mu = s_mu, rsig = s_rsig;
    float4 gv = ((const float4*)gamma)[tid];
    float4 bv = ((const float4*)beta)[tid];
    float4 o;
    o.x = (v.x - mu) * rsig * gv.x + bv.x;
    o.y = (v.y - mu) * rsig * gv.y + bv.y;
    o.z = (v.z - mu) * rsig * gv.z + bv.z;
    o.w = (v.w - mu) * rsig * gv.w + bv.w;
    ((float4*)(out + (size_t)row * DD))[tid] = o;
    if (outHi) {
        size_t i = (size_t)row * DD + tid * 4;
        uint32_t h01, l01, h23, l23;
        split2(o.x, o.y, h01, l01);
        split2(o.z, o.w, h23, l23);
        *(uint32_t*)(outHi + i) = h01; *(uint32_t*)(outHi + i + 2) = h23;
        *(uint32_t*)(outLo + i) = l01; *(uint32_t*)(outLo + i + 2) = l23;
    }
}

// ---------------- mma.sync split-bf16 GEMM (R6 champion structure) ----------------
#define GSMEM (64 * 1024)

template <int MODE>
__global__ __launch_bounds__(256, 2)
void gemm_mma(const __nv_bfloat16* __restrict__ Ahi, const __nv_bfloat16* __restrict__ Alo,
              const __nv_bfloat16* __restrict__ WHiB, const __nv_bfloat16* __restrict__ WLoB,
              const float* __restrict__ b0, const float* __restrict__ b1, const float* __restrict__ b2,
              float* __restrict__ C,
              __nv_bfloat16* __restrict__ h0, __nv_bfloat16* __restrict__ l0_,
              __nv_bfloat16* __restrict__ h1, __nv_bfloat16* __restrict__ l1_,
              __nv_bfloat16* __restrict__ h2, __nv_bfloat16* __restrict__ l2_) {
    extern __shared__ char dsm[];
    __shared__ float s_bias[128];

    int tid = threadIdx.x;
    int wid = tid >> 5;
    int lane = tid & 31;
    int warp_m = wid & 3;
    int warp_n = wid >> 2;
    int rowA0 = blockIdx.y * 128;
    int colB0 = blockIdx.x * 128;
    int z = blockIdx.z;

    const __nv_bfloat16* Bhi = WHiB + (size_t)z * DD * DD;
    const __nv_bfloat16* Blo = WLoB + (size_t)z * DD * DD;
    const float* bias = (z == 0) ? b0 : (z == 1) ? b1 : b2;
    __nv_bfloat16* CHi = (z == 0) ? h0 : (z == 1) ? h1 : h2;
    __nv_bfloat16* CLo = (z == 0) ? l0_ : (z == 1) ? l1_ : l2_;

    uint32_t base = smem_u32(dsm);
    uint32_t aBase[2] = { base, base + 32768u };
    uint32_t bBase[2] = { base + 16384u, base + 49152u };

    if (tid < 128) s_bias[tid] = bias[colB0 + tid];

    const __nv_bfloat16* TA[3] = { Ahi, Ahi, Alo };
    const __nv_bfloat16* TB[3] = { Bhi, Blo, Bhi };

    int ldR[4], ldC[4];
    uint32_t ldSw[4];
    #pragma unroll
    for (int it = 0; it < 4; it++) {
        int lin = it * 256 + tid;
        ldR[it] = lin >> 3;
        ldC[it] = (lin & 7) * 8;
        ldSw[it] = sw128((uint32_t)(ldR[it] * 128 + (lin & 7) * 16));
    }

    auto issue = [&](int i, int s) {
        int term = i >> 4;
        int k0 = (i & 15) * 64;
        const __nv_bfloat16* Ag = TA[term];
        const __nv_bfloat16* Bg = TB[term];
        #pragma unroll
        for (int it = 0; it < 4; it++) {
            CP_ASYNC16(aBase[s] + ldSw[it], Ag + (size_t)(rowA0 + ldR[it]) * DD + k0 + ldC[it]);
            CP_ASYNC16(bBase[s] + ldSw[it], Bg + (size_t)(colB0 + ldR[it]) * DD + k0 + ldC[it]);
        }
        CP_COMMIT();
    };

    float acc[2][8][4];
    #pragma unroll
    for (int mt = 0; mt < 2; mt++)
        #pragma unroll
        for (int nt = 0; nt < 8; nt++)
            #pragma unroll
            for (int q = 0; q < 4; q++) acc[mt][nt][q] = 0.f;

    int aRow = warp_m * 32 + (lane & 15);
    int aChunkHalf = lane >> 4;
    int bRow = warp_n * 64 + (lane >> 4) * 8 + (lane & 7);
    int bChunkHalf = (lane >> 3) & 1;

    issue(0, 0);

    for (int i = 0; i < 48; i++) {
        int s = i & 1;
        if (i < 47) issue(i + 1, s ^ 1);
        if (i < 47) { CP_WAIT1(); } else { CP_WAIT0(); }
        __syncthreads();

        #pragma unroll
        for (int ks = 0; ks < 4; ks++) {
            uint32_t af[2][4];
            #pragma unroll
            for (int mt = 0; mt < 2; mt++) {
                uint32_t off = (uint32_t)((aRow + mt * 16) * 128 + (ks * 2 + aChunkHalf) * 16);
                ldsm_x4(af[mt][0], af[mt][1], af[mt][2], af[mt][3], aBase[s] + sw128(off));
            }
            uint32_t bf[8][2];
            #pragma unroll
            for (int j2 = 0; j2 < 4; j2++) {
                uint32_t off = (uint32_t)((bRow + j2 * 16) * 128 + (ks * 2 + bChunkHalf) * 16);
                uint32_t r0, r1, r2, r3;
                ldsm_x4(r0, r1, r2, r3, bBase[s] + sw128(off));
                bf[j2 * 2][0] = r0; bf[j2 * 2][1] = r1;
                bf[j2 * 2 + 1][0] = r2; bf[j2 * 2 + 1][1] = r3;
            }
            #pragma unroll
            for (int mt = 0; mt < 2; mt++)
                #pragma unroll
                for (int nt = 0; nt < 8; nt++)
                    mma16816(acc[mt][nt], af[mt], bf[nt]);
        }
        __syncthreads();
    }

    int gid = lane >> 2, tig = lane & 3;
    #pragma unroll
    for (int mt = 0; mt < 2; mt++) {
        #pragma unroll
        for (int half = 0; half < 2; half++) {
            int m = rowA0 + warp_m * 32 + mt * 16 + gid + half * 8;
            #pragma unroll
            for (int nt = 0; nt < 8; nt++) {
                int col = colB0 + warp_n * 64 + nt * 8 + tig * 2;
                float vx = acc[mt][nt][half * 2 + 0] + s_bias[col - colB0];
                float vy = acc[mt][nt][half * 2 + 1] + s_bias[col - colB0 + 1];
                if (MODE == 0) {
                    float2 v; v.x = vx; v.y = vy;
                    *(float2*)(C + (size_t)m * DD + col) = v;
                } else {
                    int b = m >> 11, l = m & 2047;
                    int hh = col >> 6, hd = col & 63;
                    size_t idx = (((size_t)(b * HH + hh)) * LL + l) * HDIM + hd;
                    uint32_t hi2, lo2;
                    split2(vx, vy, hi2, lo2);
                    *(uint32_t*)(CHi + idx) = hi2;
                    *(uint32_t*)(CLo + idx) = lo2;
                }
            }
        }
    }
}

// ---------------- tensor-core flash attention (R6 structure + ex2) ----------------
#define ASMEM (64 * 1024)

__global__ __launch_bounds__(256, 1)
void attn_mma() {
    extern __shared__ char dsm[];
    __shared__ unsigned char s_mk[2][64];

    int tid = threadIdx.x;
    int wid = tid >> 5;
    int lane = tid & 31;
    int gid = lane >> 2, tig = lane & 3;
    int qt = blockIdx.x;
    int bh = blockIdx.y;
    int b = bh >> 4, h = bh & 15;
    int qbase = qt * 128;

    uint32_t base = smem_u32(dsm);
    // stage s: Khi @ s*32768, Klo +8192, Vhi +16384, Vlo +24576

    const __nv_bfloat16* qHi = g_qHi + ((size_t)bh * LL + qbase) * HDIM;
    const __nv_bfloat16* qLo = g_qLo + ((size_t)bh * LL + qbase) * HDIM;

    // ---- stage Q (hi @ base, lo @ base+16384), extract to registers ----
    #pragma unroll
    for (int it = 0; it < 4; it++) {
        int c = it * 256 + tid;
        int row = c >> 3, col16 = c & 7;
        uint32_t sw = sw128((uint32_t)(row * 128 + col16 * 16));
        CP_ASYNC16(base + sw, qHi + row * HDIM + col16 * 8);
        CP_ASYNC16(base + 16384u + sw, qLo + row * HDIM + col16 * 8);
    }
    CP_COMMIT();
    CP_WAIT0();
    __syncthreads();

    uint32_t qh[4][4], ql[4][4];
    {
        int arow = wid * 16 + (lane & 15);
        int ahalf = lane >> 4;
        #pragma unroll
        for (int ks = 0; ks < 4; ks++) {
            uint32_t off = (uint32_t)(arow * 128 + (ks * 2 + ahalf) * 16);
            ldsm_x4(qh[ks][0], qh[ks][1], qh[ks][2], qh[ks][3], base + sw128(off));
            ldsm_x4(ql[ks][0], ql[ks][1], ql[ks][2], ql[ks][3], base + 16384u + sw128(off));
        }
    }
    __syncthreads();

    int ntiles = 2 * qt + 2;

    auto issue = [&](int j, int s) {
        uint32_t st = base + (uint32_t)s * 32768u;
        size_t goff = ((size_t)bh * LL + j * 64) * HDIM;
        #pragma unroll
        for (int it = 0; it < 2; it++) {
            int c = it * 256 + tid;
            int row = c >> 3, col16 = c & 7;
            uint32_t sw = sw128((uint32_t)(row * 128 + col16 * 16));
            size_t so = goff + row * HDIM + col16 * 8;
            CP_ASYNC16(st + sw,          g_kHi + so);
            CP_ASYNC16(st + 8192u + sw,  g_kLo + so);
            CP_ASYNC16(st + 16384u + sw, g_vHi + so);
            CP_ASYNC16(st + 24576u + sw, g_vLo + so);
        }
        if (tid < 64) s_mk[s][tid] = g_mask[b * LL + j * 64 + tid];
        CP_COMMIT();
    };

    float o[8][4];
    #pragma unroll
    for (int nt = 0; nt < 8; nt++)
        #pragma unroll
        for (int q = 0; q < 4; q++) o[nt][q] = 0.f;
    float m0 = -1e30f, m1 = -1e30f, l0 = 0.f, l1 = 0.f;

    const float cs = 0.125f * 1.4426950408889634f;  // 1/sqrt(HD) * log2(e)
    int qg0 = qbase + wid * 16 + gid;
    int qg1 = qg0 + 8;

    issue(0, 0);
    int issued = 1;
    if (ntiles > 1) { issue(1, 1); issued = 2; }

    int kRow = (lane >> 4) * 8 + (lane & 7);
    int kHalf = (lane >> 3) & 1;
    int vRowL = lane & 15;
    int vHalf = lane >> 4;

    for (int j = 0; j < ntiles; j++) {
        int s = j & 1;
        if (issued > j + 1) { CP_WAIT1(); } else { CP_WAIT0(); }
        __syncthreads();

        uint32_t stK = base + (uint32_t)s * 32768u;
        uint32_t stV = stK + 16384u;

        // ---- S = Q K^T (3-term split) ----
        float sa[8][4];
        #pragma unroll
        for (int nt = 0; nt < 8; nt++)
            #pragma unroll
            for (int q = 0; q < 4; q++) sa[nt][q] = 0.f;

        #pragma unroll
        for (int ks = 0; ks < 4; ks++) {
            uint32_t bh_[8][2], bl_[8][2];
            #pragma unroll
            for (int j2 = 0; j2 < 4; j2++) {
                uint32_t off = (uint32_t)((kRow + j2 * 16) * 128 + (ks * 2 + kHalf) * 16);
                uint32_t r0, r1, r2, r3;
                ldsm_x4(r0, r1, r2, r3, stK + sw128(off));
                bh_[j2 * 2][0] = r0; bh_[j2 * 2][1] = r1;
                bh_[j2 * 2 + 1][0] = r2; bh_[j2 * 2 + 1][1] = r3;
                ldsm_x4(r0, r1, r2, r3, stK + 8192u + sw128(off));
                bl_[j2 * 2][0] = r0; bl_[j2 * 2][1] = r1;
                bl_[j2 * 2 + 1][0] = r2; bl_[j2 * 2 + 1][1] = r3;
            }
            #pragma unroll
            for (int nt = 0; nt < 8; nt++) {
                mma16816(sa[nt], qh[ks], bh_[nt]);
                mma16816(sa[nt], qh[ks], bl_[nt]);
                mma16816(sa[nt], ql[ks], bh_[nt]);
            }
        }

        // ---- scale + masks ----
        int jbase = j * 64;
        #pragma unroll
        for (int nt = 0; nt < 8; nt++) {
            int cl = nt * 8 + tig * 2;
            int kg = jbase + cl;
            int msk0 = s_mk[s][cl];
            int msk1 = s_mk[s][cl + 1];
            float v0 = sa[nt][0] * cs, v1 = sa[nt][1] * cs;
            float v2 = sa[nt][2] * cs, v3 = sa[nt][3] * cs;
            if (kg > qg0 || msk0)     v0 = -1e30f;
            if (kg + 1 > qg0 || msk1) v1 = -1e30f;
            if (kg > qg1 || msk0)     v2 = -1e30f;
            if (kg + 1 > qg1 || msk1) v3 = -1e30f;
            sa[nt][0] = v0; sa[nt][1] = v1; sa[nt][2] = v2; sa[nt][3] = v3;
        }

        // ---- online softmax (MUFU ex2) ----
        float rmax0 = -1e30f, rmax1 = -1e30f;
        #pragma unroll
        for (int nt = 0; nt < 8; nt++) {
            rmax0 = fmaxf(rmax0, fmaxf(sa[nt][0], sa[nt][1]));
            rmax1 = fmaxf(rmax1, fmaxf(sa[nt][2], sa[nt][3]));
        }
        rmax0 = fmaxf(rmax0, __shfl_xor_sync(0xffffffffu, rmax0, 1));
        rmax0 = fmaxf(rmax0, __shfl_xor_sync(0xffffffffu, rmax0, 2));
        rmax1 = fmaxf(rmax1, __shfl_xor_sync(0xffffffffu, rmax1, 1));
        rmax1 = fmaxf(rmax1, __shfl_xor_sync(0xffffffffu, rmax1, 2));
        float mn0 = fmaxf(m0, rmax0), mn1 = fmaxf(m1, rmax1);
        float f0 = ex2(m0 - mn0), f1 = ex2(m1 - mn1);
        float ps0 = 0.f, ps1 = 0.f;
        #pragma unroll
        for (int nt = 0; nt < 8; nt++) {
            float p0 = ex2(sa[nt][0] - mn0);
            float p1 = ex2(sa[nt][1] - mn0);
            float p2 = ex2(sa[nt][2] - mn1);
            float p3 = ex2(sa[nt][3] - mn1);
            ps0 += p0 + p1; ps1 += p2 + p3;
            sa[nt][0] = p0; sa[nt][1] = p1; sa[nt][2] = p2; sa[nt][3] = p3;
        }
        ps0 += __shfl_xor_sync(0xffffffffu, ps0, 1);
        ps0 += __shfl_xor_sync(0xffffffffu, ps0, 2);
        ps1 += __shfl_xor_sync(0xffffffffu, ps1, 1);
        ps1 += __shfl_xor_sync(0xffffffffu, ps1, 2);
        l0 = l0 * f0 + ps0; m0 = mn0;
        l1 = l1 * f1 + ps1; m1 = mn1;
        #pragma unroll
        for (int nt = 0; nt < 8; nt++) {
            o[nt][0] *= f0; o[nt][1] *= f0;
            o[nt][2] *= f1; o[nt][3] *= f1;
        }

        // ---- repack P to bf16 hi/lo A-fragments ----
        uint32_t phi[4][4], plo[4][4];
        #pragma unroll
        for (int ks = 0; ks < 4; ks++) {
            split2(sa[2 * ks][0],     sa[2 * ks][1],     phi[ks][0], plo[ks][0]);
            split2(sa[2 * ks][2],     sa[2 * ks][3],     phi[ks][1], plo[ks][1]);
            split2(sa[2 * ks + 1][0], sa[2 * ks + 1][1], phi[ks][2], plo[ks][2]);
            split2(sa[2 * ks + 1][2], sa[2 * ks + 1][3], phi[ks][3], plo[ks][3]);
        }

        // ---- O += P V (3-term split, V via trans ldmatrix) ----
        #pragma unroll
        for (int ks = 0; ks < 4; ks++) {
            int vrow = ks * 16 + vRowL;
            uint32_t vh_[8][2], vl_[8][2];
            #pragma unroll
            for (int g = 0; g < 4; g++) {
                uint32_t off = (uint32_t)(vrow * 128 + g * 32 + vHalf * 16);
                uint32_t r0, r1, r2, r3;
                ldsm_x4t(r0, r1, r2, r3, stV + sw128(off));
                vh_[g * 2][0] = r0; vh_[g * 2][1] = r1;
                vh_[g * 2 + 1][0] = r2; vh_[g * 2 + 1][1] = r3;
                ldsm_x4t(r0, r1, r2, r3, stV + 8192u + sw128(off));
                vl_[g * 2][0] = r0; vl_[g * 2][1] = r1;
                vl_[g * 2 + 1][0] = r2; vl_[g * 2 + 1][1] = r3;
            }
            #pragma unroll
            for (int nt = 0; nt < 8; nt++) {
                mma16816(o[nt], phi[ks], vh_[nt]);
                mma16816(o[nt], phi[ks], vl_[nt]);
                mma16816(o[nt], plo[ks], vh_[nt]);
            }
        }

        __syncthreads();
        if (j + 2 < ntiles) { issue(j + 2, s); issued++; }
    }

    // ---- epilogue: normalize + fused hi/lo split ----
    float inv0 = 1.0f / l0, inv1 = 1.0f / l1;
    #pragma unroll
    for (int nt = 0; nt < 8; nt++) {
        int d = nt * 8 + tig * 2;
        int col = h * HDIM + d;
        size_t i0 = ((size_t)b * LL + qg0) * DD + col;
        size_t i1 = ((size_t)b * LL + qg1) * DD + col;
        uint32_t hi2, lo2;
        split2(o[nt][0] * inv0, o[nt][1] * inv0, hi2, lo2);
        *(uint32_t*)(g_aHi + i0) = hi2;
        *(uint32_t*)(g_aLo + i0) = lo2;
        split2(o[nt][2] * inv1, o[nt][3] * inv1, hi2, lo2);
        *(uint32_t*)(g_aHi + i1) = hi2;
        *(uint32_t*)(g_aLo + i1) = lo2;
    }
}

// ---------------- launch ----------------
extern "C" void kernel_launch(void* const* d_in, const int* in_sizes, int n_in,
                              void* d_out, int out_size) {
    const float* x  = (const float*)d_in[0];
    const unsigned char* pm = (const unsigned char*)d_in[1];
    const float* Wq = (const float*)d_in[3];
    const float* bq = (const float*)d_in[4];
    const float* Wk = (const float*)d_in[5];
    const float* bk = (const float*)d_in[6];
    const float* Wv = (const float*)d_in[7];
    const float* bv = (const float*)d_in[8];
    const float* Wo = (const float*)d_in[9];
    const float* bo = (const float*)d_in[10];
    const float* g_pre = (const float*)d_in[11];
    const float* b_pre = (const float*)d_in[12];
    const float* g_ln  = (const float*)d_in[13];
    const float* b_ln  = (const float*)d_in[14];
    float* out = (float*)d_out;

    float *ph, *py;
    __nv_bfloat16 *phHi, *phLo, *paHi, *paLo, *pwHi, *pwLo;
    __nv_bfloat16 *pqHi, *pqLo, *pkHi, *pkLo, *pvHi, *pvLo;
    cudaGetSymbolAddress((void**)&ph,   g_h);
    cudaGetSymbolAddress((void**)&py,   g_y);
    cudaGetSymbolAddress((void**)&phHi, g_hHi);
    cudaGetSymbolAddress((void**)&phLo, g_hLo);
    cudaGetSymbolAddress((void**)&paHi, g_aHi);
    cudaGetSymbolAddress((void**)&paLo, g_aLo);
    cudaGetSymbolAddress((void**)&pwHi, g_wHi);
    cudaGetSymbolAddress((void**)&pwLo, g_wLo);
    cudaGetSymbolAddress((void**)&pqHi, g_qHi);
    cudaGetSymbolAddress((void**)&pqLo, g_qLo);
    cudaGetSymbolAddress((void**)&pkHi, g_kHi);
    cudaGetSymbolAddress((void**)&pkLo, g_kLo);
    cudaGetSymbolAddress((void**)&pvHi, g_vHi);
    cudaGetSymbolAddress((void**)&pvLo, g_vLo);

    cudaFuncSetAttribute(gemm_mma<0>, cudaFuncAttributeMaxDynamicSharedMemorySize, GSMEM);
    cudaFuncSetAttribute(gemm_mma<1>, cudaFuncAttributeMaxDynamicSharedMemorySize, GSMEM);
    cudaFuncSetAttribute(attn_mma, cudaFuncAttributeMaxDynamicSharedMemorySize, ASMEM);

    convert_mask_kernel<<<1, 256>>>(pm);

    // pre-LN with fused hi/lo split
    ln_kernel<<<NROWS, 256>>>(x, (const float*)nullptr, g_pre, b_pre, ph, phHi, phLo);

    // weight splits, single launch: y = {Wq, Wk, Wv, Wo}
    const int nW = DD * DD;
    split_w_kernel<<<dim3(nW / 1024, 4), 256>>>(Wq, Wk, Wv, Wo, pwHi, pwLo);

    // QKV projections -> bf16 hi/lo (B,H,L,HD), single launch over z = {q,k,v}
    dim3 gqkv(DD / 128, NROWS / 128, 3);
    gemm_mma<1><<<gqkv, 256, GSMEM>>>(phHi, phLo, pwHi, pwLo,
                                      bq, bk, bv, nullptr,
                                      pqHi, pqLo, pkHi, pkLo, pvHi, pvLo);

    // tensor-core flash attention (writes aHi/aLo directly)
    attn_mma<<<dim3(LL / 128, BB * HH), 256, ASMEM>>>();

    // output projection (z=0 selects Wo slice at offset 3)
    dim3 gproj(DD / 128, NROWS / 128, 1);
    gemm_mma<0><<<gproj, 256, GSMEM>>>(paHi, paLo, pwHi + 3 * (size_t)nW, pwLo + 3 * (size_t)nW,
                                       bo, bo, bo, py,
                                       nullptr, nullptr, nullptr, nullptr, nullptr, nullptr);

    // residual + final LN
    ln_kernel<<<NROWS, 256>>>(py, ph, g_ln, b_ln, out, nullptr, nullptr);
}

// round 11
// speedup vs baseline: 1.5715x; 1.0016x over previous
#include <cuda_runtime.h>
#include <cuda_bf16.h>
#include <math.h>
#include <stdint.h>

#define BB 4
#define LL 2048
#define DD 1024
#define HH 16
#define HDIM 64
#define NROWS (BB * LL)   // 8192

// ---------------- scratch ----------------
__device__ float g_h[NROWS * DD];     // LN(x) fp32 (residual)
__device__ float g_y[NROWS * DD];     // O-proj out
__device__ unsigned char g_mask[NROWS];
__device__ __nv_bfloat16 g_hHi[NROWS * DD];
__device__ __nv_bfloat16 g_hLo[NROWS * DD];
__device__ __nv_bfloat16 g_aHi[NROWS * DD];   // attention out hi/lo (B,L,D)
__device__ __nv_bfloat16 g_aLo[NROWS * DD];
__device__ __nv_bfloat16 g_wHi[4][DD * DD];
__device__ __nv_bfloat16 g_wLo[4][DD * DD];
__device__ __nv_bfloat16 g_qHi[NROWS * DD];   // (B,H,L,HD)
__device__ __nv_bfloat16 g_qLo[NROWS * DD];
__device__ __nv_bfloat16 g_kHi[NROWS * DD];
__device__ __nv_bfloat16 g_kLo[NROWS * DD];
__device__ __nv_bfloat16 g_vHi[NROWS * DD];
__device__ __nv_bfloat16 g_vLo[NROWS * DD];

// ---------------- helpers ----------------
__device__ __forceinline__ uint32_t smem_u32(const void* p) {
    uint32_t a;
    asm("{ .reg .u64 t; cvta.to.shared.u64 t, %1; cvt.u32.u64 %0, t; }" : "=r"(a) : "l"(p));
    return a;
}
__device__ __forceinline__ void ldsm_x4(uint32_t& d0, uint32_t& d1, uint32_t& d2, uint32_t& d3,
                                        uint32_t addr) {
    asm volatile("ldmatrix.sync.aligned.m8n8.x4.shared.b16 {%0,%1,%2,%3}, [%4];"
                 : "=r"(d0), "=r"(d1), "=r"(d2), "=r"(d3) : "r"(addr));
}
__device__ __forceinline__ void ldsm_x4t(uint32_t& d0, uint32_t& d1, uint32_t& d2, uint32_t& d3,
                                         uint32_t addr) {
    asm volatile("ldmatrix.sync.aligned.m8n8.x4.trans.shared.b16 {%0,%1,%2,%3}, [%4];"
                 : "=r"(d0), "=r"(d1), "=r"(d2), "=r"(d3) : "r"(addr));
}
__device__ __forceinline__ void mma16816(float* c, const uint32_t* a, const uint32_t* b) {
    asm volatile(
        "mma.sync.aligned.m16n8k16.row.col.f32.bf16.bf16.f32 "
        "{%0,%1,%2,%3}, {%4,%5,%6,%7}, {%8,%9}, {%0,%1,%2,%3};"
        : "+f"(c[0]), "+f"(c[1]), "+f"(c[2]), "+f"(c[3])
        : "r"(a[0]), "r"(a[1]), "r"(a[2]), "r"(a[3]), "r"(b[0]), "r"(b[1]));
}
__device__ __forceinline__ float ex2(float x) {
    float y;
    asm("ex2.approx.ftz.f32 %0, %1;" : "=f"(y) : "f"(x));
    return y;
}
#define CP_ASYNC16(dst, src) \
    asm volatile("cp.async.cg.shared.global [%0], [%1], 16;" :: "r"(dst), "l"(src))
#define CP_COMMIT() asm volatile("cp.async.commit_group;")
#define CP_WAIT1()  asm volatile("cp.async.wait_group 1;")
#define CP_WAIT0()  asm volatile("cp.async.wait_group 0;")

__device__ __forceinline__ uint32_t sw128(uint32_t off) {
    return off ^ ((off >> 3) & 0x70u);
}
__device__ __forceinline__ void split2(float a, float b, uint32_t& hi, uint32_t& lo) {
    __nv_bfloat16 ha = __float2bfloat16_rn(a), hb = __float2bfloat16_rn(b);
    float ra = a - __bfloat162float(ha), rb = b - __bfloat162float(hb);
    __nv_bfloat162 h2; h2.x = ha; h2.y = hb;
    __nv_bfloat162 l2; l2.x = __float2bfloat16_rn(ra); l2.y = __float2bfloat16_rn(rb);
    hi = *(uint32_t*)&h2;
    lo = *(uint32_t*)&l2;
}

// ---------------- padding-mask canonicalization ----------------
__global__ void convert_mask_kernel(const unsigned char* __restrict__ pm) {
    __shared__ int fz0, fz3;
    int tid = threadIdx.x;
    if (tid == 0) { fz0 = 0; fz3 = 0; }
    __syncthreads();
    int z0 = 0, z3 = 0;
    for (int j = tid; j < NROWS; j += blockDim.x) {
        unsigned char v = pm[j];
        if (v) {
            if ((j & 3) == 0) z0 = 1;
            if ((j & 3) == 3) z3 = 1;
        }
    }
    if (z0) atomicOr(&fz0, 1);
    if (z3) atomicOr(&fz3, 1);
    __syncthreads();
    int mode;
    if (!fz3) mode = fz0 ? 3 : 0;
    else      mode = fz0 ? 1 : 2;
    for (int i = tid; i < NROWS; i += blockDim.x) {
        unsigned char r;
        if (mode == 0)      r = 0;
        else if (mode == 1) r = (pm[i] != 0);
        else if (mode == 2) r = (((const float*)pm)[i] != 0.0f);
        else                r = (((const int*)pm)[i] != 0);
        g_mask[i] = r;
    }
}

// ---------------- fp32 -> bf16 hi/lo split, 4 weights in one launch ----------------
__global__ void split_w_kernel(const float* __restrict__ s0, const float* __restrict__ s1,
                               const float* __restrict__ s2, const float* __restrict__ s3,
                               __nv_bfloat16* __restrict__ hiB,
                               __nv_bfloat16* __restrict__ loB) {
    int w = blockIdx.y;
    const float* src = (w == 0) ? s0 : (w == 1) ? s1 : (w == 2) ? s2 : s3;
    size_t off = (size_t)w * DD * DD;
    int i = (blockIdx.x * blockDim.x + threadIdx.x) * 4;
    float4 v = *(const float4*)(src + i);
    uint32_t h01, l01, h23, l23;
    split2(v.x, v.y, h01, l01);
    split2(v.z, v.w, h23, l23);
    *(uint32_t*)(hiB + off + i) = h01; *(uint32_t*)(hiB + off + i + 2) = h23;
    *(uint32_t*)(loB + off + i) = l01; *(uint32_t*)(loB + off + i + 2) = l23;
}

// ---------------- LayerNorm (optional residual; optional fused hi/lo split) ----------------
__global__ void ln_kernel(const float* __restrict__ x, const float* __restrict__ res,
                          const float* __restrict__ gamma, const float* __restrict__ beta,
                          float* __restrict__ out,
                          __nv_bfloat16* __restrict__ outHi,
                          __nv_bfloat16* __restrict__ outLo) {
    int row = blockIdx.x;
    int tid = threadIdx.x;
    const float4* xr = (const float4*)(x + (size_t)row * DD);
    float4 v = xr[tid];
    if (res) {
        const float4* rr = (const float4*)(res + (size_t)row * DD);
        float4 r2 = rr[tid];
        v.x += r2.x; v.y += r2.y; v.z += r2.z; v.w += r2.w;
    }
    float s  = v.x + v.y + v.z + v.w;
    float ss = v.x * v.x + v.y * v.y + v.z * v.z + v.w * v.w;
    for (int off = 16; off > 0; off >>= 1) {
        s  += __shfl_down_sync(0xffffffffu, s, off);
        ss += __shfl_down_sync(0xffffffffu, ss, off);
    }
    __shared__ float rs[8], rss[8];
    __shared__ float s_mu, s_rsig;
    int wid = tid >> 5, lane = tid & 31;
    if (lane == 0) { rs[wid] = s; rss[wid] = ss; }
    __syncthreads();
    if (tid == 0) {
        float S = 0.f, SS = 0.f;
        #pragma unroll
        for (int i = 0; i < 8; i++) { S += rs[i]; SS += rss[i]; }
        float mu  = S * (1.0f / DD);
        float var = SS * (1.0f / DD) - mu * mu;
        s_mu = mu;
        s_rsig = rsqrtf(var + 1e-5f);
    }
    __syncthreads();
    float mu = s_mu, rsig = s_rsig;
    float4 gv = ((const float4*)gamma)[tid];
    float4 bv = ((const float4*)beta)[tid];
    float4 o;
    o.x = (v.x - mu) * rsig * gv.x + bv.x;
    o.y = (v.y - mu) * rsig * gv.y + bv.y;
    o.z = (v.z - mu) * rsig * gv.z + bv.z;
    o.w = (v.w - mu) * rsig * gv.w + bv.w;
    ((float4*)(out + (size_t)row * DD))[tid] = o;
    if (outHi) {
        size_t i = (size_t)row * DD + tid * 4;
        uint32_t h01, l01, h23, l23;
        split2(o.x, o.y, h01, l01);
        split2(o.z, o.w, h23, l23);
        *(uint32_t*)(outHi + i) = h01; *(uint32_t*)(outHi + i + 2) = h23;
        *(uint32_t*)(outLo + i) = l01; *(uint32_t*)(outLo + i + 2) = l23;
    }
}

// ---------------- mma.sync split-bf16 GEMM (R6 champion structure, unchanged) ----------------
#define GSMEM (64 * 1024)

template <int MODE>
__global__ __launch_bounds__(256, 2)
void gemm_mma(const __nv_bfloat16* __restrict__ Ahi, const __nv_bfloat16* __restrict__ Alo,
              const __nv_bfloat16* __restrict__ WHiB, const __nv_bfloat16* __restrict__ WLoB,
              const float* __restrict__ b0, const float* __restrict__ b1, const float* __restrict__ b2,
              float* __restrict__ C,
              __nv_bfloat16* __restrict__ h0, __nv_bfloat16* __restrict__ l0_,
              __nv_bfloat16* __restrict__ h1, __nv_bfloat16* __restrict__ l1_,
              __nv_bfloat16* __restrict__ h2, __nv_bfloat16* __restrict__ l2_) {
    extern __shared__ char dsm[];
    __shared__ float s_bias[128];

    int tid = threadIdx.x;
    int wid = tid >> 5;
    int lane = tid & 31;
    int warp_m = wid & 3;
    int warp_n = wid >> 2;
    int rowA0 = blockIdx.y * 128;
    int colB0 = blockIdx.x * 128;
    int z = blockIdx.z;

    const __nv_bfloat16* Bhi = WHiB + (size_t)z * DD * DD;
    const __nv_bfloat16* Blo = WLoB + (size_t)z * DD * DD;
    const float* bias = (z == 0) ? b0 : (z == 1) ? b1 : b2;
    __nv_bfloat16* CHi = (z == 0) ? h0 : (z == 1) ? h1 : h2;
    __nv_bfloat16* CLo = (z == 0) ? l0_ : (z == 1) ? l1_ : l2_;

    uint32_t base = smem_u32(dsm);
    uint32_t aBase[2] = { base, base + 32768u };
    uint32_t bBase[2] = { base + 16384u, base + 49152u };

    if (tid < 128) s_bias[tid] = bias[colB0 + tid];

    const __nv_bfloat16* TA[3] = { Ahi, Ahi, Alo };
    const __nv_bfloat16* TB[3] = { Bhi, Blo, Bhi };

    int ldR[4], ldC[4];
    uint32_t ldSw[4];
    #pragma unroll
    for (int it = 0; it < 4; it++) {
        int lin = it * 256 + tid;
        ldR[it] = lin >> 3;
        ldC[it] = (lin & 7) * 8;
        ldSw[it] = sw128((uint32_t)(ldR[it] * 128 + (lin & 7) * 16));
    }

    auto issue = [&](int i, int s) {
        int term = i >> 4;
        int k0 = (i & 15) * 64;
        const __nv_bfloat16* Ag = TA[term];
        const __nv_bfloat16* Bg = TB[term];
        #pragma unroll
        for (int it = 0; it < 4; it++) {
            CP_ASYNC16(aBase[s] + ldSw[it], Ag + (size_t)(rowA0 + ldR[it]) * DD + k0 + ldC[it]);
            CP_ASYNC16(bBase[s] + ldSw[it], Bg + (size_t)(colB0 + ldR[it]) * DD + k0 + ldC[it]);
        }
        CP_COMMIT();
    };

    float acc[2][8][4];
    #pragma unroll
    for (int mt = 0; mt < 2; mt++)
        #pragma unroll
        for (int nt = 0; nt < 8; nt++)
            #pragma unroll
            for (int q = 0; q < 4; q++) acc[mt][nt][q] = 0.f;

    int aRow = warp_m * 32 + (lane & 15);
    int aChunkHalf = lane >> 4;
    int bRow = warp_n * 64 + (lane >> 4) * 8 + (lane & 7);
    int bChunkHalf = (lane >> 3) & 1;

    issue(0, 0);

    for (int i = 0; i < 48; i++) {
        int s = i & 1;
        if (i < 47) issue(i + 1, s ^ 1);
        if (i < 47) { CP_WAIT1(); } else { CP_WAIT0(); }
        __syncthreads();

        #pragma unroll
        for (int ks = 0; ks < 4; ks++) {
            uint32_t af[2][4];
            #pragma unroll
            for (int mt = 0; mt < 2; mt++) {
                uint32_t off = (uint32_t)((aRow + mt * 16) * 128 + (ks * 2 + aChunkHalf) * 16);
                ldsm_x4(af[mt][0], af[mt][1], af[mt][2], af[mt][3], aBase[s] + sw128(off));
            }
            uint32_t bf[8][2];
            #pragma unroll
            for (int j2 = 0; j2 < 4; j2++) {
                uint32_t off = (uint32_t)((bRow + j2 * 16) * 128 + (ks * 2 + bChunkHalf) * 16);
                uint32_t r0, r1, r2, r3;
                ldsm_x4(r0, r1, r2, r3, bBase[s] + sw128(off));
                bf[j2 * 2][0] = r0; bf[j2 * 2][1] = r1;
                bf[j2 * 2 + 1][0] = r2; bf[j2 * 2 + 1][1] = r3;
            }
            #pragma unroll
            for (int mt = 0; mt < 2; mt++)
                #pragma unroll
                for (int nt = 0; nt < 8; nt++)
                    mma16816(acc[mt][nt], af[mt], bf[nt]);
        }
        __syncthreads();
    }

    int gid = lane >> 2, tig = lane & 3;
    #pragma unroll
    for (int mt = 0; mt < 2; mt++) {
        #pragma unroll
        for (int half = 0; half < 2; half++) {
            int m = rowA0 + warp_m * 32 + mt * 16 + gid + half * 8;
            #pragma unroll
            for (int nt = 0; nt < 8; nt++) {
                int col = colB0 + warp_n * 64 + nt * 8 + tig * 2;
                float vx = acc[mt][nt][half * 2 + 0] + s_bias[col - colB0];
                float vy = acc[mt][nt][half * 2 + 1] + s_bias[col - colB0 + 1];
                if (MODE == 0) {
                    float2 v; v.x = vx; v.y = vy;
                    *(float2*)(C + (size_t)m * DD + col) = v;
                } else {
                    int b = m >> 11, l = m & 2047;
                    int hh = col >> 6, hd = col & 63;
                    size_t idx = (((size_t)(b * HH + hh)) * LL + l) * HDIM + hd;
                    uint32_t hi2, lo2;
                    split2(vx, vy, hi2, lo2);
                    *(uint32_t*)(CHi + idx) = hi2;
                    *(uint32_t*)(CLo + idx) = lo2;
                }
            }
        }
    }
}

// ---------------- tensor-core flash attention, register-lean, occ 2 ----------------
// hi/lo K and V fragments never coexist: load hi frags -> 2 MMA groups -> reuse regs for lo -> 1 MMA group.
#define ASMEM (64 * 1024)

__global__ __launch_bounds__(256, 2)
void attn_mma() {
    extern __shared__ char dsm[];
    __shared__ unsigned char s_mk[2][64];

    int tid = threadIdx.x;
    int wid = tid >> 5;
    int lane = tid & 31;
    int gid = lane >> 2, tig = lane & 3;
    int qt = blockIdx.x;
    int bh = blockIdx.y;
    int b = bh >> 4, h = bh & 15;
    int qbase = qt * 128;

    uint32_t base = smem_u32(dsm);
    // stage s: Khi @ s*32768, Klo +8192, Vhi +16384, Vlo +24576

    const __nv_bfloat16* qHi = g_qHi + ((size_t)bh * LL + qbase) * HDIM;
    const __nv_bfloat16* qLo = g_qLo + ((size_t)bh * LL + qbase) * HDIM;

    // ---- stage Q (hi @ base, lo @ base+16384), extract to registers ----
    #pragma unroll
    for (int it = 0; it < 4; it++) {
        int c = it * 256 + tid;
        int row = c >> 3, col16 = c & 7;
        uint32_t sw = sw128((uint32_t)(row * 128 + col16 * 16));
        CP_ASYNC16(base + sw, qHi + row * HDIM + col16 * 8);
        CP_ASYNC16(base + 16384u + sw, qLo + row * HDIM + col16 * 8);
    }
    CP_COMMIT();
    CP_WAIT0();
    __syncthreads();

    uint32_t qh[4][4], ql[4][4];
    {
        int arow = wid * 16 + (lane & 15);
        int ahalf = lane >> 4;
        #pragma unroll
        for (int ks = 0; ks < 4; ks++) {
            uint32_t off = (uint32_t)(arow * 128 + (ks * 2 + ahalf) * 16);
            ldsm_x4(qh[ks][0], qh[ks][1], qh[ks][2], qh[ks][3], base + sw128(off));
            ldsm_x4(ql[ks][0], ql[ks][1], ql[ks][2], ql[ks][3], base + 16384u + sw128(off));
        }
    }
    __syncthreads();

    int ntiles = 2 * qt + 2;

    auto issue = [&](int j, int s) {
        uint32_t st = base + (uint32_t)s * 32768u;
        size_t goff = ((size_t)bh * LL + j * 64) * HDIM;
        #pragma unroll
        for (int it = 0; it < 2; it++) {
            int c = it * 256 + tid;
            int row = c >> 3, col16 = c & 7;
            uint32_t sw = sw128((uint32_t)(row * 128 + col16 * 16));
            size_t so = goff + row * HDIM + col16 * 8;
            CP_ASYNC16(st + sw,          g_kHi + so);
            CP_ASYNC16(st + 8192u + sw,  g_kLo + so);
            CP_ASYNC16(st + 16384u + sw, g_vHi + so);
            CP_ASYNC16(st + 24576u + sw, g_vLo + so);
        }
        if (tid < 64) s_mk[s][tid] = g_mask[b * LL + j * 64 + tid];
        CP_COMMIT();
    };

    float o[8][4];
    #pragma unroll
    for (int nt = 0; nt < 8; nt++)
        #pragma unroll
        for (int q = 0; q < 4; q++) o[nt][q] = 0.f;
    float m0 = -1e30f, m1 = -1e30f, l0 = 0.f, l1 = 0.f;

    const float cs = 0.125f * 1.4426950408889634f;  // 1/sqrt(HD) * log2(e)
    int qg0 = qbase + wid * 16 + gid;
    int qg1 = qg0 + 8;

    issue(0, 0);
    int issued = 1;
    if (ntiles > 1) { issue(1, 1); issued = 2; }

    int kRow = (lane >> 4) * 8 + (lane & 7);
    int kHalf = (lane >> 3) & 1;
    int vRowL = lane & 15;
    int vHalf = lane >> 4;

    for (int j = 0; j < ntiles; j++) {
        int s = j & 1;
        if (issued > j + 1) { CP_WAIT1(); } else { CP_WAIT0(); }
        __syncthreads();

        uint32_t stK = base + (uint32_t)s * 32768u;
        uint32_t stV = stK + 16384u;

        // ---- S = Q K^T (3-term split; hi/lo K frags sequential, shared regs) ----
        float sa[8][4];
        #pragma unroll
        for (int nt = 0; nt < 8; nt++)
            #pragma unroll
            for (int q = 0; q < 4; q++) sa[nt][q] = 0.f;

        #pragma unroll
        for (int ks = 0; ks < 4; ks++) {
            uint32_t kf[8][2];
            // hi K frags: consumed by qh and ql MMAs
            #pragma unroll
            for (int j2 = 0; j2 < 4; j2++) {
                uint32_t off = (uint32_t)((kRow + j2 * 16) * 128 + (ks * 2 + kHalf) * 16);
                uint32_t r0, r1, r2, r3;
                ldsm_x4(r0, r1, r2, r3, stK + sw128(off));
                kf[j2 * 2][0] = r0; kf[j2 * 2][1] = r1;
                kf[j2 * 2 + 1][0] = r2; kf[j2 * 2 + 1][1] = r3;
            }
            #pragma unroll
            for (int nt = 0; nt < 8; nt++) {
                mma16816(sa[nt], qh[ks], kf[nt]);
                mma16816(sa[nt], ql[ks], kf[nt]);
            }
            // lo K frags reuse the same registers
            #pragma unroll
            for (int j2 = 0; j2 < 4; j2++) {
                uint32_t off = (uint32_t)((kRow + j2 * 16) * 128 + (ks * 2 + kHalf) * 16);
                uint32_t r0, r1, r2, r3;
                ldsm_x4(r0, r1, r2, r3, stK + 8192u + sw128(off));
                kf[j2 * 2][0] = r0; kf[j2 * 2][1] = r1;
                kf[j2 * 2 + 1][0] = r2; kf[j2 * 2 + 1][1] = r3;
            }
            #pragma unroll
            for (int nt = 0; nt < 8; nt++)
                mma16816(sa[nt], qh[ks], kf[nt]);
        }

        // ---- scale + masks ----
        int jbase = j * 64;
        #pragma unroll
        for (int nt = 0; nt < 8; nt++) {
            int cl = nt * 8 + tig * 2;
            int kg = jbase + cl;
            int msk0 = s_mk[s][cl];
            int msk1 = s_mk[s][cl + 1];
            float v0 = sa[nt][0] * cs, v1 = sa[nt][1] * cs;
            float v2 = sa[nt][2] * cs, v3 = sa[nt][3] * cs;
            if (kg > qg0 || msk0)     v0 = -1e30f;
            if (kg + 1 > qg0 || msk1) v1 = -1e30f;
            if (kg > qg1 || msk0)     v2 = -1e30f;
            if (kg + 1 > qg1 || msk1) v3 = -1e30f;
            sa[nt][0] = v0; sa[nt][1] = v1; sa[nt][2] = v2; sa[nt][3] = v3;
        }

        // ---- online softmax (MUFU ex2) ----
        float rmax0 = -1e30f, rmax1 = -1e30f;
        #pragma unroll
        for (int nt = 0; nt < 8; nt++) {
            rmax0 = fmaxf(rmax0, fmaxf(sa[nt][0], sa[nt][1]));
            rmax1 = fmaxf(rmax1, fmaxf(sa[nt][2], sa[nt][3]));
        }
        rmax0 = fmaxf(rmax0, __shfl_xor_sync(0xffffffffu, rmax0, 1));
        rmax0 = fmaxf(rmax0, __shfl_xor_sync(0xffffffffu, rmax0, 2));
        rmax1 = fmaxf(rmax1, __shfl_xor_sync(0xffffffffu, rmax1, 1));
        rmax1 = fmaxf(rmax1, __shfl_xor_sync(0xffffffffu, rmax1, 2));
        float mn0 = fmaxf(m0, rmax0), mn1 = fmaxf(m1, rmax1);
        float f0 = ex2(m0 - mn0), f1 = ex2(m1 - mn1);
        float ps0 = 0.f, ps1 = 0.f;
        #pragma unroll
        for (int nt = 0; nt < 8; nt++) {
            float p0 = ex2(sa[nt][0] - mn0);
            float p1 = ex2(sa[nt][1] - mn0);
            float p2 = ex2(sa[nt][2] - mn1);
            float p3 = ex2(sa[nt][3] - mn1);
            ps0 += p0 + p1; ps1 += p2 + p3;
            sa[nt][0] = p0; sa[nt][1] = p1; sa[nt][2] = p2; sa[nt][3] = p3;
        }
        ps0 += __shfl_xor_sync(0xffffffffu, ps0, 1);
        ps0 += __shfl_xor_sync(0xffffffffu, ps0, 2);
        ps1 += __shfl_xor_sync(0xffffffffu, ps1, 1);
        ps1 += __shfl_xor_sync(0xffffffffu, ps1, 2);
        l0 = l0 * f0 + ps0; m0 = mn0;
        l1 = l1 * f1 + ps1; m1 = mn1;
        #pragma unroll
        for (int nt = 0; nt < 8; nt++) {
            o[nt][0] *= f0; o[nt][1] *= f0;
            o[nt][2] *= f1; o[nt][3] *= f1;
        }

        // ---- repack P to bf16 hi/lo A-fragments (sa dead after) ----
        uint32_t phi[4][4], plo[4][4];
        #pragma unroll
        for (int ks = 0; ks < 4; ks++) {
            split2(sa[2 * ks][0],     sa[2 * ks][1],     phi[ks][0], plo[ks][0]);
            split2(sa[2 * ks][2],     sa[2 * ks][3],     phi[ks][1], plo[ks][1]);
            split2(sa[2 * ks + 1][0], sa[2 * ks + 1][1], phi[ks][2], plo[ks][2]);
            split2(sa[2 * ks + 1][2], sa[2 * ks + 1][3], phi[ks][3], plo[ks][3]);
        }

        // ---- O += P V (3-term split; hi/lo V frags sequential, shared regs) ----
        #pragma unroll
        for (int ks = 0; ks < 4; ks++) {
            int vrow = ks * 16 + vRowL;
            uint32_t vf[8][2];
            #pragma unroll
            for (int g = 0; g < 4; g++) {
                uint32_t off = (uint32_t)(vrow * 128 + g * 32 + vHalf * 16);
                uint32_t r0, r1, r2, r3;
                ldsm_x4t(r0, r1, r2, r3, stV + sw128(off));
                vf[g * 2][0] = r0; vf[g * 2][1] = r1;
                vf[g * 2 + 1][0] = r2; vf[g * 2 + 1][1] = r3;
            }
            #pragma unroll
            for (int nt = 0; nt < 8; nt++) {
                mma16816(o[nt], phi[ks], vf[nt]);
                mma16816(o[nt], plo[ks], vf[nt]);
            }
            #pragma unroll
            for (int g = 0; g < 4; g++) {
                uint32_t off = (uint32_t)(vrow * 128 + g * 32 + vHalf * 16);
                uint32_t r0, r1, r2, r3;
                ldsm_x4t(r0, r1, r2, r3, stV + 8192u + sw128(off));
                vf[g * 2][0] = r0; vf[g * 2][1] = r1;
                vf[g * 2 + 1][0] = r2; vf[g * 2 + 1][1] = r3;
            }
            #pragma unroll
            for (int nt = 0; nt < 8; nt++)
                mma16816(o[nt], phi[ks], vf[nt]);
        }

        __syncthreads();
        if (j + 2 < ntiles) { issue(j + 2, s); issued++; }
    }

    // ---- epilogue: normalize + fused hi/lo split ----
    float inv0 = 1.0f / l0, inv1 = 1.0f / l1;
    #pragma unroll
    for (int nt = 0; nt < 8; nt++) {
        int d = nt * 8 + tig * 2;
        int col = h * HDIM + d;
        size_t i0 = ((size_t)b * LL + qg0) * DD + col;
        size_t i1 = ((size_t)b * LL + qg1) * DD + col;
        uint32_t hi2, lo2;
        split2(o[nt][0] * inv0, o[nt][1] * inv0, hi2, lo2);
        *(uint32_t*)(g_aHi + i0) = hi2;
        *(uint32_t*)(g_aLo + i0) = lo2;
        split2(o[nt][2] * inv1, o[nt][3] * inv1, hi2, lo2);
        *(uint32_t*)(g_aHi + i1) = hi2;
        *(uint32_t*)(g_aLo + i1) = lo2;
    }
}

// ---------------- launch ----------------
extern "C" void kernel_launch(void* const* d_in, const int* in_sizes, int n_in,
                              void* d_out, int out_size) {
    const float* x  = (const float*)d_in[0];
    const unsigned char* pm = (const unsigned char*)d_in[1];
    const float* Wq = (const float*)d_in[3];
    const float* bq = (const float*)d_in[4];
    const float* Wk = (const float*)d_in[5];
    const float* bk = (const float*)d_in[6];
    const float* Wv = (const float*)d_in[7];
    const float* bv = (const float*)d_in[8];
    const float* Wo = (const float*)d_in[9];
    const float* bo = (const float*)d_in[10];
    const float* g_pre = (const float*)d_in[11];
    const float* b_pre = (const float*)d_in[12];
    const float* g_ln  = (const float*)d_in[13];
    const float* b_ln  = (const float*)d_in[14];
    float* out = (float*)d_out;

    float *ph, *py;
    __nv_bfloat16 *phHi, *phLo, *paHi, *paLo, *pwHi, *pwLo;
    __nv_bfloat16 *pqHi, *pqLo, *pkHi, *pkLo, *pvHi, *pvLo;
    cudaGetSymbolAddress((void**)&ph,   g_h);
    cudaGetSymbolAddress((void**)&py,   g_y);
    cudaGetSymbolAddress((void**)&phHi, g_hHi);
    cudaGetSymbolAddress((void**)&phLo, g_hLo);
    cudaGetSymbolAddress((void**)&paHi, g_aHi);
    cudaGetSymbolAddress((void**)&paLo, g_aLo);
    cudaGetSymbolAddress((void**)&pwHi, g_wHi);
    cudaGetSymbolAddress((void**)&pwLo, g_wLo);
    cudaGetSymbolAddress((void**)&pqHi, g_qHi);
    cudaGetSymbolAddress((void**)&pqLo, g_qLo);
    cudaGetSymbolAddress((void**)&pkHi, g_kHi);
    cudaGetSymbolAddress((void**)&pkLo, g_kLo);
    cudaGetSymbolAddress((void**)&pvHi, g_vHi);
    cudaGetSymbolAddress((void**)&pvLo, g_vLo);

    cudaFuncSetAttribute(gemm_mma<0>, cudaFuncAttributeMaxDynamicSharedMemorySize, GSMEM);
    cudaFuncSetAttribute(gemm_mma<1>, cudaFuncAttributeMaxDynamicSharedMemorySize, GSMEM);
    cudaFuncSetAttribute(attn_mma, cudaFuncAttributeMaxDynamicSharedMemorySize, ASMEM);

    convert_mask_kernel<<<1, 256>>>(pm);

    // pre-LN with fused hi/lo split
    ln_kernel<<<NROWS, 256>>>(x, (const float*)nullptr, g_pre, b_pre, ph, phHi, phLo);

    // weight splits, single launch: y = {Wq, Wk, Wv, Wo}
    const int nW = DD * DD;
    split_w_kernel<<<dim3(nW / 1024, 4), 256>>>(Wq, Wk, Wv, Wo, pwHi, pwLo);

    // QKV projections -> bf16 hi/lo (B,H,L,HD), single launch over z = {q,k,v}
    dim3 gqkv(DD / 128, NROWS / 128, 3);
    gemm_mma<1><<<gqkv, 256, GSMEM>>>(phHi, phLo, pwHi, pwLo,
                                      bq, bk, bv, nullptr,
                                      pqHi, pqLo, pkHi, pkLo, pvHi, pvLo);

    // tensor-core flash attention (writes aHi/aLo directly)
    attn_mma<<<dim3(LL / 128, BB * HH), 256, ASMEM>>>();

    // output projection (z=0 selects Wo slice at offset 3)
    dim3 gproj(DD / 128, NROWS / 128, 1);
    gemm_mma<0><<<gproj, 256, GSMEM>>>(paHi, paLo, pwHi + 3 * (size_t)nW, pwLo + 3 * (size_t)nW,
                                       bo, bo, bo, py,
                                       nullptr, nullptr, nullptr, nullptr, nullptr, nullptr);

    // residual + final LN
    ln_kernel<<<NROWS, 256>>>(py, ph, g_ln, b_ln, out, nullptr, nullptr);
}

// round 12
// speedup vs baseline: 1.6045x; 1.0210x over previous
#include <cuda_runtime.h>
#include <cuda_bf16.h>
#include <math.h>
#include <stdint.h>

#define BB 4
#define LL 2048
#define DD 1024
#define HH 16
#define HDIM 64
#define NROWS (BB * LL)   // 8192

// ---------------- scratch ----------------
__device__ float g_h[NROWS * DD];     // LN(x) fp32 (residual)
__device__ float g_y[NROWS * DD];     // O-proj out
__device__ unsigned char g_mask[NROWS];
__device__ int g_len[BB];             // valid length per batch
__device__ __nv_bfloat16 g_hHi[NROWS * DD];
__device__ __nv_bfloat16 g_hLo[NROWS * DD];
__device__ __nv_bfloat16 g_aHi[NROWS * DD];   // attention out hi/lo (B,L,D)
__device__ __nv_bfloat16 g_aLo[NROWS * DD];
__device__ __nv_bfloat16 g_wHi[4][DD * DD];
__device__ __nv_bfloat16 g_wLo[4][DD * DD];
__device__ __nv_bfloat16 g_qHi[NROWS * DD];   // (B,H,L,HD)
__device__ __nv_bfloat16 g_qLo[NROWS * DD];
__device__ __nv_bfloat16 g_kHi[NROWS * DD];
__device__ __nv_bfloat16 g_kLo[NROWS * DD];
__device__ __nv_bfloat16 g_vHi[NROWS * DD];
__device__ __nv_bfloat16 g_vLo[NROWS * DD];

// ---------------- helpers ----------------
__device__ __forceinline__ uint32_t smem_u32(const void* p) {
    uint32_t a;
    asm("{ .reg .u64 t; cvta.to.shared.u64 t, %1; cvt.u32.u64 %0, t; }" : "=r"(a) : "l"(p));
    return a;
}
__device__ __forceinline__ void ldsm_x4(uint32_t& d0, uint32_t& d1, uint32_t& d2, uint32_t& d3,
                                        uint32_t addr) {
    asm volatile("ldmatrix.sync.aligned.m8n8.x4.shared.b16 {%0,%1,%2,%3}, [%4];"
                 : "=r"(d0), "=r"(d1), "=r"(d2), "=r"(d3) : "r"(addr));
}
__device__ __forceinline__ void ldsm_x4t(uint32_t& d0, uint32_t& d1, uint32_t& d2, uint32_t& d3,
                                         uint32_t addr) {
    asm volatile("ldmatrix.sync.aligned.m8n8.x4.trans.shared.b16 {%0,%1,%2,%3}, [%4];"
                 : "=r"(d0), "=r"(d1), "=r"(d2), "=r"(d3) : "r"(addr));
}
__device__ __forceinline__ void mma16816(float* c, const uint32_t* a, const uint32_t* b) {
    asm volatile(
        "mma.sync.aligned.m16n8k16.row.col.f32.bf16.bf16.f32 "
        "{%0,%1,%2,%3}, {%4,%5,%6,%7}, {%8,%9}, {%0,%1,%2,%3};"
        : "+f"(c[0]), "+f"(c[1]), "+f"(c[2]), "+f"(c[3])
        : "r"(a[0]), "r"(a[1]), "r"(a[2]), "r"(a[3]), "r"(b[0]), "r"(b[1]));
}
__device__ __forceinline__ float ex2(float x) {
    float y;
    asm("ex2.approx.ftz.f32 %0, %1;" : "=f"(y) : "f"(x));
    return y;
}
#define CP_ASYNC16(dst, src) \
    asm volatile("cp.async.cg.shared.global [%0], [%1], 16;" :: "r"(dst), "l"(src))
#define CP_COMMIT() asm volatile("cp.async.commit_group;")
#define CP_WAIT1()  asm volatile("cp.async.wait_group 1;")
#define CP_WAIT0()  asm volatile("cp.async.wait_group 0;")

__device__ __forceinline__ uint32_t sw128(uint32_t off) {
    return off ^ ((off >> 3) & 0x70u);
}
__device__ __forceinline__ void split2(float a, float b, uint32_t& hi, uint32_t& lo) {
    __nv_bfloat16 ha = __float2bfloat16_rn(a), hb = __float2bfloat16_rn(b);
    float ra = a - __bfloat162float(ha), rb = b - __bfloat162float(hb);
    __nv_bfloat162 h2; h2.x = ha; h2.y = hb;
    __nv_bfloat162 l2; l2.x = __float2bfloat16_rn(ra); l2.y = __float2bfloat16_rn(rb);
    hi = *(uint32_t*)&h2;
    lo = *(uint32_t*)&l2;
}

// ---------------- padding-mask canonicalization + per-batch length ----------------
__global__ void convert_mask_kernel(const unsigned char* __restrict__ pm) {
    __shared__ int fz0, fz3;
    int tid = threadIdx.x;
    if (tid == 0) { fz0 = 0; fz3 = 0; }
    if (tid < BB) g_len[tid] = 0;
    __syncthreads();
    int z0 = 0, z3 = 0;
    for (int j = tid; j < NROWS; j += blockDim.x) {
        unsigned char v = pm[j];
        if (v) {
            if ((j & 3) == 0) z0 = 1;
            if ((j & 3) == 3) z3 = 1;
        }
    }
    if (z0) atomicOr(&fz0, 1);
    if (z3) atomicOr(&fz3, 1);
    __syncthreads();
    int mode;
    if (!fz3) mode = fz0 ? 3 : 0;
    else      mode = fz0 ? 1 : 2;
    int cnt[BB];
    #pragma unroll
    for (int b = 0; b < BB; b++) cnt[b] = 0;
    for (int i = tid; i < NROWS; i += blockDim.x) {
        unsigned char r;
        if (mode == 0)      r = 0;
        else if (mode == 1) r = (pm[i] != 0);
        else if (mode == 2) r = (((const float*)pm)[i] != 0.0f);
        else                r = (((const int*)pm)[i] != 0);
        g_mask[i] = r;
        if (!r) cnt[i >> 11]++;
    }
    #pragma unroll
    for (int b = 0; b < BB; b++)
        if (cnt[b]) atomicAdd(&g_len[b], cnt[b]);
}

// ---------------- fp32 -> bf16 hi/lo split, 4 weights in one launch ----------------
__global__ void split_w_kernel(const float* __restrict__ s0, const float* __restrict__ s1,
                               const float* __restrict__ s2, const float* __restrict__ s3,
                               __nv_bfloat16* __restrict__ hiB,
                               __nv_bfloat16* __restrict__ loB) {
    int w = blockIdx.y;
    const float* src = (w == 0) ? s0 : (w == 1) ? s1 : (w == 2) ? s2 : s3;
    size_t off = (size_t)w * DD * DD;
    int i = (blockIdx.x * blockDim.x + threadIdx.x) * 4;
    float4 v = *(const float4*)(src + i);
    uint32_t h01, l01, h23, l23;
    split2(v.x, v.y, h01, l01);
    split2(v.z, v.w, h23, l23);
    *(uint32_t*)(hiB + off + i) = h01; *(uint32_t*)(hiB + off + i + 2) = h23;
    *(uint32_t*)(loB + off + i) = l01; *(uint32_t*)(loB + off + i + 2) = l23;
}

// ---------------- LayerNorm (optional residual; optional fused hi/lo split) ----------------
__global__ void ln_kernel(const float* __restrict__ x, const float* __restrict__ res,
                          const float* __restrict__ gamma, const float* __restrict__ beta,
                          float* __restrict__ out,
                          __nv_bfloat16* __restrict__ outHi,
                          __nv_bfloat16* __restrict__ outLo) {
    int row = blockIdx.x;
    int tid = threadIdx.x;
    const float4* xr = (const float4*)(x + (size_t)row * DD);
    float4 v = xr[tid];
    if (res) {
        const float4* rr = (const float4*)(res + (size_t)row * DD);
        float4 r2 = rr[tid];
        v.x += r2.x; v.y += r2.y; v.z += r2.z; v.w += r2.w;
    }
    float s  = v.x + v.y + v.z + v.w;
    float ss = v.x * v.x + v.y * v.y + v.z * v.z + v.w * v.w;
    for (int off = 16; off > 0; off >>= 1) {
        s  += __shfl_down_sync(0xffffffffu, s, off);
        ss += __shfl_down_sync(0xffffffffu, ss, off);
    }
    __shared__ float rs[8], rss[8];
    __shared__ float s_mu, s_rsig;
    int wid = tid >> 5, lane = tid & 31;
    if (lane == 0) { rs[wid] = s; rss[wid] = ss; }
    __syncthreads();
    if (tid == 0) {
        float S = 0.f, SS = 0.f;
        #pragma unroll
        for (int i = 0; i < 8; i++) { S += rs[i]; SS += rss[i]; }
        float mu  = S * (1.0f / DD);
        float var = SS * (1.0f / DD) - mu * mu;
        s_mu = mu;
        s_rsig = rsqrtf(var + 1e-5f);
    }
    __syncthreads();
    float mu = s_mu, rsig = s_rsig;
    float4 gv = ((const float4*)gamma)[tid];
    float4 bv = ((const float4*)beta)[tid];
    float4 o;
    o.x = (v.x - mu) * rsig * gv.x + bv.x;
    o.y = (v.y - mu) * rsig * gv.y + bv.y;
    o.z = (v.z - mu) * rsig * gv.z + bv.z;
    o.w = (v.w - mu) * rsig * gv.w + bv.w;
    ((float4*)(out + (size_t)row * DD))[tid] = o;
    if (outHi) {
        size_t i = (size_t)row * DD + tid * 4;
        uint32_t h01, l01, h23, l23;
        split2(o.x, o.y, h01, l01);
        split2(o.z, o.w, h23, l23);
        *(uint32_t*)(outHi + i) = h01; *(uint32_t*)(outHi + i + 2) = h23;
        *(uint32_t*)(outLo + i) = l01; *(uint32_t*)(outLo + i + 2) = l23;
    }
}

// ---------------- mma.sync split-bf16 GEMM (champion structure + K/V tile skip) ----------------
#define GSMEM (64 * 1024)

template <int MODE>
__global__ __launch_bounds__(256, 2)
void gemm_mma(const __nv_bfloat16* __restrict__ Ahi, const __nv_bfloat16* __restrict__ Alo,
              const __nv_bfloat16* __restrict__ WHiB, const __nv_bfloat16* __restrict__ WLoB,
              const float* __restrict__ b0, const float* __restrict__ b1, const float* __restrict__ b2,
              float* __restrict__ C,
              __nv_bfloat16* __restrict__ h0, __nv_bfloat16* __restrict__ l0_,
              __nv_bfloat16* __restrict__ h1, __nv_bfloat16* __restrict__ l1_,
              __nv_bfloat16* __restrict__ h2, __nv_bfloat16* __restrict__ l2_) {
    extern __shared__ char dsm[];
    __shared__ float s_bias[128];

    int tid = threadIdx.x;
    int wid = tid >> 5;
    int lane = tid & 31;
    int warp_m = wid & 3;
    int warp_n = wid >> 2;
    int rowA0 = blockIdx.y * 128;
    int colB0 = blockIdx.x * 128;
    int z = blockIdx.z;

    // K/V rows fully inside the padding suffix are never consumed: skip the CTA.
    if (MODE == 1 && z >= 1) {
        if ((rowA0 & 2047) >= g_len[rowA0 >> 11]) return;
    }

    const __nv_bfloat16* Bhi = WHiB + (size_t)z * DD * DD;
    const __nv_bfloat16* Blo = WLoB + (size_t)z * DD * DD;
    const float* bias = (z == 0) ? b0 : (z == 1) ? b1 : b2;
    __nv_bfloat16* CHi = (z == 0) ? h0 : (z == 1) ? h1 : h2;
    __nv_bfloat16* CLo = (z == 0) ? l0_ : (z == 1) ? l1_ : l2_;

    uint32_t base = smem_u32(dsm);
    uint32_t aBase[2] = { base, base + 32768u };
    uint32_t bBase[2] = { base + 16384u, base + 49152u };

    if (tid < 128) s_bias[tid] = bias[colB0 + tid];

    const __nv_bfloat16* TA[3] = { Ahi, Ahi, Alo };
    const __nv_bfloat16* TB[3] = { Bhi, Blo, Bhi };

    int ldR[4], ldC[4];
    uint32_t ldSw[4];
    #pragma unroll
    for (int it = 0; it < 4; it++) {
        int lin = it * 256 + tid;
        ldR[it] = lin >> 3;
        ldC[it] = (lin & 7) * 8;
        ldSw[it] = sw128((uint32_t)(ldR[it] * 128 + (lin & 7) * 16));
    }

    auto issue = [&](int i, int s) {
        int term = i >> 4;
        int k0 = (i & 15) * 64;
        const __nv_bfloat16* Ag = TA[term];
        const __nv_bfloat16* Bg = TB[term];
        #pragma unroll
        for (int it = 0; it < 4; it++) {
            CP_ASYNC16(aBase[s] + ldSw[it], Ag + (size_t)(rowA0 + ldR[it]) * DD + k0 + ldC[it]);
            CP_ASYNC16(bBase[s] + ldSw[it], Bg + (size_t)(colB0 + ldR[it]) * DD + k0 + ldC[it]);
        }
        CP_COMMIT();
    };

    float acc[2][8][4];
    #pragma unroll
    for (int mt = 0; mt < 2; mt++)
        #pragma unroll
        for (int nt = 0; nt < 8; nt++)
            #pragma unroll
            for (int q = 0; q < 4; q++) acc[mt][nt][q] = 0.f;

    int aRow = warp_m * 32 + (lane & 15);
    int aChunkHalf = lane >> 4;
    int bRow = warp_n * 64 + (lane >> 4) * 8 + (lane & 7);
    int bChunkHalf = (lane >> 3) & 1;

    issue(0, 0);

    for (int i = 0; i < 48; i++) {
        int s = i & 1;
        if (i < 47) issue(i + 1, s ^ 1);
        if (i < 47) { CP_WAIT1(); } else { CP_WAIT0(); }
        __syncthreads();

        #pragma unroll
        for (int ks = 0; ks < 4; ks++) {
            uint32_t af[2][4];
            #pragma unroll
            for (int mt = 0; mt < 2; mt++) {
                uint32_t off = (uint32_t)((aRow + mt * 16) * 128 + (ks * 2 + aChunkHalf) * 16);
                ldsm_x4(af[mt][0], af[mt][1], af[mt][2], af[mt][3], aBase[s] + sw128(off));
            }
            uint32_t bf[8][2];
            #pragma unroll
            for (int j2 = 0; j2 < 4; j2++) {
                uint32_t off = (uint32_t)((bRow + j2 * 16) * 128 + (ks * 2 + bChunkHalf) * 16);
                uint32_t r0, r1, r2, r3;
                ldsm_x4(r0, r1, r2, r3, bBase[s] + sw128(off));
                bf[j2 * 2][0] = r0; bf[j2 * 2][1] = r1;
                bf[j2 * 2 + 1][0] = r2; bf[j2 * 2 + 1][1] = r3;
            }
            #pragma unroll
            for (int mt = 0; mt < 2; mt++)
                #pragma unroll
                for (int nt = 0; nt < 8; nt++)
                    mma16816(acc[mt][nt], af[mt], bf[nt]);
        }
        __syncthreads();
    }

    int gid = lane >> 2, tig = lane & 3;
    #pragma unroll
    for (int mt = 0; mt < 2; mt++) {
        #pragma unroll
        for (int half = 0; half < 2; half++) {
            int m = rowA0 + warp_m * 32 + mt * 16 + gid + half * 8;
            #pragma unroll
            for (int nt = 0; nt < 8; nt++) {
                int col = colB0 + warp_n * 64 + nt * 8 + tig * 2;
                float vx = acc[mt][nt][half * 2 + 0] + s_bias[col - colB0];
                float vy = acc[mt][nt][half * 2 + 1] + s_bias[col - colB0 + 1];
                if (MODE == 0) {
                    float2 v; v.x = vx; v.y = vy;
                    *(float2*)(C + (size_t)m * DD + col) = v;
                } else {
                    int b = m >> 11, l = m & 2047;
                    int hh = col >> 6, hd = col & 63;
                    size_t idx = (((size_t)(b * HH + hh)) * LL + l) * HDIM + hd;
                    uint32_t hi2, lo2;
                    split2(vx, vy, hi2, lo2);
                    *(uint32_t*)(CHi + idx) = hi2;
                    *(uint32_t*)(CLo + idx) = lo2;
                }
            }
        }
    }
}

// ---------------- tensor-core flash attention (champion + masked-tile skip) ----------------
#define ASMEM (64 * 1024)

__global__ __launch_bounds__(256, 2)
void attn_mma() {
    extern __shared__ char dsm[];
    __shared__ unsigned char s_mk[2][64];

    int tid = threadIdx.x;
    int wid = tid >> 5;
    int lane = tid & 31;
    int gid = lane >> 2, tig = lane & 3;
    int qt = blockIdx.x;
    int bh = blockIdx.y;
    int b = bh >> 4, h = bh & 15;
    int qbase = qt * 128;

    uint32_t base = smem_u32(dsm);
    // stage s: Khi @ s*32768, Klo +8192, Vhi +16384, Vlo +24576

    const __nv_bfloat16* qHi = g_qHi + ((size_t)bh * LL + qbase) * HDIM;
    const __nv_bfloat16* qLo = g_qLo + ((size_t)bh * LL + qbase) * HDIM;

    // ---- stage Q (hi @ base, lo @ base+16384), extract to registers ----
    #pragma unroll
    for (int it = 0; it < 4; it++) {
        int c = it * 256 + tid;
        int row = c >> 3, col16 = c & 7;
        uint32_t sw = sw128((uint32_t)(row * 128 + col16 * 16));
        CP_ASYNC16(base + sw, qHi + row * HDIM + col16 * 8);
        CP_ASYNC16(base + 16384u + sw, qLo + row * HDIM + col16 * 8);
    }
    CP_COMMIT();
    CP_WAIT0();
    __syncthreads();

    uint32_t qh[4][4], ql[4][4];
    {
        int arow = wid * 16 + (lane & 15);
        int ahalf = lane >> 4;
        #pragma unroll
        for (int ks = 0; ks < 4; ks++) {
            uint32_t off = (uint32_t)(arow * 128 + (ks * 2 + ahalf) * 16);
            ldsm_x4(qh[ks][0], qh[ks][1], qh[ks][2], qh[ks][3], base + sw128(off));
            ldsm_x4(ql[ks][0], ql[ks][1], ql[ks][2], ql[ks][3], base + 16384u + sw128(off));
        }
    }
    __syncthreads();

    // valid key tiles only: tiles fully inside the padding suffix contribute exactly 0
    int len = g_len[b];
    int ntiles_c = 2 * qt + 2;
    int ntiles_v = (len + 63) >> 6;
    int ntiles = (ntiles_c < ntiles_v) ? ntiles_c : ntiles_v;

    auto issue = [&](int j, int s) {
        uint32_t st = base + (uint32_t)s * 32768u;
        size_t goff = ((size_t)bh * LL + j * 64) * HDIM;
        #pragma unroll
        for (int it = 0; it < 2; it++) {
            int c = it * 256 + tid;
            int row = c >> 3, col16 = c & 7;
            uint32_t sw = sw128((uint32_t)(row * 128 + col16 * 16));
            size_t so = goff + row * HDIM + col16 * 8;
            CP_ASYNC16(st + sw,          g_kHi + so);
            CP_ASYNC16(st + 8192u + sw,  g_kLo + so);
            CP_ASYNC16(st + 16384u + sw, g_vHi + so);
            CP_ASYNC16(st + 24576u + sw, g_vLo + so);
        }
        if (tid < 64) s_mk[s][tid] = g_mask[b * LL + j * 64 + tid];
        CP_COMMIT();
    };

    float o[8][4];
    #pragma unroll
    for (int nt = 0; nt < 8; nt++)
        #pragma unroll
        for (int q = 0; q < 4; q++) o[nt][q] = 0.f;
    float m0 = -1e30f, m1 = -1e30f, l0 = 0.f, l1 = 0.f;

    const float cs = 0.125f * 1.4426950408889634f;  // 1/sqrt(HD) * log2(e)
    int qg0 = qbase + wid * 16 + gid;
    int qg1 = qg0 + 8;

    issue(0, 0);
    int issued = 1;
    if (ntiles > 1) { issue(1, 1); issued = 2; }

    int kRow = (lane >> 4) * 8 + (lane & 7);
    int kHalf = (lane >> 3) & 1;
    int vRowL = lane & 15;
    int vHalf = lane >> 4;

    for (int j = 0; j < ntiles; j++) {
        int s = j & 1;
        if (issued > j + 1) { CP_WAIT1(); } else { CP_WAIT0(); }
        __syncthreads();

        uint32_t stK = base + (uint32_t)s * 32768u;
        uint32_t stV = stK + 16384u;

        // ---- S = Q K^T (3-term split; hi/lo K frags sequential, shared regs) ----
        float sa[8][4];
        #pragma unroll
        for (int nt = 0; nt < 8; nt++)
            #pragma unroll
            for (int q = 0; q < 4; q++) sa[nt][q] = 0.f;

        #pragma unroll
        for (int ks = 0; ks < 4; ks++) {
            uint32_t kf[8][2];
            #pragma unroll
            for (int j2 = 0; j2 < 4; j2++) {
                uint32_t off = (uint32_t)((kRow + j2 * 16) * 128 + (ks * 2 + kHalf) * 16);
                uint32_t r0, r1, r2, r3;
                ldsm_x4(r0, r1, r2, r3, stK + sw128(off));
                kf[j2 * 2][0] = r0; kf[j2 * 2][1] = r1;
                kf[j2 * 2 + 1][0] = r2; kf[j2 * 2 + 1][1] = r3;
            }
            #pragma unroll
            for (int nt = 0; nt < 8; nt++) {
                mma16816(sa[nt], qh[ks], kf[nt]);
                mma16816(sa[nt], ql[ks], kf[nt]);
            }
            #pragma unroll
            for (int j2 = 0; j2 < 4; j2++) {
                uint32_t off = (uint32_t)((kRow + j2 * 16) * 128 + (ks * 2 + kHalf) * 16);
                uint32_t r0, r1, r2, r3;
                ldsm_x4(r0, r1, r2, r3, stK + 8192u + sw128(off));
                kf[j2 * 2][0] = r0; kf[j2 * 2][1] = r1;
                kf[j2 * 2 + 1][0] = r2; kf[j2 * 2 + 1][1] = r3;
            }
            #pragma unroll
            for (int nt = 0; nt < 8; nt++)
                mma16816(sa[nt], qh[ks], kf[nt]);
        }

        // ---- scale + masks ----
        int jbase = j * 64;
        #pragma unroll
        for (int nt = 0; nt < 8; nt++) {
            int cl = nt * 8 + tig * 2;
            int kg = jbase + cl;
            int msk0 = s_mk[s][cl];
            int msk1 = s_mk[s][cl + 1];
            float v0 = sa[nt][0] * cs, v1 = sa[nt][1] * cs;
            float v2 = sa[nt][2] * cs, v3 = sa[nt][3] * cs;
            if (kg > qg0 || msk0)     v0 = -1e30f;
            if (kg + 1 > qg0 || msk1) v1 = -1e30f;
            if (kg > qg1 || msk0)     v2 = -1e30f;
            if (kg + 1 > qg1 || msk1) v3 = -1e30f;
            sa[nt][0] = v0; sa[nt][1] = v1; sa[nt][2] = v2; sa[nt][3] = v3;
        }

        // ---- online softmax (MUFU ex2) ----
        float rmax0 = -1e30f, rmax1 = -1e30f;
        #pragma unroll
        for (int nt = 0; nt < 8; nt++) {
            rmax0 = fmaxf(rmax0, fmaxf(sa[nt][0], sa[nt][1]));
            rmax1 = fmaxf(rmax1, fmaxf(sa[nt][2], sa[nt][3]));
        }
        rmax0 = fmaxf(rmax0, __shfl_xor_sync(0xffffffffu, rmax0, 1));
        rmax0 = fmaxf(rmax0, __shfl_xor_sync(0xffffffffu, rmax0, 2));
        rmax1 = fmaxf(rmax1, __shfl_xor_sync(0xffffffffu, rmax1, 1));
        rmax1 = fmaxf(rmax1, __shfl_xor_sync(0xffffffffu, rmax1, 2));
        float mn0 = fmaxf(m0, rmax0), mn1 = fmaxf(m1, rmax1);
        float f0 = ex2(m0 - mn0), f1 = ex2(m1 - mn1);
        float ps0 = 0.f, ps1 = 0.f;
        #pragma unroll
        for (int nt = 0; nt < 8; nt++) {
            float p0 = ex2(sa[nt][0] - mn0);
            float p1 = ex2(sa[nt][1] - mn0);
            float p2 = ex2(sa[nt][2] - mn1);
            float p3 = ex2(sa[nt][3] - mn1);
            ps0 += p0 + p1; ps1 += p2 + p3;
            sa[nt][0] = p0; sa[nt][1] = p1; sa[nt][2] = p2; sa[nt][3] = p3;
        }
        ps0 += __shfl_xor_sync(0xffffffffu, ps0, 1);
        ps0 += __shfl_xor_sync(0xffffffffu, ps0, 2);
        ps1 += __shfl_xor_sync(0xffffffffu, ps1, 1);
        ps1 += __shfl_xor_sync(0xffffffffu, ps1, 2);
        l0 = l0 * f0 + ps0; m0 = mn0;
        l1 = l1 * f1 + ps1; m1 = mn1;
        #pragma unroll
        for (int nt = 0; nt < 8; nt++) {
            o[nt][0] *= f0; o[nt][1] *= f0;
            o[nt][2] *= f1; o[nt][3] *= f1;
        }

        // ---- repack P to bf16 hi/lo A-fragments ----
        uint32_t phi[4][4], plo[4][4];
        #pragma unroll
        for (int ks = 0; ks < 4; ks++) {
            split2(sa[2 * ks][0],     sa[2 * ks][1],     phi[ks][0], plo[ks][0]);
            split2(sa[2 * ks][2],     sa[2 * ks][3],     phi[ks][1], plo[ks][1]);
            split2(sa[2 * ks + 1][0], sa[2 * ks + 1][1], phi[ks][2], plo[ks][2]);
            split2(sa[2 * ks + 1][2], sa[2 * ks + 1][3], phi[ks][3], plo[ks][3]);
        }

        // ---- O += P V (3-term split; hi/lo V frags sequential, shared regs) ----
        #pragma unroll
        for (int ks = 0; ks < 4; ks++) {
            int vrow = ks * 16 + vRowL;
            uint32_t vf[8][2];
            #pragma unroll
            for (int g = 0; g < 4; g++) {
                uint32_t off = (uint32_t)(vrow * 128 + g * 32 + vHalf * 16);
                uint32_t r0, r1, r2, r3;
                ldsm_x4t(r0, r1, r2, r3, stV + sw128(off));
                vf[g * 2][0] = r0; vf[g * 2][1] = r1;
                vf[g * 2 + 1][0] = r2; vf[g * 2 + 1][1] = r3;
            }
            #pragma unroll
            for (int nt = 0; nt < 8; nt++) {
                mma16816(o[nt], phi[ks], vf[nt]);
                mma16816(o[nt], plo[ks], vf[nt]);
            }
            #pragma unroll
            for (int g = 0; g < 4; g++) {
                uint32_t off = (uint32_t)(vrow * 128 + g * 32 + vHalf * 16);
                uint32_t r0, r1, r2, r3;
                ldsm_x4t(r0, r1, r2, r3, stV + 8192u + sw128(off));
                vf[g * 2][0] = r0; vf[g * 2][1] = r1;
                vf[g * 2 + 1][0] = r2; vf[g * 2 + 1][1] = r3;
            }
            #pragma unroll
            for (int nt = 0; nt < 8; nt++)
                mma16816(o[nt], phi[ks], vf[nt]);
        }

        __syncthreads();
        if (j + 2 < ntiles) { issue(j + 2, s); issued++; }
    }

    // ---- epilogue: normalize + fused hi/lo split ----
    float inv0 = 1.0f / l0, inv1 = 1.0f / l1;
    #pragma unroll
    for (int nt = 0; nt < 8; nt++) {
        int d = nt * 8 + tig * 2;
        int col = h * HDIM + d;
        size_t i0 = ((size_t)b * LL + qg0) * DD + col;
        size_t i1 = ((size_t)b * LL + qg1) * DD + col;
        uint32_t hi2, lo2;
        split2(o[nt][0] * inv0, o[nt][1] * inv0, hi2, lo2);
        *(uint32_t*)(g_aHi + i0) = hi2;
        *(uint32_t*)(g_aLo + i0) = lo2;
        split2(o[nt][2] * inv1, o[nt][3] * inv1, hi2, lo2);
        *(uint32_t*)(g_aHi + i1) = hi2;
        *(uint32_t*)(g_aLo + i1) = lo2;
    }
}

// ---------------- launch ----------------
extern "C" void kernel_launch(void* const* d_in, const int* in_sizes, int n_in,
                              void* d_out, int out_size) {
    const float* x  = (const float*)d_in[0];
    const unsigned char* pm = (const unsigned char*)d_in[1];
    const float* Wq = (const float*)d_in[3];
    const float* bq = (const float*)d_in[4];
    const float* Wk = (const float*)d_in[5];
    const float* bk = (const float*)d_in[6];
    const float* Wv = (const float*)d_in[7];
    const float* bv = (const float*)d_in[8];
    const float* Wo = (const float*)d_in[9];
    const float* bo = (const float*)d_in[10];
    const float* g_pre = (const float*)d_in[11];
    const float* b_pre = (const float*)d_in[12];
    const float* g_ln  = (const float*)d_in[13];
    const float* b_ln  = (const float*)d_in[14];
    float* out = (float*)d_out;

    float *ph, *py;
    __nv_bfloat16 *phHi, *phLo, *paHi, *paLo, *pwHi, *pwLo;
    __nv_bfloat16 *pqHi, *pqLo, *pkHi, *pkLo, *pvHi, *pvLo;
    cudaGetSymbolAddress((void**)&ph,   g_h);
    cudaGetSymbolAddress((void**)&py,   g_y);
    cudaGetSymbolAddress((void**)&phHi, g_hHi);
    cudaGetSymbolAddress((void**)&phLo, g_hLo);
    cudaGetSymbolAddress((void**)&paHi, g_aHi);
    cudaGetSymbolAddress((void**)&paLo, g_aLo);
    cudaGetSymbolAddress((void**)&pwHi, g_wHi);
    cudaGetSymbolAddress((void**)&pwLo, g_wLo);
    cudaGetSymbolAddress((void**)&pqHi, g_qHi);
    cudaGetSymbolAddress((void**)&pqLo, g_qLo);
    cudaGetSymbolAddress((void**)&pkHi, g_kHi);
    cudaGetSymbolAddress((void**)&pkLo, g_kLo);
    cudaGetSymbolAddress((void**)&pvHi, g_vHi);
    cudaGetSymbolAddress((void**)&pvLo, g_vLo);

    cudaFuncSetAttribute(gemm_mma<0>, cudaFuncAttributeMaxDynamicSharedMemorySize, GSMEM);
    cudaFuncSetAttribute(gemm_mma<1>, cudaFuncAttributeMaxDynamicSharedMemorySize, GSMEM);
    cudaFuncSetAttribute(attn_mma, cudaFuncAttributeMaxDynamicSharedMemorySize, ASMEM);

    convert_mask_kernel<<<1, 256>>>(pm);

    // pre-LN with fused hi/lo split
    ln_kernel<<<NROWS, 256>>>(x, (const float*)nullptr, g_pre, b_pre, ph, phHi, phLo);

    // weight splits, single launch: y = {Wq, Wk, Wv, Wo}
    const int nW = DD * DD;
    split_w_kernel<<<dim3(nW / 1024, 4), 256>>>(Wq, Wk, Wv, Wo, pwHi, pwLo);

    // QKV projections -> bf16 hi/lo (B,H,L,HD), single launch over z = {q,k,v}
    dim3 gqkv(DD / 128, NROWS / 128, 3);
    gemm_mma<1><<<gqkv, 256, GSMEM>>>(phHi, phLo, pwHi, pwLo,
                                      bq, bk, bv, nullptr,
                                      pqHi, pqLo, pkHi, pkLo, pvHi, pvLo);

    // tensor-core flash attention (writes aHi/aLo directly)
    attn_mma<<<dim3(LL / 128, BB * HH), 256, ASMEM>>>();

    // output projection (z=0 selects Wo slice at offset 3)
    dim3 gproj(DD / 128, NROWS / 128, 1);
    gemm_mma<0><<<gproj, 256, GSMEM>>>(paHi, paLo, pwHi + 3 * (size_t)nW, pwLo + 3 * (size_t)nW,
                                       bo, bo, bo, py,
                                       nullptr, nullptr, nullptr, nullptr, nullptr, nullptr);

    // residual + final LN
    ln_kernel<<<NROWS, 256>>>(py, ph, g_ln, b_ln, out, nullptr, nullptr);
}

// round 14
// speedup vs baseline: 1.6708x; 1.0414x over previous
#include <cuda_runtime.h>
#include <cuda_bf16.h>
#include <math.h>
#include <stdint.h>

#define BB 4
#define LL 2048
#define DD 1024
#define HH 16
#define HDIM 64
#define NROWS (BB * LL)   // 8192

// ---------------- scratch ----------------
__device__ float g_h[NROWS * DD];     // LN(x) fp32 (residual)
__device__ float g_y[NROWS * DD];     // O-proj out
__device__ unsigned char g_mask[NROWS];
__device__ int g_len[BB];             // valid length per batch
__device__ __nv_bfloat16 g_hHi[NROWS * DD];
__device__ __nv_bfloat16 g_hLo[NROWS * DD];
__device__ __nv_bfloat16 g_aHi[NROWS * DD];   // attention out hi/lo (B,L,D)
__device__ __nv_bfloat16 g_aLo[NROWS * DD];
__device__ __nv_bfloat16 g_wHi[4][DD * DD];
__device__ __nv_bfloat16 g_wLo[4][DD * DD];
__device__ __nv_bfloat16 g_qHi[NROWS * DD];   // (B,H,L,HD)
__device__ __nv_bfloat16 g_qLo[NROWS * DD];
__device__ __nv_bfloat16 g_kHi[NROWS * DD];
__device__ __nv_bfloat16 g_kLo[NROWS * DD];
__device__ __nv_bfloat16 g_vHi[NROWS * DD];
__device__ __nv_bfloat16 g_vLo[NROWS * DD];

// ---------------- helpers ----------------
__device__ __forceinline__ uint32_t smem_u32(const void* p) {
    uint32_t a;
    asm("{ .reg .u64 t; cvta.to.shared.u64 t, %1; cvt.u32.u64 %0, t; }" : "=r"(a) : "l"(p));
    return a;
}
__device__ __forceinline__ void ldsm_x4(uint32_t& d0, uint32_t& d1, uint32_t& d2, uint32_t& d3,
                                        uint32_t addr) {
    asm volatile("ldmatrix.sync.aligned.m8n8.x4.shared.b16 {%0,%1,%2,%3}, [%4];"
                 : "=r"(d0), "=r"(d1), "=r"(d2), "=r"(d3) : "r"(addr));
}
__device__ __forceinline__ void ldsm_x4t(uint32_t& d0, uint32_t& d1, uint32_t& d2, uint32_t& d3,
                                         uint32_t addr) {
    asm volatile("ldmatrix.sync.aligned.m8n8.x4.trans.shared.b16 {%0,%1,%2,%3}, [%4];"
                 : "=r"(d0), "=r"(d1), "=r"(d2), "=r"(d3) : "r"(addr));
}
__device__ __forceinline__ void mma16816(float* c, const uint32_t* a, const uint32_t* b) {
    asm volatile(
        "mma.sync.aligned.m16n8k16.row.col.f32.bf16.bf16.f32 "
        "{%0,%1,%2,%3}, {%4,%5,%6,%7}, {%8,%9}, {%0,%1,%2,%3};"
        : "+f"(c[0]), "+f"(c[1]), "+f"(c[2]), "+f"(c[3])
        : "r"(a[0]), "r"(a[1]), "r"(a[2]), "r"(a[3]), "r"(b[0]), "r"(b[1]));
}
__device__ __forceinline__ float ex2(float x) {
    float y;
    asm("ex2.approx.ftz.f32 %0, %1;" : "=f"(y) : "f"(x));
    return y;
}
#define CP_ASYNC16(dst, src) \
    asm volatile("cp.async.cg.shared.global [%0], [%1], 16;" :: "r"(dst), "l"(src))
#define CP_COMMIT() asm volatile("cp.async.commit_group;")
#define CP_WAIT1()  asm volatile("cp.async.wait_group 1;")
#define CP_WAIT0()  asm volatile("cp.async.wait_group 0;")

__device__ __forceinline__ uint32_t sw128(uint32_t off) {
    return off ^ ((off >> 3) & 0x70u);
}
__device__ __forceinline__ void split2(float a, float b, uint32_t& hi, uint32_t& lo) {
    __nv_bfloat16 ha = __float2bfloat16_rn(a), hb = __float2bfloat16_rn(b);
    float ra = a - __bfloat162float(ha), rb = b - __bfloat162float(hb);
    __nv_bfloat162 h2; h2.x = ha; h2.y = hb;
    __nv_bfloat162 l2; l2.x = __float2bfloat16_rn(ra); l2.y = __float2bfloat16_rn(rb);
    hi = *(uint32_t*)&h2;
    lo = *(uint32_t*)&l2;
}

// ---------------- padding-mask canonicalization + per-batch length ----------------
__global__ void convert_mask_kernel(const unsigned char* __restrict__ pm) {
    __shared__ int fz0, fz3;
    int tid = threadIdx.x;
    if (tid == 0) { fz0 = 0; fz3 = 0; }
    if (tid < BB) g_len[tid] = 0;
    __syncthreads();
    int z0 = 0, z3 = 0;
    for (int j = tid; j < NROWS; j += blockDim.x) {
        unsigned char v = pm[j];
        if (v) {
            if ((j & 3) == 0) z0 = 1;
            if ((j & 3) == 3) z3 = 1;
        }
    }
    if (z0) atomicOr(&fz0, 1);
    if (z3) atomicOr(&fz3, 1);
    __syncthreads();
    int mode;
    if (!fz3) mode = fz0 ? 3 : 0;
    else      mode = fz0 ? 1 : 2;
    int cnt[BB];
    #pragma unroll
    for (int b = 0; b < BB; b++) cnt[b] = 0;
    for (int i = tid; i < NROWS; i += blockDim.x) {
        unsigned char r;
        if (mode == 0)      r = 0;
        else if (mode == 1) r = (pm[i] != 0);
        else if (mode == 2) r = (((const float*)pm)[i] != 0.0f);
        else                r = (((const int*)pm)[i] != 0);
        g_mask[i] = r;
        if (!r) cnt[i >> 11]++;
    }
    #pragma unroll
    for (int b = 0; b < BB; b++)
        if (cnt[b]) atomicAdd(&g_len[b], cnt[b]);
}

// ---------------- fp32 -> bf16 hi/lo split, 4 weights in one launch ----------------
__global__ void split_w_kernel(const float* __restrict__ s0, const float* __restrict__ s1,
                               const float* __restrict__ s2, const float* __restrict__ s3,
                               __nv_bfloat16* __restrict__ hiB,
                               __nv_bfloat16* __restrict__ loB) {
    int w = blockIdx.y;
    const float* src = (w == 0) ? s0 : (w == 1) ? s1 : (w == 2) ? s2 : s3;
    size_t off = (size_t)w * DD * DD;
    int i = (blockIdx.x * blockDim.x + threadIdx.x) * 4;
    float4 v = *(const float4*)(src + i);
    uint32_t h01, l01, h23, l23;
    split2(v.x, v.y, h01, l01);
    split2(v.z, v.w, h23, l23);
    *(uint32_t*)(hiB + off + i) = h01; *(uint32_t*)(hiB + off + i + 2) = h23;
    *(uint32_t*)(loB + off + i) = l01; *(uint32_t*)(loB + off + i + 2) = l23;
}

// ---------------- LayerNorm (optional residual; optional fused hi/lo split) ----------------
__global__ void ln_kernel(const float* __restrict__ x, const float* __restrict__ res,
                          const float* __restrict__ gamma, const float* __restrict__ beta,
                          float* __restrict__ out,
                          __nv_bfloat16* __restrict__ outHi,
                          __nv_bfloat16* __restrict__ outLo) {
    int row = blockIdx.x;
    int tid = threadIdx.x;
    const float4* xr = (const float4*)(x + (size_t)row * DD);
    float4 v = xr[tid];
    if (res) {
        const float4* rr = (const float4*)(res + (size_t)row * DD);
        float4 r2 = rr[tid];
        v.x += r2.x; v.y += r2.y; v.z += r2.z; v.w += r2.w;
    }
    float s  = v.x + v.y + v.z + v.w;
    float ss = v.x * v.x + v.y * v.y + v.z * v.z + v.w * v.w;
    for (int off = 16; off > 0; off >>= 1) {
        s  += __shfl_down_sync(0xffffffffu, s, off);
        ss += __shfl_down_sync(0xffffffffu, ss, off);
    }
    __shared__ float rs[8], rss[8];
    __shared__ float s_mu, s_rsig;
    int wid = tid >> 5, lane = tid & 31;
    if (lane == 0) { rs[wid] = s; rss[wid] = ss; }
    __syncthreads();
    if (tid == 0) {
        float S = 0.f, SS = 0.f;
        #pragma unroll
        for (int i = 0; i < 8; i++) { S += rs[i]; SS += rss[i]; }
        float mu  = S * (1.0f / DD);
        float var = SS * (1.0f / DD) - mu * mu;
        s_mu = mu;
        s_rsig = rsqrtf(var + 1e-5f);
    }
    __syncthreads();
    float mu = s_mu, rsig = s_rsig;
    float4 gv = ((const float4*)gamma)[tid];
    float4 bv = ((const float4*)beta)[tid];
    float4 o;
    o.x = (v.x - mu) * rsig * gv.x + bv.x;
    o.y = (v.y - mu) * rsig * gv.y + bv.y;
    o.z = (v.z - mu) * rsig * gv.z + bv.z;
    o.w = (v.w - mu) * rsig * gv.w + bv.w;
    ((float4*)(out + (size_t)row * DD))[tid] = o;
    if (outHi) {
        size_t i = (size_t)row * DD + tid * 4;
        uint32_t h01, l01, h23, l23;
        split2(o.x, o.y, h01, l01);
        split2(o.z, o.w, h23, l23);
        *(uint32_t*)(outHi + i) = h01; *(uint32_t*)(outHi + i + 2) = h23;
        *(uint32_t*)(outLo + i) = l01; *(uint32_t*)(outLo + i + 2) = l23;
    }
}

// ---------------- mma.sync split-bf16 GEMM, fused hi|lo rows, BK=32 ----------------
// smem row (128B) = [hi 64B | lo 64B] for A and B. Each chunk stages all 4 arrays
// once and computes all 3 split terms: Ahi*Bhi + Alo*Bhi + Ahi*Blo.
#define GSMEM (64 * 1024)

template <int MODE>
__global__ __launch_bounds__(256, 2)
void gemm_mma(const __nv_bfloat16* __restrict__ Ahi, const __nv_bfloat16* __restrict__ Alo,
              const __nv_bfloat16* __restrict__ WHiB, const __nv_bfloat16* __restrict__ WLoB,
              const float* __restrict__ b0, const float* __restrict__ b1, const float* __restrict__ b2,
              float* __restrict__ C,
              __nv_bfloat16* __restrict__ h0, __nv_bfloat16* __restrict__ l0_,
              __nv_bfloat16* __restrict__ h1, __nv_bfloat16* __restrict__ l1_,
              __nv_bfloat16* __restrict__ h2, __nv_bfloat16* __restrict__ l2_) {
    extern __shared__ char dsm[];
    __shared__ float s_bias[128];

    int tid = threadIdx.x;
    int wid = tid >> 5;
    int lane = tid & 31;
    int warp_m = wid & 3;
    int warp_n = wid >> 2;
    int rowA0 = blockIdx.y * 128;
    int colB0 = blockIdx.x * 128;
    int z = blockIdx.z;

    // K/V rows fully inside the padding suffix are never consumed: skip the CTA.
    if (MODE == 1 && z >= 1) {
        if ((rowA0 & 2047) >= g_len[rowA0 >> 11]) return;
    }

    const __nv_bfloat16* Bhi = WHiB + (size_t)z * DD * DD;
    const __nv_bfloat16* Blo = WLoB + (size_t)z * DD * DD;
    const float* bias = (z == 0) ? b0 : (z == 1) ? b1 : b2;
    __nv_bfloat16* CHi = (z == 0) ? h0 : (z == 1) ? h1 : h2;
    __nv_bfloat16* CLo = (z == 0) ? l0_ : (z == 1) ? l1_ : l2_;

    uint32_t base = smem_u32(dsm);
    uint32_t aBase[2] = { base, base + 32768u };
    uint32_t bBase[2] = { base + 16384u, base + 49152u };

    if (tid < 128) s_bias[tid] = bias[colB0 + tid];

    // per-thread load map: 4 chunks of 16B per tile per stage (1024 chunks total)
    // lin = it*256+tid: row = lin>>3, c8 = lin&7 (0-3: hi half, 4-7: lo half)
    int ldRow[4], ldOff[4], ldHiSel[4];
    uint32_t ldSw[4];
    #pragma unroll
    for (int it = 0; it < 4; it++) {
        int lin = it * 256 + tid;
        ldRow[it] = lin >> 3;
        int c8 = lin & 7;
        ldHiSel[it] = (c8 < 4);
        ldOff[it] = (c8 & 3) * 8;
        ldSw[it] = sw128((uint32_t)(ldRow[it] * 128 + c8 * 16));
    }

    auto issue = [&](int c, int s) {
        int k0 = c * 32;
        #pragma unroll
        for (int it = 0; it < 4; it++) {
            const __nv_bfloat16* a = (ldHiSel[it] ? Ahi : Alo) +
                (size_t)(rowA0 + ldRow[it]) * DD + k0 + ldOff[it];
            CP_ASYNC16(aBase[s] + ldSw[it], a);
            const __nv_bfloat16* bb = (ldHiSel[it] ? Bhi : Blo) +
                (size_t)(colB0 + ldRow[it]) * DD + k0 + ldOff[it];
            CP_ASYNC16(bBase[s] + ldSw[it], bb);
        }
        CP_COMMIT();
    };

    float acc[2][8][4];
    #pragma unroll
    for (int mt = 0; mt < 2; mt++)
        #pragma unroll
        for (int nt = 0; nt < 8; nt++)
            #pragma unroll
            for (int q = 0; q < 4; q++) acc[mt][nt][q] = 0.f;

    int aRow = warp_m * 32 + (lane & 15);
    int aChunkHalf = lane >> 4;
    int bRow = warp_n * 64 + (lane >> 4) * 8 + (lane & 7);
    int bChunkHalf = (lane >> 3) & 1;

    issue(0, 0);

    for (int i = 0; i < 32; i++) {
        int s = i & 1;
        if (i < 31) issue(i + 1, s ^ 1);
        if (i < 31) { CP_WAIT1(); } else { CP_WAIT0(); }
        __syncthreads();

        #pragma unroll
        for (int ks = 0; ks < 2; ks++) {
            uint32_t afh[2][4], afl[2][4];
            #pragma unroll
            for (int mt = 0; mt < 2; mt++) {
                uint32_t off = (uint32_t)((aRow + mt * 16) * 128 + (ks * 2 + aChunkHalf) * 16);
                ldsm_x4(afh[mt][0], afh[mt][1], afh[mt][2], afh[mt][3], aBase[s] + sw128(off));
                ldsm_x4(afl[mt][0], afl[mt][1], afl[mt][2], afl[mt][3], aBase[s] + sw128(off + 64u));
            }
            uint32_t bf[8][2];
            // Bhi fragments -> Ahi*Bhi and Alo*Bhi
            #pragma unroll
            for (int j2 = 0; j2 < 4; j2++) {
                uint32_t off = (uint32_t)((bRow + j2 * 16) * 128 + (ks * 2 + bChunkHalf) * 16);
                uint32_t r0, r1, r2, r3;
                ldsm_x4(r0, r1, r2, r3, bBase[s] + sw128(off));
                bf[j2 * 2][0] = r0; bf[j2 * 2][1] = r1;
                bf[j2 * 2 + 1][0] = r2; bf[j2 * 2 + 1][1] = r3;
            }
            #pragma unroll
            for (int mt = 0; mt < 2; mt++)
                #pragma unroll
                for (int nt = 0; nt < 8; nt++)
                    mma16816(acc[mt][nt], afh[mt], bf[nt]);
            #pragma unroll
            for (int mt = 0; mt < 2; mt++)
                #pragma unroll
                for (int nt = 0; nt < 8; nt++)
                    mma16816(acc[mt][nt], afl[mt], bf[nt]);
            // Blo fragments -> Ahi*Blo
            #pragma unroll
            for (int j2 = 0; j2 < 4; j2++) {
                uint32_t off = (uint32_t)((bRow + j2 * 16) * 128 + (ks * 2 + bChunkHalf) * 16 + 64);
                uint32_t r0, r1, r2, r3;
                ldsm_x4(r0, r1, r2, r3, bBase[s] + sw128(off));
                bf[j2 * 2][0] = r0; bf[j2 * 2][1] = r1;
                bf[j2 * 2 + 1][0] = r2; bf[j2 * 2 + 1][1] = r3;
            }
            #pragma unroll
            for (int mt = 0; mt < 2; mt++)
                #pragma unroll
                for (int nt = 0; nt < 8; nt++)
                    mma16816(acc[mt][nt], afh[mt], bf[nt]);
        }
        __syncthreads();
    }

    int gid = lane >> 2, tig = lane & 3;
    #pragma unroll
    for (int mt = 0; mt < 2; mt++) {
        #pragma unroll
        for (int half = 0; half < 2; half++) {
            int m = rowA0 + warp_m * 32 + mt * 16 + gid + half * 8;
            #pragma unroll
            for (int nt = 0; nt < 8; nt++) {
                int col = colB0 + warp_n * 64 + nt * 8 + tig * 2;
                float vx = acc[mt][nt][half * 2 + 0] + s_bias[col - colB0];
                float vy = acc[mt][nt][half * 2 + 1] + s_bias[col - colB0 + 1];
                if (MODE == 0) {
                    float2 v; v.x = vx; v.y = vy;
                    *(float2*)(C + (size_t)m * DD + col) = v;
                } else {
                    int b = m >> 11, l = m & 2047;
                    int hh = col >> 6, hd = col & 63;
                    size_t idx = (((size_t)(b * HH + hh)) * LL + l) * HDIM + hd;
                    uint32_t hi2, lo2;
                    split2(vx, vy, hi2, lo2);
                    *(uint32_t*)(CHi + idx) = hi2;
                    *(uint32_t*)(CLo + idx) = lo2;
                }
            }
        }
    }
}

// ---------------- tensor-core flash attention (R12 champion) ----------------
#define ASMEM (64 * 1024)

__global__ __launch_bounds__(256, 2)
void attn_mma() {
    extern __shared__ char dsm[];
    __shared__ unsigned char s_mk[2][64];

    int tid = threadIdx.x;
    int wid = tid >> 5;
    int lane = tid & 31;
    int gid = lane >> 2, tig = lane & 3;
    int qt = blockIdx.x;
    int bh = blockIdx.y;
    int b = bh >> 4, h = bh & 15;
    int qbase = qt * 128;

    uint32_t base = smem_u32(dsm);
    // stage s: Khi @ s*32768, Klo +8192, Vhi +16384, Vlo +24576

    const __nv_bfloat16* qHi = g_qHi + ((size_t)bh * LL + qbase) * HDIM;
    const __nv_bfloat16* qLo = g_qLo + ((size_t)bh * LL + qbase) * HDIM;

    #pragma unroll
    for (int it = 0; it < 4; it++) {
        int c = it * 256 + tid;
        int row = c >> 3, col16 = c & 7;
        uint32_t sw = sw128((uint32_t)(row * 128 + col16 * 16));
        CP_ASYNC16(base + sw, qHi + row * HDIM + col16 * 8);
        CP_ASYNC16(base + 16384u + sw, qLo + row * HDIM + col16 * 8);
    }
    CP_COMMIT();
    CP_WAIT0();
    __syncthreads();

    uint32_t qh[4][4], ql[4][4];
    {
        int arow = wid * 16 + (lane & 15);
        int ahalf = lane >> 4;
        #pragma unroll
        for (int ks = 0; ks < 4; ks++) {
            uint32_t off = (uint32_t)(arow * 128 + (ks * 2 + ahalf) * 16);
            ldsm_x4(qh[ks][0], qh[ks][1], qh[ks][2], qh[ks][3], base + sw128(off));
            ldsm_x4(ql[ks][0], ql[ks][1], ql[ks][2], ql[ks][3], base + 16384u + sw128(off));
        }
    }
    __syncthreads();

    int len = g_len[b];
    int ntiles_c = 2 * qt + 2;
    int ntiles_v = (len + 63) >> 6;
    int ntiles = (ntiles_c < ntiles_v) ? ntiles_c : ntiles_v;

    auto issue = [&](int j, int s) {
        uint32_t st = base + (uint32_t)s * 32768u;
        size_t goff = ((size_t)bh * LL + j * 64) * HDIM;
        #pragma unroll
        for (int it = 0; it < 2; it++) {
            int c = it * 256 + tid;
            int row = c >> 3, col16 = c & 7;
            uint32_t sw = sw128((uint32_t)(row * 128 + col16 * 16));
            size_t so = goff + row * HDIM + col16 * 8;
            CP_ASYNC16(st + sw,          g_kHi + so);
            CP_ASYNC16(st + 8192u + sw,  g_kLo + so);
            CP_ASYNC16(st + 16384u + sw, g_vHi + so);
            CP_ASYNC16(st + 24576u + sw, g_vLo + so);
        }
        if (tid < 64) s_mk[s][tid] = g_mask[b * LL + j * 64 + tid];
        CP_COMMIT();
    };

    float o[8][4];
    #pragma unroll
    for (int nt = 0; nt < 8; nt++)
        #pragma unroll
        for (int q = 0; q < 4; q++) o[nt][q] = 0.f;
    float m0 = -1e30f, m1 = -1e30f, l0 = 0.f, l1 = 0.f;

    const float cs = 0.125f * 1.4426950408889634f;  // 1/sqrt(HD) * log2(e)
    int qg0 = qbase + wid * 16 + gid;
    int qg1 = qg0 + 8;

    issue(0, 0);
    int issued = 1;
    if (ntiles > 1) { issue(1, 1); issued = 2; }

    int kRow = (lane >> 4) * 8 + (lane & 7);
    int kHalf = (lane >> 3) & 1;
    int vRowL = lane & 15;
    int vHalf = lane >> 4;

    for (int j = 0; j < ntiles; j++) {
        int s = j & 1;
        if (issued > j + 1) { CP_WAIT1(); } else { CP_WAIT0(); }
        __syncthreads();

        uint32_t stK = base + (uint32_t)s * 32768u;
        uint32_t stV = stK + 16384u;

        float sa[8][4];
        #pragma unroll
        for (int nt = 0; nt < 8; nt++)
            #pragma unroll
            for (int q = 0; q < 4; q++) sa[nt][q] = 0.f;

        #pragma unroll
        for (int ks = 0; ks < 4; ks++) {
            uint32_t kf[8][2];
            #pragma unroll
            for (int j2 = 0; j2 < 4; j2++) {
                uint32_t off = (uint32_t)((kRow + j2 * 16) * 128 + (ks * 2 + kHalf) * 16);
                uint32_t r0, r1, r2, r3;
                ldsm_x4(r0, r1, r2, r3, stK + sw128(off));
                kf[j2 * 2][0] = r0; kf[j2 * 2][1] = r1;
                kf[j2 * 2 + 1][0] = r2; kf[j2 * 2 + 1][1] = r3;
            }
            #pragma unroll
            for (int nt = 0; nt < 8; nt++) {
                mma16816(sa[nt], qh[ks], kf[nt]);
                mma16816(sa[nt], ql[ks], kf[nt]);
            }
            #pragma unroll
            for (int j2 = 0; j2 < 4; j2++) {
                uint32_t off = (uint32_t)((kRow + j2 * 16) * 128 + (ks * 2 + kHalf) * 16);
                uint32_t r0, r1, r2, r3;
                ldsm_x4(r0, r1, r2, r3, stK + 8192u + sw128(off));
                kf[j2 * 2][0] = r0; kf[j2 * 2][1] = r1;
                kf[j2 * 2 + 1][0] = r2; kf[j2 * 2 + 1][1] = r3;
            }
            #pragma unroll
            for (int nt = 0; nt < 8; nt++)
                mma16816(sa[nt], qh[ks], kf[nt]);
        }

        int jbase = j * 64;
        #pragma unroll
        for (int nt = 0; nt < 8; nt++) {
            int cl = nt * 8 + tig * 2;
            int kg = jbase + cl;
            int msk0 = s_mk[s][cl];
            int msk1 = s_mk[s][cl + 1];
            float v0 = sa[nt][0] * cs, v1 = sa[nt][1] * cs;
            float v2 = sa[nt][2] * cs, v3 = sa[nt][3] * cs;
            if (kg > qg0 || msk0)     v0 = -1e30f;
            if (kg + 1 > qg0 || msk1) v1 = -1e30f;
            if (kg > qg1 || msk0)     v2 = -1e30f;
            if (kg + 1 > qg1 || msk1) v3 = -1e30f;
            sa[nt][0] = v0; sa[nt][1] = v1; sa[nt][2] = v2; sa[nt][3] = v3;
        }

        float rmax0 = -1e30f, rmax1 = -1e30f;
        #pragma unroll
        for (int nt = 0; nt < 8; nt++) {
            rmax0 = fmaxf(rmax0, fmaxf(sa[nt][0], sa[nt][1]));
            rmax1 = fmaxf(rmax1, fmaxf(sa[nt][2], sa[nt][3]));
        }
        rmax0 = fmaxf(rmax0, __shfl_xor_sync(0xffffffffu, rmax0, 1));
        rmax0 = fmaxf(rmax0, __shfl_xor_sync(0xffffffffu, rmax0, 2));
        rmax1 = fmaxf(rmax1, __shfl_xor_sync(0xffffffffu, rmax1, 1));
        rmax1 = fmaxf(rmax1, __shfl_xor_sync(0xffffffffu, rmax1, 2));
        float mn0 = fmaxf(m0, rmax0), mn1 = fmaxf(m1, rmax1);
        float f0 = ex2(m0 - mn0), f1 = ex2(m1 - mn1);
        float ps0 = 0.f, ps1 = 0.f;
        #pragma unroll
        for (int nt = 0; nt < 8; nt++) {
            float p0 = ex2(sa[nt][0] - mn0);
            float p1 = ex2(sa[nt][1] - mn0);
            float p2 = ex2(sa[nt][2] - mn1);
            float p3 = ex2(sa[nt][3] - mn1);
            ps0 += p0 + p1; ps1 += p2 + p3;
            sa[nt][0] = p0; sa[nt][1] = p1; sa[nt][2] = p2; sa[nt][3] = p3;
        }
        ps0 += __shfl_xor_sync(0xffffffffu, ps0, 1);
        ps0 += __shfl_xor_sync(0xffffffffu, ps0, 2);
        ps1 += __shfl_xor_sync(0xffffffffu, ps1, 1);
        ps1 += __shfl_xor_sync(0xffffffffu, ps1, 2);
        l0 = l0 * f0 + ps0; m0 = mn0;
        l1 = l1 * f1 + ps1; m1 = mn1;
        #pragma unroll
        for (int nt = 0; nt < 8; nt++) {
            o[nt][0] *= f0; o[nt][1] *= f0;
            o[nt][2] *= f1; o[nt][3] *= f1;
        }

        uint32_t phi[4][4], plo[4][4];
        #pragma unroll
        for (int ks = 0; ks < 4; ks++) {
            split2(sa[2 * ks][0],     sa[2 * ks][1],     phi[ks][0], plo[ks][0]);
            split2(sa[2 * ks][2],     sa[2 * ks][3],     phi[ks][1], plo[ks][1]);
            split2(sa[2 * ks + 1][0], sa[2 * ks + 1][1], phi[ks][2], plo[ks][2]);
            split2(sa[2 * ks + 1][2], sa[2 * ks + 1][3], phi[ks][3], plo[ks][3]);
        }

        #pragma unroll
        for (int ks = 0; ks < 4; ks++) {
            int vrow = ks * 16 + vRowL;
            uint32_t vf[8][2];
            #pragma unroll
            for (int g = 0; g < 4; g++) {
                uint32_t off = (uint32_t)(vrow * 128 + g * 32 + vHalf * 16);
                uint32_t r0, r1, r2, r3;
                ldsm_x4t(r0, r1, r2, r3, stV + sw128(off));
                vf[g * 2][0] = r0; vf[g * 2][1] = r1;
                vf[g * 2 + 1][0] = r2; vf[g * 2 + 1][1] = r3;
            }
            #pragma unroll
            for (int nt = 0; nt < 8; nt++) {
                mma16816(o[nt], phi[ks], vf[nt]);
                mma16816(o[nt], plo[ks], vf[nt]);
            }
            #pragma unroll
            for (int g = 0; g < 4; g++) {
                uint32_t off = (uint32_t)(vrow * 128 + g * 32 + vHalf * 16);
                uint32_t r0, r1, r2, r3;
                ldsm_x4t(r0, r1, r2, r3, stV + 8192u + sw128(off));
                vf[g * 2][0] = r0; vf[g * 2][1] = r1;
                vf[g * 2 + 1][0] = r2; vf[g * 2 + 1][1] = r3;
            }
            #pragma unroll
            for (int nt = 0; nt < 8; nt++)
                mma16816(o[nt], phi[ks], vf[nt]);
        }

        __syncthreads();
        if (j + 2 < ntiles) { issue(j + 2, s); issued++; }
    }

    float inv0 = 1.0f / l0, inv1 = 1.0f / l1;
    #pragma unroll
    for (int nt = 0; nt < 8; nt++) {
        int d = nt * 8 + tig * 2;
        int col = h * HDIM + d;
        size_t i0 = ((size_t)b * LL + qg0) * DD + col;
        size_t i1 = ((size_t)b * LL + qg1) * DD + col;
        uint32_t hi2, lo2;
        split2(o[nt][0] * inv0, o[nt][1] * inv0, hi2, lo2);
        *(uint32_t*)(g_aHi + i0) = hi2;
        *(uint32_t*)(g_aLo + i0) = lo2;
        split2(o[nt][2] * inv1, o[nt][3] * inv1, hi2, lo2);
        *(uint32_t*)(g_aHi + i1) = hi2;
        *(uint32_t*)(g_aLo + i1) = lo2;
    }
}

// ---------------- launch ----------------
extern "C" void kernel_launch(void* const* d_in, const int* in_sizes, int n_in,
                              void* d_out, int out_size) {
    const float* x  = (const float*)d_in[0];
    const unsigned char* pm = (const unsigned char*)d_in[1];
    const float* Wq = (const float*)d_in[3];
    const float* bq = (const float*)d_in[4];
    const float* Wk = (const float*)d_in[5];
    const float* bk = (const float*)d_in[6];
    const float* Wv = (const float*)d_in[7];
    const float* bv = (const float*)d_in[8];
    const float* Wo = (const float*)d_in[9];
    const float* bo = (const float*)d_in[10];
    const float* g_pre = (const float*)d_in[11];
    const float* b_pre = (const float*)d_in[12];
    const float* g_ln  = (const float*)d_in[13];
    const float* b_ln  = (const float*)d_in[14];
    float* out = (float*)d_out;

    float *ph, *py;
    __nv_bfloat16 *phHi, *phLo, *paHi, *paLo, *pwHi, *pwLo;
    __nv_bfloat16 *pqHi, *pqLo, *pkHi, *pkLo, *pvHi, *pvLo;
    cudaGetSymbolAddress((void**)&ph,   g_h);
    cudaGetSymbolAddress((void**)&py,   g_y);
    cudaGetSymbolAddress((void**)&phHi, g_hHi);
    cudaGetSymbolAddress((void**)&phLo, g_hLo);
    cudaGetSymbolAddress((void**)&paHi, g_aHi);
    cudaGetSymbolAddress((void**)&paLo, g_aLo);
    cudaGetSymbolAddress((void**)&pwHi, g_wHi);
    cudaGetSymbolAddress((void**)&pwLo, g_wLo);
    cudaGetSymbolAddress((void**)&pqHi, g_qHi);
    cudaGetSymbolAddress((void**)&pqLo, g_qLo);
    cudaGetSymbolAddress((void**)&pkHi, g_kHi);
    cudaGetSymbolAddress((void**)&pkLo, g_kLo);
    cudaGetSymbolAddress((void**)&pvHi, g_vHi);
    cudaGetSymbolAddress((void**)&pvLo, g_vLo);

    cudaFuncSetAttribute(gemm_mma<0>, cudaFuncAttributeMaxDynamicSharedMemorySize, GSMEM);
    cudaFuncSetAttribute(gemm_mma<1>, cudaFuncAttributeMaxDynamicSharedMemorySize, GSMEM);
    cudaFuncSetAttribute(attn_mma, cudaFuncAttributeMaxDynamicSharedMemorySize, ASMEM);

    convert_mask_kernel<<<1, 256>>>(pm);

    // pre-LN with fused hi/lo split
    ln_kernel<<<NROWS, 256>>>(x, (const float*)nullptr, g_pre, b_pre, ph, phHi, phLo);

    // weight splits, single launch: y = {Wq, Wk, Wv, Wo}
    const int nW = DD * DD;
    split_w_kernel<<<dim3(nW / 1024, 4), 256>>>(Wq, Wk, Wv, Wo, pwHi, pwLo);

    // QKV projections -> bf16 hi/lo (B,H,L,HD), single launch over z = {q,k,v}
    dim3 gqkv(DD / 128, NROWS / 128, 3);
    gemm_mma<1><<<gqkv, 256, GSMEM>>>(phHi, phLo, pwHi, pwLo,
                                      bq, bk, bv, nullptr,
                                      pqHi, pqLo, pkHi, pkLo, pvHi, pvLo);

    // tensor-core flash attention (writes aHi/aLo directly)
    attn_mma<<<dim3(LL / 128, BB * HH), 256, ASMEM>>>();

    // output projection (z=0 selects Wo slice at offset 3)
    dim3 gproj(DD / 128, NROWS / 128, 1);
    gemm_mma<0><<<gproj, 256, GSMEM>>>(paHi, paLo, pwHi + 3 * (size_t)nW, pwLo + 3 * (size_t)nW,
                                       bo, bo, bo, py,
                                       nullptr, nullptr, nullptr, nullptr, nullptr, nullptr);

    // residual + final LN
    ln_kernel<<<NROWS, 256>>>(py, ph, g_ln, b_ln, out, nullptr, nullptr);
}

// round 16
// speedup vs baseline: 1.6709x; 1.0001x over previous
#include <cuda_runtime.h>
#include <cuda_bf16.h>
#include <math.h>
#include <stdint.h>

#define BB 4
#define LL 2048
#define DD 1024
#define HH 16
#define HDIM 64
#define NROWS (BB * LL)   // 8192

// ---------------- scratch ----------------
__device__ float g_h[NROWS * DD];     // LN(x) fp32 (residual)
__device__ float g_y[NROWS * DD];     // O-proj out
__device__ unsigned char g_mask[NROWS];
__device__ int g_len[BB];             // valid length per batch
__device__ __nv_bfloat16 g_hHi[NROWS * DD];
__device__ __nv_bfloat16 g_hLo[NROWS * DD];
__device__ __nv_bfloat16 g_aHi[NROWS * DD];   // attention out hi/lo (B,L,D)
__device__ __nv_bfloat16 g_aLo[NROWS * DD];
__device__ __nv_bfloat16 g_wHi[4][DD * DD];
__device__ __nv_bfloat16 g_wLo[4][DD * DD];
__device__ __nv_bfloat16 g_qHi[NROWS * DD];   // (B,H,L,HD)
__device__ __nv_bfloat16 g_qLo[NROWS * DD];
__device__ __nv_bfloat16 g_kHi[NROWS * DD];
__device__ __nv_bfloat16 g_kLo[NROWS * DD];
__device__ __nv_bfloat16 g_vHi[NROWS * DD];
__device__ __nv_bfloat16 g_vLo[NROWS * DD];

// ---------------- helpers ----------------
__device__ __forceinline__ uint32_t smem_u32(const void* p) {
    uint32_t a;
    asm("{ .reg .u64 t; cvta.to.shared.u64 t, %1; cvt.u32.u64 %0, t; }" : "=r"(a) : "l"(p));
    return a;
}
__device__ __forceinline__ void ldsm_x4(uint32_t& d0, uint32_t& d1, uint32_t& d2, uint32_t& d3,
                                        uint32_t addr) {
    asm volatile("ldmatrix.sync.aligned.m8n8.x4.shared.b16 {%0,%1,%2,%3}, [%4];"
                 : "=r"(d0), "=r"(d1), "=r"(d2), "=r"(d3) : "r"(addr));
}
__device__ __forceinline__ void ldsm_x4t(uint32_t& d0, uint32_t& d1, uint32_t& d2, uint32_t& d3,
                                         uint32_t addr) {
    asm volatile("ldmatrix.sync.aligned.m8n8.x4.trans.shared.b16 {%0,%1,%2,%3}, [%4];"
                 : "=r"(d0), "=r"(d1), "=r"(d2), "=r"(d3) : "r"(addr));
}
__device__ __forceinline__ void mma16816(float* c, const uint32_t* a, const uint32_t* b) {
    asm volatile(
        "mma.sync.aligned.m16n8k16.row.col.f32.bf16.bf16.f32 "
        "{%0,%1,%2,%3}, {%4,%5,%6,%7}, {%8,%9}, {%0,%1,%2,%3};"
        : "+f"(c[0]), "+f"(c[1]), "+f"(c[2]), "+f"(c[3])
        : "r"(a[0]), "r"(a[1]), "r"(a[2]), "r"(a[3]), "r"(b[0]), "r"(b[1]));
}
__device__ __forceinline__ float ex2(float x) {
    float y;
    asm("ex2.approx.ftz.f32 %0, %1;" : "=f"(y) : "f"(x));
    return y;
}
#define CP_ASYNC16(dst, src) \
    asm volatile("cp.async.cg.shared.global [%0], [%1], 16;" :: "r"(dst), "l"(src))
#define CP_COMMIT() asm volatile("cp.async.commit_group;")
#define CP_WAIT1()  asm volatile("cp.async.wait_group 1;")
#define CP_WAIT0()  asm volatile("cp.async.wait_group 0;")

__device__ __forceinline__ uint32_t sw128(uint32_t off) {
    return off ^ ((off >> 3) & 0x70u);
}
__device__ __forceinline__ void split2(float a, float b, uint32_t& hi, uint32_t& lo) {
    __nv_bfloat16 ha = __float2bfloat16_rn(a), hb = __float2bfloat16_rn(b);
    float ra = a - __bfloat162float(ha), rb = b - __bfloat162float(hb);
    __nv_bfloat162 h2; h2.x = ha; h2.y = hb;
    __nv_bfloat162 l2; l2.x = __float2bfloat16_rn(ra); l2.y = __float2bfloat16_rn(rb);
    hi = *(uint32_t*)&h2;
    lo = *(uint32_t*)&l2;
}

// ---------------- padding-mask canonicalization + per-batch length ----------------
__global__ void convert_mask_kernel(const unsigned char* __restrict__ pm) {
    __shared__ int fz0, fz3;
    int tid = threadIdx.x;
    if (tid == 0) { fz0 = 0; fz3 = 0; }
    if (tid < BB) g_len[tid] = 0;
    __syncthreads();
    int z0 = 0, z3 = 0;
    for (int j = tid; j < NROWS; j += blockDim.x) {
        unsigned char v = pm[j];
        if (v) {
            if ((j & 3) == 0) z0 = 1;
            if ((j & 3) == 3) z3 = 1;
        }
    }
    if (z0) atomicOr(&fz0, 1);
    if (z3) atomicOr(&fz3, 1);
    __syncthreads();
    int mode;
    if (!fz3) mode = fz0 ? 3 : 0;
    else      mode = fz0 ? 1 : 2;
    int cnt[BB];
    #pragma unroll
    for (int b = 0; b < BB; b++) cnt[b] = 0;
    for (int i = tid; i < NROWS; i += blockDim.x) {
        unsigned char r;
        if (mode == 0)      r = 0;
        else if (mode == 1) r = (pm[i] != 0);
        else if (mode == 2) r = (((const float*)pm)[i] != 0.0f);
        else                r = (((const int*)pm)[i] != 0);
        g_mask[i] = r;
        if (!r) cnt[i >> 11]++;
    }
    #pragma unroll
    for (int b = 0; b < BB; b++)
        if (cnt[b]) atomicAdd(&g_len[b], cnt[b]);
}

// ---------------- fp32 -> bf16 hi/lo split, 4 weights in one launch ----------------
__global__ void split_w_kernel(const float* __restrict__ s0, const float* __restrict__ s1,
                               const float* __restrict__ s2, const float* __restrict__ s3,
                               __nv_bfloat16* __restrict__ hiB,
                               __nv_bfloat16* __restrict__ loB) {
    int w = blockIdx.y;
    const float* src = (w == 0) ? s0 : (w == 1) ? s1 : (w == 2) ? s2 : s3;
    size_t off = (size_t)w * DD * DD;
    int i = (blockIdx.x * blockDim.x + threadIdx.x) * 4;
    float4 v = *(const float4*)(src + i);
    uint32_t h01, l01, h23, l23;
    split2(v.x, v.y, h01, l01);
    split2(v.z, v.w, h23, l23);
    *(uint32_t*)(hiB + off + i) = h01; *(uint32_t*)(hiB + off + i + 2) = h23;
    *(uint32_t*)(loB + off + i) = l01; *(uint32_t*)(loB + off + i + 2) = l23;
}

// ---------------- LayerNorm (optional residual; optional fused hi/lo split) ----------------
__global__ void ln_kernel(const float* __restrict__ x, const float* __restrict__ res,
                          const float* __restrict__ gamma, const float* __restrict__ beta,
                          float* __restrict__ out,
                          __nv_bfloat16* __restrict__ outHi,
                          __nv_bfloat16* __restrict__ outLo) {
    int row = blockIdx.x;
    int tid = threadIdx.x;
    const float4* xr = (const float4*)(x + (size_t)row * DD);
    float4 v = xr[tid];
    if (res) {
        const float4* rr = (const float4*)(res + (size_t)row * DD);
        float4 r2 = rr[tid];
        v.x += r2.x; v.y += r2.y; v.z += r2.z; v.w += r2.w;
    }
    float s  = v.x + v.y + v.z + v.w;
    float ss = v.x * v.x + v.y * v.y + v.z * v.z + v.w * v.w;
    for (int off = 16; off > 0; off >>= 1) {
        s  += __shfl_down_sync(0xffffffffu, s, off);
        ss += __shfl_down_sync(0xffffffffu, ss, off);
    }
    __shared__ float rs[8], rss[8];
    __shared__ float s_mu, s_rsig;
    int wid = tid >> 5, lane = tid & 31;
    if (lane == 0) { rs[wid] = s; rss[wid] = ss; }
    __syncthreads();
    if (tid == 0) {
        float S = 0.f, SS = 0.f;
        #pragma unroll
        for (int i = 0; i < 8; i++) { S += rs[i]; SS += rss[i]; }
        float mu  = S * (1.0f / DD);
        float var = SS * (1.0f / DD) - mu * mu;
        s_mu = mu;
        s_rsig = rsqrtf(var + 1e-5f);
    }
    __syncthreads();
    float mu = s_mu, rsig = s_rsig;
    float4 gv = ((const float4*)gamma)[tid];
    float4 bv = ((const float4*)beta)[tid];
    float4 o;
    o.x = (v.x - mu) * rsig * gv.x + bv.x;
    o.y = (v.y - mu) * rsig * gv.y + bv.y;
    o.z = (v.z - mu) * rsig * gv.z + bv.z;
    o.w = (v.w - mu) * rsig * gv.w + bv.w;
    ((float4*)(out + (size_t)row * DD))[tid] = o;
    if (outHi) {
        size_t i = (size_t)row * DD + tid * 4;
        uint32_t h01, l01, h23, l23;
        split2(o.x, o.y, h01, l01);
        split2(o.z, o.w, h23, l23);
        *(uint32_t*)(outHi + i) = h01; *(uint32_t*)(outHi + i + 2) = h23;
        *(uint32_t*)(outLo + i) = l01; *(uint32_t*)(outLo + i + 2) = l23;
    }
}

// ---------------- mma.sync split-bf16 GEMM, fused hi|lo rows, BK=32 ----------------
// smem row (128B) = [hi 64B | lo 64B] for A and B. Each chunk stages all 4 arrays
// once and computes all 3 split terms: Ahi*Bhi + Alo*Bhi + Ahi*Blo.
#define GSMEM (64 * 1024)

template <int MODE>
__global__ __launch_bounds__(256, 2)
void gemm_mma(const __nv_bfloat16* __restrict__ Ahi, const __nv_bfloat16* __restrict__ Alo,
              const __nv_bfloat16* __restrict__ WHiB, const __nv_bfloat16* __restrict__ WLoB,
              const float* __restrict__ b0, const float* __restrict__ b1, const float* __restrict__ b2,
              float* __restrict__ C,
              __nv_bfloat16* __restrict__ h0, __nv_bfloat16* __restrict__ l0_,
              __nv_bfloat16* __restrict__ h1, __nv_bfloat16* __restrict__ l1_,
              __nv_bfloat16* __restrict__ h2, __nv_bfloat16* __restrict__ l2_) {
    extern __shared__ char dsm[];
    __shared__ float s_bias[128];

    int tid = threadIdx.x;
    int wid = tid >> 5;
    int lane = tid & 31;
    int warp_m = wid & 3;
    int warp_n = wid >> 2;
    int rowA0 = blockIdx.y * 128;
    int colB0 = blockIdx.x * 128;
    int z = blockIdx.z;

    // K/V rows fully inside the padding suffix are never consumed: skip the CTA.
    if (MODE == 1 && z >= 1) {
        if ((rowA0 & 2047) >= g_len[rowA0 >> 11]) return;
    }

    const __nv_bfloat16* Bhi = WHiB + (size_t)z * DD * DD;
    const __nv_bfloat16* Blo = WLoB + (size_t)z * DD * DD;
    const float* bias = (z == 0) ? b0 : (z == 1) ? b1 : b2;
    __nv_bfloat16* CHi = (z == 0) ? h0 : (z == 1) ? h1 : h2;
    __nv_bfloat16* CLo = (z == 0) ? l0_ : (z == 1) ? l1_ : l2_;

    uint32_t base = smem_u32(dsm);
    uint32_t aBase[2] = { base, base + 32768u };
    uint32_t bBase[2] = { base + 16384u, base + 49152u };

    if (tid < 128) s_bias[tid] = bias[colB0 + tid];

    int ldRow[4], ldOff[4], ldHiSel[4];
    uint32_t ldSw[4];
    #pragma unroll
    for (int it = 0; it < 4; it++) {
        int lin = it * 256 + tid;
        ldRow[it] = lin >> 3;
        int c8 = lin & 7;
        ldHiSel[it] = (c8 < 4);
        ldOff[it] = (c8 & 3) * 8;
        ldSw[it] = sw128((uint32_t)(ldRow[it] * 128 + c8 * 16));
    }

    auto issue = [&](int c, int s) {
        int k0 = c * 32;
        #pragma unroll
        for (int it = 0; it < 4; it++) {
            const __nv_bfloat16* a = (ldHiSel[it] ? Ahi : Alo) +
                (size_t)(rowA0 + ldRow[it]) * DD + k0 + ldOff[it];
            CP_ASYNC16(aBase[s] + ldSw[it], a);
            const __nv_bfloat16* bb = (ldHiSel[it] ? Bhi : Blo) +
                (size_t)(colB0 + ldRow[it]) * DD + k0 + ldOff[it];
            CP_ASYNC16(bBase[s] + ldSw[it], bb);
        }
        CP_COMMIT();
    };

    float acc[2][8][4];
    #pragma unroll
    for (int mt = 0; mt < 2; mt++)
        #pragma unroll
        for (int nt = 0; nt < 8; nt++)
            #pragma unroll
            for (int q = 0; q < 4; q++) acc[mt][nt][q] = 0.f;

    int aRow = warp_m * 32 + (lane & 15);
    int aChunkHalf = lane >> 4;
    int bRow = warp_n * 64 + (lane >> 4) * 8 + (lane & 7);
    int bChunkHalf = (lane >> 3) & 1;

    issue(0, 0);

    for (int i = 0; i < 32; i++) {
        int s = i & 1;
        if (i < 31) issue(i + 1, s ^ 1);
        if (i < 31) { CP_WAIT1(); } else { CP_WAIT0(); }
        __syncthreads();

        #pragma unroll
        for (int ks = 0; ks < 2; ks++) {
            uint32_t afh[2][4], afl[2][4];
            #pragma unroll
            for (int mt = 0; mt < 2; mt++) {
                uint32_t off = (uint32_t)((aRow + mt * 16) * 128 + (ks * 2 + aChunkHalf) * 16);
                ldsm_x4(afh[mt][0], afh[mt][1], afh[mt][2], afh[mt][3], aBase[s] + sw128(off));
                ldsm_x4(afl[mt][0], afl[mt][1], afl[mt][2], afl[mt][3], aBase[s] + sw128(off + 64u));
            }
            uint32_t bf[8][2];
            #pragma unroll
            for (int j2 = 0; j2 < 4; j2++) {
                uint32_t off = (uint32_t)((bRow + j2 * 16) * 128 + (ks * 2 + bChunkHalf) * 16);
                uint32_t r0, r1, r2, r3;
                ldsm_x4(r0, r1, r2, r3, bBase[s] + sw128(off));
                bf[j2 * 2][0] = r0; bf[j2 * 2][1] = r1;
                bf[j2 * 2 + 1][0] = r2; bf[j2 * 2 + 1][1] = r3;
            }
            #pragma unroll
            for (int mt = 0; mt < 2; mt++)
                #pragma unroll
                for (int nt = 0; nt < 8; nt++)
                    mma16816(acc[mt][nt], afh[mt], bf[nt]);
            #pragma unroll
            for (int mt = 0; mt < 2; mt++)
                #pragma unroll
                for (int nt = 0; nt < 8; nt++)
                    mma16816(acc[mt][nt], afl[mt], bf[nt]);
            #pragma unroll
            for (int j2 = 0; j2 < 4; j2++) {
                uint32_t off = (uint32_t)((bRow + j2 * 16) * 128 + (ks * 2 + bChunkHalf) * 16 + 64);
                uint32_t r0, r1, r2, r3;
                ldsm_x4(r0, r1, r2, r3, bBase[s] + sw128(off));
                bf[j2 * 2][0] = r0; bf[j2 * 2][1] = r1;
                bf[j2 * 2 + 1][0] = r2; bf[j2 * 2 + 1][1] = r3;
            }
            #pragma unroll
            for (int mt = 0; mt < 2; mt++)
                #pragma unroll
                for (int nt = 0; nt < 8; nt++)
                    mma16816(acc[mt][nt], afh[mt], bf[nt]);
        }
        __syncthreads();
    }

    int gid = lane >> 2, tig = lane & 3;
    #pragma unroll
    for (int mt = 0; mt < 2; mt++) {
        #pragma unroll
        for (int half = 0; half < 2; half++) {
            int m = rowA0 + warp_m * 32 + mt * 16 + gid + half * 8;
            #pragma unroll
            for (int nt = 0; nt < 8; nt++) {
                int col = colB0 + warp_n * 64 + nt * 8 + tig * 2;
                float vx = acc[mt][nt][half * 2 + 0] + s_bias[col - colB0];
                float vy = acc[mt][nt][half * 2 + 1] + s_bias[col - colB0 + 1];
                if (MODE == 0) {
                    float2 v; v.x = vx; v.y = vy;
                    *(float2*)(C + (size_t)m * DD + col) = v;
                } else {
                    int b = m >> 11, l = m & 2047;
                    int hh = col >> 6, hd = col & 63;
                    size_t idx = (((size_t)(b * HH + hh)) * LL + l) * HDIM + hd;
                    uint32_t hi2, lo2;
                    split2(vx, vy, hi2, lo2);
                    *(uint32_t*)(CHi + idx) = hi2;
                    *(uint32_t*)(CLo + idx) = lo2;
                }
            }
        }
    }
}

// ---------------- tensor-core flash attention (R12 champion + big-tiles-first) ----------------
#define ASMEM (64 * 1024)

__global__ __launch_bounds__(256, 2)
void attn_mma() {
    extern __shared__ char dsm[];
    __shared__ unsigned char s_mk[2][64];

    int tid = threadIdx.x;
    int wid = tid >> 5;
    int lane = tid & 31;
    int gid = lane >> 2, tig = lane & 3;
    int qt = gridDim.x - 1 - blockIdx.x;   // big tiles first: causal load balance
    int bh = blockIdx.y;
    int b = bh >> 4, h = bh & 15;
    int qbase = qt * 128;

    uint32_t base = smem_u32(dsm);
    // stage s: Khi @ s*32768, Klo +8192, Vhi +16384, Vlo +24576

    const __nv_bfloat16* qHi = g_qHi + ((size_t)bh * LL + qbase) * HDIM;
    const __nv_bfloat16* qLo = g_qLo + ((size_t)bh * LL + qbase) * HDIM;

    #pragma unroll
    for (int it = 0; it < 4; it++) {
        int c = it * 256 + tid;
        int row = c >> 3, col16 = c & 7;
        uint32_t sw = sw128((uint32_t)(row * 128 + col16 * 16));
        CP_ASYNC16(base + sw, qHi + row * HDIM + col16 * 8);
        CP_ASYNC16(base + 16384u + sw, qLo + row * HDIM + col16 * 8);
    }
    CP_COMMIT();
    CP_WAIT0();
    __syncthreads();

    uint32_t qh[4][4], ql[4][4];
    {
        int arow = wid * 16 + (lane & 15);
        int ahalf = lane >> 4;
        #pragma unroll
        for (int ks = 0; ks < 4; ks++) {
            uint32_t off = (uint32_t)(arow * 128 + (ks * 2 + ahalf) * 16);
            ldsm_x4(qh[ks][0], qh[ks][1], qh[ks][2], qh[ks][3], base + sw128(off));
            ldsm_x4(ql[ks][0], ql[ks][1], ql[ks][2], ql[ks][3], base + 16384u + sw128(off));
        }
    }
    __syncthreads();

    int len = g_len[b];
    int ntiles_c = 2 * qt + 2;
    int ntiles_v = (len + 63) >> 6;
    int ntiles = (ntiles_c < ntiles_v) ? ntiles_c : ntiles_v;

    auto issue = [&](int j, int s) {
        uint32_t st = base + (uint32_t)s * 32768u;
        size_t goff = ((size_t)bh * LL + j * 64) * HDIM;
        #pragma unroll
        for (int it = 0; it < 2; it++) {
            int c = it * 256 + tid;
            int row = c >> 3, col16 = c & 7;
            uint32_t sw = sw128((uint32_t)(row * 128 + col16 * 16));
            size_t so = goff + row * HDIM + col16 * 8;
            CP_ASYNC16(st + sw,          g_kHi + so);
            CP_ASYNC16(st + 8192u + sw,  g_kLo + so);
            CP_ASYNC16(st + 16384u + sw, g_vHi + so);
            CP_ASYNC16(st + 24576u + sw, g_vLo + so);
        }
        if (tid < 64) s_mk[s][tid] = g_mask[b * LL + j * 64 + tid];
        CP_COMMIT();
    };

    float o[8][4];
    #pragma unroll
    for (int nt = 0; nt < 8; nt++)
        #pragma unroll
        for (int q = 0; q < 4; q++) o[nt][q] = 0.f;
    float m0 = -1e30f, m1 = -1e30f, l0 = 0.f, l1 = 0.f;

    const float cs = 0.125f * 1.4426950408889634f;  // 1/sqrt(HD) * log2(e)
    int qg0 = qbase + wid * 16 + gid;
    int qg1 = qg0 + 8;

    issue(0, 0);
    int issued = 1;
    if (ntiles > 1) { issue(1, 1); issued = 2; }

    int kRow = (lane >> 4) * 8 + (lane & 7);
    int kHalf = (lane >> 3) & 1;
    int vRowL = lane & 15;
    int vHalf = lane >> 4;

    for (int j = 0; j < ntiles; j++) {
        int s = j & 1;
        if (issued > j + 1) { CP_WAIT1(); } else { CP_WAIT0(); }
        __syncthreads();

        uint32_t stK = base + (uint32_t)s * 32768u;
        uint32_t stV = stK + 16384u;

        float sa[8][4];
        #pragma unroll
        for (int nt = 0; nt < 8; nt++)
            #pragma unroll
            for (int q = 0; q < 4; q++) sa[nt][q] = 0.f;

        #pragma unroll
        for (int ks = 0; ks < 4; ks++) {
            uint32_t kf[8][2];
            #pragma unroll
            for (int j2 = 0; j2 < 4; j2++) {
                uint32_t off = (uint32_t)((kRow + j2 * 16) * 128 + (ks * 2 + kHalf) * 16);
                uint32_t r0, r1, r2, r3;
                ldsm_x4(r0, r1, r2, r3, stK + sw128(off));
                kf[j2 * 2][0] = r0; kf[j2 * 2][1] = r1;
                kf[j2 * 2 + 1][0] = r2; kf[j2 * 2 + 1][1] = r3;
            }
            #pragma unroll
            for (int nt = 0; nt < 8; nt++) {
                mma16816(sa[nt], qh[ks], kf[nt]);
                mma16816(sa[nt], ql[ks], kf[nt]);
            }
            #pragma unroll
            for (int j2 = 0; j2 < 4; j2++) {
                uint32_t off = (uint32_t)((kRow + j2 * 16) * 128 + (ks * 2 + kHalf) * 16);
                uint32_t r0, r1, r2, r3;
                ldsm_x4(r0, r1, r2, r3, stK + 8192u + sw128(off));
                kf[j2 * 2][0] = r0; kf[j2 * 2][1] = r1;
                kf[j2 * 2 + 1][0] = r2; kf[j2 * 2 + 1][1] = r3;
            }
            #pragma unroll
            for (int nt = 0; nt < 8; nt++)
                mma16816(sa[nt], qh[ks], kf[nt]);
        }

        int jbase = j * 64;
        #pragma unroll
        for (int nt = 0; nt < 8; nt++) {
            int cl = nt * 8 + tig * 2;
            int kg = jbase + cl;
            int msk0 = s_mk[s][cl];
            int msk1 = s_mk[s][cl + 1];
            float v0 = sa[nt][0] * cs, v1 = sa[nt][1] * cs;
            float v2 = sa[nt][2] * cs, v3 = sa[nt][3] * cs;
            if (kg > qg0 || msk0)     v0 = -1e30f;
            if (kg + 1 > qg0 || msk1) v1 = -1e30f;
            if (kg > qg1 || msk0)     v2 = -1e30f;
            if (kg + 1 > qg1 || msk1) v3 = -1e30f;
            sa[nt][0] = v0; sa[nt][1] = v1; sa[nt][2] = v2; sa[nt][3] = v3;
        }

        float rmax0 = -1e30f, rmax1 = -1e30f;
        #pragma unroll
        for (int nt = 0; nt < 8; nt++) {
            rmax0 = fmaxf(rmax0, fmaxf(sa[nt][0], sa[nt][1]));
            rmax1 = fmaxf(rmax1, fmaxf(sa[nt][2], sa[nt][3]));
        }
        rmax0 = fmaxf(rmax0, __shfl_xor_sync(0xffffffffu, rmax0, 1));
        rmax0 = fmaxf(rmax0, __shfl_xor_sync(0xffffffffu, rmax0, 2));
        rmax1 = fmaxf(rmax1, __shfl_xor_sync(0xffffffffu, rmax1, 1));
        rmax1 = fmaxf(rmax1, __shfl_xor_sync(0xffffffffu, rmax1, 2));
        float mn0 = fmaxf(m0, rmax0), mn1 = fmaxf(m1, rmax1);
        float f0 = ex2(m0 - mn0), f1 = ex2(m1 - mn1);
        float ps0 = 0.f, ps1 = 0.f;
        #pragma unroll
        for (int nt = 0; nt < 8; nt++) {
            float p0 = ex2(sa[nt][0] - mn0);
            float p1 = ex2(sa[nt][1] - mn0);
            float p2 = ex2(sa[nt][2] - mn1);
            float p3 = ex2(sa[nt][3] - mn1);
            ps0 += p0 + p1; ps1 += p2 + p3;
            sa[nt][0] = p0; sa[nt][1] = p1; sa[nt][2] = p2; sa[nt][3] = p3;
        }
        ps0 += __shfl_xor_sync(0xffffffffu, ps0, 1);
        ps0 += __shfl_xor_sync(0xffffffffu, ps0, 2);
        ps1 += __shfl_xor_sync(0xffffffffu, ps1, 1);
        ps1 += __shfl_xor_sync(0xffffffffu, ps1, 2);
        l0 = l0 * f0 + ps0; m0 = mn0;
        l1 = l1 * f1 + ps1; m1 = mn1;
        #pragma unroll
        for (int nt = 0; nt < 8; nt++) {
            o[nt][0] *= f0; o[nt][1] *= f0;
            o[nt][2] *= f1; o[nt][3] *= f1;
        }

        uint32_t phi[4][4], plo[4][4];
        #pragma unroll
        for (int ks = 0; ks < 4; ks++) {
            split2(sa[2 * ks][0],     sa[2 * ks][1],     phi[ks][0], plo[ks][0]);
            split2(sa[2 * ks][2],     sa[2 * ks][3],     phi[ks][1], plo[ks][1]);
            split2(sa[2 * ks + 1][0], sa[2 * ks + 1][1], phi[ks][2], plo[ks][2]);
            split2(sa[2 * ks + 1][2], sa[2 * ks + 1][3], phi[ks][3], plo[ks][3]);
        }

        #pragma unroll
        for (int ks = 0; ks < 4; ks++) {
            int vrow = ks * 16 + vRowL;
            uint32_t vf[8][2];
            #pragma unroll
            for (int g = 0; g < 4; g++) {
                uint32_t off = (uint32_t)(vrow * 128 + g * 32 + vHalf * 16);
                uint32_t r0, r1, r2, r3;
                ldsm_x4t(r0, r1, r2, r3, stV + sw128(off));
                vf[g * 2][0] = r0; vf[g * 2][1] = r1;
                vf[g * 2 + 1][0] = r2; vf[g * 2 + 1][1] = r3;
            }
            #pragma unroll
            for (int nt = 0; nt < 8; nt++) {
                mma16816(o[nt], phi[ks], vf[nt]);
                mma16816(o[nt], plo[ks], vf[nt]);
            }
            #pragma unroll
            for (int g = 0; g < 4; g++) {
                uint32_t off = (uint32_t)(vrow * 128 + g * 32 + vHalf * 16);
                uint32_t r0, r1, r2, r3;
                ldsm_x4t(r0, r1, r2, r3, stV + 8192u + sw128(off));
                vf[g * 2][0] = r0; vf[g * 2][1] = r1;
                vf[g * 2 + 1][0] = r2; vf[g * 2 + 1][1] = r3;
            }
            #pragma unroll
            for (int nt = 0; nt < 8; nt++)
                mma16816(o[nt], phi[ks], vf[nt]);
        }

        __syncthreads();
        if (j + 2 < ntiles) { issue(j + 2, s); issued++; }
    }

    float inv0 = 1.0f / l0, inv1 = 1.0f / l1;
    #pragma unroll
    for (int nt = 0; nt < 8; nt++) {
        int d = nt * 8 + tig * 2;
        int col = h * HDIM + d;
        size_t i0 = ((size_t)b * LL + qg0) * DD + col;
        size_t i1 = ((size_t)b * LL + qg1) * DD + col;
        uint32_t hi2, lo2;
        split2(o[nt][0] * inv0, o[nt][1] * inv0, hi2, lo2);
        *(uint32_t*)(g_aHi + i0) = hi2;
        *(uint32_t*)(g_aLo + i0) = lo2;
        split2(o[nt][2] * inv1, o[nt][3] * inv1, hi2, lo2);
        *(uint32_t*)(g_aHi + i1) = hi2;
        *(uint32_t*)(g_aLo + i1) = lo2;
    }
}

// ---------------- launch ----------------
extern "C" void kernel_launch(void* const* d_in, const int* in_sizes, int n_in,
                              void* d_out, int out_size) {
    const float* x  = (const float*)d_in[0];
    const unsigned char* pm = (const unsigned char*)d_in[1];
    const float* Wq = (const float*)d_in[3];
    const float* bq = (const float*)d_in[4];
    const float* Wk = (const float*)d_in[5];
    const float* bk = (const float*)d_in[6];
    const float* Wv = (const float*)d_in[7];
    const float* bv = (const float*)d_in[8];
    const float* Wo = (const float*)d_in[9];
    const float* bo = (const float*)d_in[10];
    const float* g_pre = (const float*)d_in[11];
    const float* b_pre = (const float*)d_in[12];
    const float* g_ln  = (const float*)d_in[13];
    const float* b_ln  = (const float*)d_in[14];
    float* out = (float*)d_out;

    float *ph, *py;
    __nv_bfloat16 *phHi, *phLo, *paHi, *paLo, *pwHi, *pwLo;
    __nv_bfloat16 *pqHi, *pqLo, *pkHi, *pkLo, *pvHi, *pvLo;
    cudaGetSymbolAddress((void**)&ph,   g_h);
    cudaGetSymbolAddress((void**)&py,   g_y);
    cudaGetSymbolAddress((void**)&phHi, g_hHi);
    cudaGetSymbolAddress((void**)&phLo, g_hLo);
    cudaGetSymbolAddress((void**)&paHi, g_aHi);
    cudaGetSymbolAddress((void**)&paLo, g_aLo);
    cudaGetSymbolAddress((void**)&pwHi, g_wHi);
    cudaGetSymbolAddress((void**)&pwLo, g_wLo);
    cudaGetSymbolAddress((void**)&pqHi, g_qHi);
    cudaGetSymbolAddress((void**)&pqLo, g_qLo);
    cudaGetSymbolAddress((void**)&pkHi, g_kHi);
    cudaGetSymbolAddress((void**)&pkLo, g_kLo);
    cudaGetSymbolAddress((void**)&pvHi, g_vHi);
    cudaGetSymbolAddress((void**)&pvLo, g_vLo);

    cudaFuncSetAttribute(gemm_mma<0>, cudaFuncAttributeMaxDynamicSharedMemorySize, GSMEM);
    cudaFuncSetAttribute(gemm_mma<1>, cudaFuncAttributeMaxDynamicSharedMemorySize, GSMEM);
    cudaFuncSetAttribute(attn_mma, cudaFuncAttributeMaxDynamicSharedMemorySize, ASMEM);

    convert_mask_kernel<<<1, 256>>>(pm);

    // pre-LN with fused hi/lo split
    ln_kernel<<<NROWS, 256>>>(x, (const float*)nullptr, g_pre, b_pre, ph, phHi, phLo);

    // weight splits, single launch: y = {Wq, Wk, Wv, Wo}
    const int nW = DD * DD;
    split_w_kernel<<<dim3(nW / 1024, 4), 256>>>(Wq, Wk, Wv, Wo, pwHi, pwLo);

    // QKV projections -> bf16 hi/lo (B,H,L,HD), single launch over z = {q,k,v}
    dim3 gqkv(DD / 128, NROWS / 128, 3);
    gemm_mma<1><<<gqkv, 256, GSMEM>>>(phHi, phLo, pwHi, pwLo,
                                      bq, bk, bv, nullptr,
                                      pqHi, pqLo, pkHi, pkLo, pvHi, pvLo);

    // tensor-core flash attention (writes aHi/aLo directly)
    attn_mma<<<dim3(LL / 128, BB * HH), 256, ASMEM>>>();

    // output projection (z=0 selects Wo slice at offset 3)
    dim3 gproj(DD / 128, NROWS / 128, 1);
    gemm_mma<0><<<gproj, 256, GSMEM>>>(paHi, paLo, pwHi + 3 * (size_t)nW, pwLo + 3 * (size_t)nW,
                                       bo, bo, bo, py,
                                       nullptr, nullptr, nullptr, nullptr, nullptr, nullptr);

    // residual + final LN
    ln_kernel<<<NROWS, 256>>>(py, ph, g_ln, b_ln, out, nullptr, nullptr);
}

// round 17
// speedup vs baseline: 1.7222x; 1.0307x over previous
#include <cuda_runtime.h>
#include <cuda_bf16.h>
#include <math.h>
#include <stdint.h>

#define BB 4
#define LL 2048
#define DD 1024
#define HH 16
#define HDIM 64
#define NROWS (BB * LL)   // 8192

// ---------------- scratch ----------------
__device__ float g_y[NROWS * DD];     // O-proj out
__device__ unsigned char g_mask[NROWS];
__device__ int g_len[BB];             // valid length per batch
__device__ __nv_bfloat16 g_hHi[NROWS * DD];   // LN(x) hi/lo (also residual source)
__device__ __nv_bfloat16 g_hLo[NROWS * DD];
__device__ __nv_bfloat16 g_aHi[NROWS * DD];   // attention out hi/lo (B,L,D)
__device__ __nv_bfloat16 g_aLo[NROWS * DD];
__device__ __nv_bfloat16 g_wHi[4][DD * DD];
__device__ __nv_bfloat16 g_wLo[4][DD * DD];
__device__ __nv_bfloat16 g_qHi[NROWS * DD];   // (B,H,L,HD)
__device__ __nv_bfloat16 g_qLo[NROWS * DD];
__device__ __nv_bfloat16 g_kHi[NROWS * DD];
__device__ __nv_bfloat16 g_kLo[NROWS * DD];
__device__ __nv_bfloat16 g_vHi[NROWS * DD];
__device__ __nv_bfloat16 g_vLo[NROWS * DD];

// ---------------- helpers ----------------
__device__ __forceinline__ uint32_t smem_u32(const void* p) {
    uint32_t a;
    asm("{ .reg .u64 t; cvta.to.shared.u64 t, %1; cvt.u32.u64 %0, t; }" : "=r"(a) : "l"(p));
    return a;
}
__device__ __forceinline__ void ldsm_x4(uint32_t& d0, uint32_t& d1, uint32_t& d2, uint32_t& d3,
                                        uint32_t addr) {
    asm volatile("ldmatrix.sync.aligned.m8n8.x4.shared.b16 {%0,%1,%2,%3}, [%4];"
                 : "=r"(d0), "=r"(d1), "=r"(d2), "=r"(d3) : "r"(addr));
}
__device__ __forceinline__ void ldsm_x4t(uint32_t& d0, uint32_t& d1, uint32_t& d2, uint32_t& d3,
                                         uint32_t addr) {
    asm volatile("ldmatrix.sync.aligned.m8n8.x4.trans.shared.b16 {%0,%1,%2,%3}, [%4];"
                 : "=r"(d0), "=r"(d1), "=r"(d2), "=r"(d3) : "r"(addr));
}
__device__ __forceinline__ void mma16816(float* c, const uint32_t* a, const uint32_t* b) {
    asm volatile(
        "mma.sync.aligned.m16n8k16.row.col.f32.bf16.bf16.f32 "
        "{%0,%1,%2,%3}, {%4,%5,%6,%7}, {%8,%9}, {%0,%1,%2,%3};"
        : "+f"(c[0]), "+f"(c[1]), "+f"(c[2]), "+f"(c[3])
        : "r"(a[0]), "r"(a[1]), "r"(a[2]), "r"(a[3]), "r"(b[0]), "r"(b[1]));
}
__device__ __forceinline__ float ex2(float x) {
    float y;
    asm("ex2.approx.ftz.f32 %0, %1;" : "=f"(y) : "f"(x));
    return y;
}
#define CP_ASYNC16(dst, src) \
    asm volatile("cp.async.cg.shared.global [%0], [%1], 16;" :: "r"(dst), "l"(src))
#define CP_COMMIT() asm volatile("cp.async.commit_group;")
#define CP_WAIT1()  asm volatile("cp.async.wait_group 1;")
#define CP_WAIT0()  asm volatile("cp.async.wait_group 0;")

__device__ __forceinline__ uint32_t sw128(uint32_t off) {
    return off ^ ((off >> 3) & 0x70u);
}
__device__ __forceinline__ void split2(float a, float b, uint32_t& hi, uint32_t& lo) {
    __nv_bfloat16 ha = __float2bfloat16_rn(a), hb = __float2bfloat16_rn(b);
    float ra = a - __bfloat162float(ha), rb = b - __bfloat162float(hb);
    __nv_bfloat162 h2; h2.x = ha; h2.y = hb;
    __nv_bfloat162 l2; l2.x = __float2bfloat16_rn(ra); l2.y = __float2bfloat16_rn(rb);
    hi = *(uint32_t*)&h2;
    lo = *(uint32_t*)&l2;
}

// ---------------- padding-mask canonicalization + per-batch length ----------------
__global__ void convert_mask_kernel(const unsigned char* __restrict__ pm) {
    __shared__ int fz0, fz3;
    int tid = threadIdx.x;
    if (tid == 0) { fz0 = 0; fz3 = 0; }
    if (tid < BB) g_len[tid] = 0;
    __syncthreads();
    int z0 = 0, z3 = 0;
    for (int j = tid; j < NROWS; j += blockDim.x) {
        unsigned char v = pm[j];
        if (v) {
            if ((j & 3) == 0) z0 = 1;
            if ((j & 3) == 3) z3 = 1;
        }
    }
    if (z0) atomicOr(&fz0, 1);
    if (z3) atomicOr(&fz3, 1);
    __syncthreads();
    int mode;
    if (!fz3) mode = fz0 ? 3 : 0;
    else      mode = fz0 ? 1 : 2;
    int cnt[BB];
    #pragma unroll
    for (int b = 0; b < BB; b++) cnt[b] = 0;
    for (int i = tid; i < NROWS; i += blockDim.x) {
        unsigned char r;
        if (mode == 0)      r = 0;
        else if (mode == 1) r = (pm[i] != 0);
        else if (mode == 2) r = (((const float*)pm)[i] != 0.0f);
        else                r = (((const int*)pm)[i] != 0);
        g_mask[i] = r;
        if (!r) cnt[i >> 11]++;
    }
    #pragma unroll
    for (int b = 0; b < BB; b++)
        if (cnt[b]) atomicAdd(&g_len[b], cnt[b]);
}

// ---------------- fp32 -> bf16 hi/lo split, 4 weights in one launch ----------------
__global__ void split_w_kernel(const float* __restrict__ s0, const float* __restrict__ s1,
                               const float* __restrict__ s2, const float* __restrict__ s3,
                               __nv_bfloat16* __restrict__ hiB,
                               __nv_bfloat16* __restrict__ loB) {
    int w = blockIdx.y;
    const float* src = (w == 0) ? s0 : (w == 1) ? s1 : (w == 2) ? s2 : s3;
    size_t off = (size_t)w * DD * DD;
    int i = (blockIdx.x * blockDim.x + threadIdx.x) * 4;
    float4 v = *(const float4*)(src + i);
    uint32_t h01, l01, h23, l23;
    split2(v.x, v.y, h01, l01);
    split2(v.z, v.w, h23, l23);
    *(uint32_t*)(hiB + off + i) = h01; *(uint32_t*)(hiB + off + i + 2) = h23;
    *(uint32_t*)(loB + off + i) = l01; *(uint32_t*)(loB + off + i + 2) = l23;
}

// ---------------- LayerNorm ----------------
// res fp32 OR resHi/resLo bf16 pair (reconstructed); out fp32 optional; outHi/outLo optional.
__global__ void ln_kernel(const float* __restrict__ x,
                          const __nv_bfloat16* __restrict__ resHi,
                          const __nv_bfloat16* __restrict__ resLo,
                          const float* __restrict__ gamma, const float* __restrict__ beta,
                          float* __restrict__ out,
                          __nv_bfloat16* __restrict__ outHi,
                          __nv_bfloat16* __restrict__ outLo) {
    int row = blockIdx.x;
    int tid = threadIdx.x;
    const float4* xr = (const float4*)(x + (size_t)row * DD);
    float4 v = xr[tid];
    if (resHi) {
        size_t i = (size_t)row * DD + tid * 4;
        uint32_t h01 = *(const uint32_t*)(resHi + i), h23 = *(const uint32_t*)(resHi + i + 2);
        uint32_t l01 = *(const uint32_t*)(resLo + i), l23 = *(const uint32_t*)(resLo + i + 2);
        __nv_bfloat162 H01 = *(__nv_bfloat162*)&h01, H23 = *(__nv_bfloat162*)&h23;
        __nv_bfloat162 L01 = *(__nv_bfloat162*)&l01, L23 = *(__nv_bfloat162*)&l23;
        v.x += __bfloat162float(H01.x) + __bfloat162float(L01.x);
        v.y += __bfloat162float(H01.y) + __bfloat162float(L01.y);
        v.z += __bfloat162float(H23.x) + __bfloat162float(L23.x);
        v.w += __bfloat162float(H23.y) + __bfloat162float(L23.y);
    }
    float s  = v.x + v.y + v.z + v.w;
    float ss = v.x * v.x + v.y * v.y + v.z * v.z + v.w * v.w;
    for (int off = 16; off > 0; off >>= 1) {
        s  += __shfl_down_sync(0xffffffffu, s, off);
        ss += __shfl_down_sync(0xffffffffu, ss, off);
    }
    __shared__ float rs[8], rss[8];
    __shared__ float s_mu, s_rsig;
    int wid = tid >> 5, lane = tid & 31;
    if (lane == 0) { rs[wid] = s; rss[wid] = ss; }
    __syncthreads();
    if (tid == 0) {
        float S = 0.f, SS = 0.f;
        #pragma unroll
        for (int i = 0; i < 8; i++) { S += rs[i]; SS += rss[i]; }
        float mu  = S * (1.0f / DD);
        float var = SS * (1.0f / DD) - mu * mu;
        s_mu = mu;
        s_rsig = rsqrtf(var + 1e-5f);
    }
    __syncthreads();
    float mu = s_mu, rsig = s_rsig;
    float4 gv = ((const float4*)gamma)[tid];
    float4 bv = ((const float4*)beta)[tid];
    float4 o;
    o.x = (v.x - mu) * rsig * gv.x + bv.x;
    o.y = (v.y - mu) * rsig * gv.y + bv.y;
    o.z = (v.z - mu) * rsig * gv.z + bv.z;
    o.w = (v.w - mu) * rsig * gv.w + bv.w;
    if (out) ((float4*)(out + (size_t)row * DD))[tid] = o;
    if (outHi) {
        size_t i = (size_t)row * DD + tid * 4;
        uint32_t h01, l01, h23, l23;
        split2(o.x, o.y, h01, l01);
        split2(o.z, o.w, h23, l23);
        *(uint32_t*)(outHi + i) = h01; *(uint32_t*)(outHi + i + 2) = h23;
        *(uint32_t*)(outLo + i) = l01; *(uint32_t*)(outLo + i + 2) = l23;
    }
}

// ---------------- mma.sync split-bf16 GEMM, fused hi|lo rows, BK=32 ----------------
#define GSMEM (64 * 1024)

template <int MODE>
__global__ __launch_bounds__(256, 2)
void gemm_mma(const __nv_bfloat16* __restrict__ Ahi, const __nv_bfloat16* __restrict__ Alo,
              const __nv_bfloat16* __restrict__ WHiB, const __nv_bfloat16* __restrict__ WLoB,
              const float* __restrict__ b0, const float* __restrict__ b1, const float* __restrict__ b2,
              float* __restrict__ C,
              __nv_bfloat16* __restrict__ h0, __nv_bfloat16* __restrict__ l0_,
              __nv_bfloat16* __restrict__ h1, __nv_bfloat16* __restrict__ l1_,
              __nv_bfloat16* __restrict__ h2, __nv_bfloat16* __restrict__ l2_) {
    extern __shared__ char dsm[];
    __shared__ float s_bias[128];

    int tid = threadIdx.x;
    int wid = tid >> 5;
    int lane = tid & 31;
    int warp_m = wid & 3;
    int warp_n = wid >> 2;
    int rowA0 = blockIdx.y * 128;
    int colB0 = blockIdx.x * 128;
    int z = blockIdx.z;

    if (MODE == 1 && z >= 1) {
        if ((rowA0 & 2047) >= g_len[rowA0 >> 11]) return;
    }

    const __nv_bfloat16* Bhi = WHiB + (size_t)z * DD * DD;
    const __nv_bfloat16* Blo = WLoB + (size_t)z * DD * DD;
    const float* bias = (z == 0) ? b0 : (z == 1) ? b1 : b2;
    __nv_bfloat16* CHi = (z == 0) ? h0 : (z == 1) ? h1 : h2;
    __nv_bfloat16* CLo = (z == 0) ? l0_ : (z == 1) ? l1_ : l2_;

    uint32_t base = smem_u32(dsm);
    uint32_t aBase[2] = { base, base + 32768u };
    uint32_t bBase[2] = { base + 16384u, base + 49152u };

    if (tid < 128) s_bias[tid] = bias[colB0 + tid];

    int ldRow[4], ldOff[4], ldHiSel[4];
    uint32_t ldSw[4];
    #pragma unroll
    for (int it = 0; it < 4; it++) {
        int lin = it * 256 + tid;
        ldRow[it] = lin >> 3;
        int c8 = lin & 7;
        ldHiSel[it] = (c8 < 4);
        ldOff[it] = (c8 & 3) * 8;
        ldSw[it] = sw128((uint32_t)(ldRow[it] * 128 + c8 * 16));
    }

    auto issue = [&](int c, int s) {
        int k0 = c * 32;
        #pragma unroll
        for (int it = 0; it < 4; it++) {
            const __nv_bfloat16* a = (ldHiSel[it] ? Ahi : Alo) +
                (size_t)(rowA0 + ldRow[it]) * DD + k0 + ldOff[it];
            CP_ASYNC16(aBase[s] + ldSw[it], a);
            const __nv_bfloat16* bb = (ldHiSel[it] ? Bhi : Blo) +
                (size_t)(colB0 + ldRow[it]) * DD + k0 + ldOff[it];
            CP_ASYNC16(bBase[s] + ldSw[it], bb);
        }
        CP_COMMIT();
    };

    float acc[2][8][4];
    #pragma unroll
    for (int mt = 0; mt < 2; mt++)
        #pragma unroll
        for (int nt = 0; nt < 8; nt++)
            #pragma unroll
            for (int q = 0; q < 4; q++) acc[mt][nt][q] = 0.f;

    int aRow = warp_m * 32 + (lane & 15);
    int aChunkHalf = lane >> 4;
    int bRow = warp_n * 64 + (lane >> 4) * 8 + (lane & 7);
    int bChunkHalf = (lane >> 3) & 1;

    issue(0, 0);

    for (int i = 0; i < 32; i++) {
        int s = i & 1;
        if (i < 31) issue(i + 1, s ^ 1);
        if (i < 31) { CP_WAIT1(); } else { CP_WAIT0(); }
        __syncthreads();

        #pragma unroll
        for (int ks = 0; ks < 2; ks++) {
            uint32_t afh[2][4], afl[2][4];
            #pragma unroll
            for (int mt = 0; mt < 2; mt++) {
                uint32_t off = (uint32_t)((aRow + mt * 16) * 128 + (ks * 2 + aChunkHalf) * 16);
                ldsm_x4(afh[mt][0], afh[mt][1], afh[mt][2], afh[mt][3], aBase[s] + sw128(off));
                ldsm_x4(afl[mt][0], afl[mt][1], afl[mt][2], afl[mt][3], aBase[s] + sw128(off + 64u));
            }
            uint32_t bf[8][2];
            #pragma unroll
            for (int j2 = 0; j2 < 4; j2++) {
                uint32_t off = (uint32_t)((bRow + j2 * 16) * 128 + (ks * 2 + bChunkHalf) * 16);
                uint32_t r0, r1, r2, r3;
                ldsm_x4(r0, r1, r2, r3, bBase[s] + sw128(off));
                bf[j2 * 2][0] = r0; bf[j2 * 2][1] = r1;
                bf[j2 * 2 + 1][0] = r2; bf[j2 * 2 + 1][1] = r3;
            }
            #pragma unroll
            for (int mt = 0; mt < 2; mt++)
                #pragma unroll
                for (int nt = 0; nt < 8; nt++)
                    mma16816(acc[mt][nt], afh[mt], bf[nt]);
            #pragma unroll
            for (int mt = 0; mt < 2; mt++)
                #pragma unroll
                for (int nt = 0; nt < 8; nt++)
                    mma16816(acc[mt][nt], afl[mt], bf[nt]);
            #pragma unroll
            for (int j2 = 0; j2 < 4; j2++) {
                uint32_t off = (uint32_t)((bRow + j2 * 16) * 128 + (ks * 2 + bChunkHalf) * 16 + 64);
                uint32_t r0, r1, r2, r3;
                ldsm_x4(r0, r1, r2, r3, bBase[s] + sw128(off));
                bf[j2 * 2][0] = r0; bf[j2 * 2][1] = r1;
                bf[j2 * 2 + 1][0] = r2; bf[j2 * 2 + 1][1] = r3;
            }
            #pragma unroll
            for (int mt = 0; mt < 2; mt++)
                #pragma unroll
                for (int nt = 0; nt < 8; nt++)
                    mma16816(acc[mt][nt], afh[mt], bf[nt]);
        }
        __syncthreads();
    }

    int gid = lane >> 2, tig = lane & 3;
    #pragma unroll
    for (int mt = 0; mt < 2; mt++) {
        #pragma unroll
        for (int half = 0; half < 2; half++) {
            int m = rowA0 + warp_m * 32 + mt * 16 + gid + half * 8;
            #pragma unroll
            for (int nt = 0; nt < 8; nt++) {
                int col = colB0 + warp_n * 64 + nt * 8 + tig * 2;
                float vx = acc[mt][nt][half * 2 + 0] + s_bias[col - colB0];
                float vy = acc[mt][nt][half * 2 + 1] + s_bias[col - colB0 + 1];
                if (MODE == 0) {
                    float2 v; v.x = vx; v.y = vy;
                    *(float2*)(C + (size_t)m * DD + col) = v;
                } else {
                    int b = m >> 11, l = m & 2047;
                    int hh = col >> 6, hd = col & 63;
                    size_t idx = (((size_t)(b * HH + hh)) * LL + l) * HDIM + hd;
                    uint32_t hi2, lo2;
                    split2(vx, vy, hi2, lo2);
                    *(uint32_t*)(CHi + idx) = hi2;
                    *(uint32_t*)(CLo + idx) = lo2;
                }
            }
        }
    }
}

// ---------------- tensor-core flash attention (+ interior-tile fast path) ----------------
#define ASMEM (64 * 1024)

__global__ __launch_bounds__(256, 2)
void attn_mma() {
    extern __shared__ char dsm[];
    __shared__ unsigned char s_mk[2][64];

    int tid = threadIdx.x;
    int wid = tid >> 5;
    int lane = tid & 31;
    int gid = lane >> 2, tig = lane & 3;
    int qt = gridDim.x - 1 - blockIdx.x;
    int bh = blockIdx.y;
    int b = bh >> 4, h = bh & 15;
    int qbase = qt * 128;

    uint32_t base = smem_u32(dsm);

    const __nv_bfloat16* qHi = g_qHi + ((size_t)bh * LL + qbase) * HDIM;
    const __nv_bfloat16* qLo = g_qLo + ((size_t)bh * LL + qbase) * HDIM;

    #pragma unroll
    for (int it = 0; it < 4; it++) {
        int c = it * 256 + tid;
        int row = c >> 3, col16 = c & 7;
        uint32_t sw = sw128((uint32_t)(row * 128 + col16 * 16));
        CP_ASYNC16(base + sw, qHi + row * HDIM + col16 * 8);
        CP_ASYNC16(base + 16384u + sw, qLo + row * HDIM + col16 * 8);
    }
    CP_COMMIT();
    CP_WAIT0();
    __syncthreads();

    uint32_t qh[4][4], ql[4][4];
    {
        int arow = wid * 16 + (lane & 15);
        int ahalf = lane >> 4;
        #pragma unroll
        for (int ks = 0; ks < 4; ks++) {
            uint32_t off = (uint32_t)(arow * 128 + (ks * 2 + ahalf) * 16);
            ldsm_x4(qh[ks][0], qh[ks][1], qh[ks][2], qh[ks][3], base + sw128(off));
            ldsm_x4(ql[ks][0], ql[ks][1], ql[ks][2], ql[ks][3], base + 16384u + sw128(off));
        }
    }
    __syncthreads();

    int len = g_len[b];
    int ntiles_c = 2 * qt + 2;
    int ntiles_v = (len + 63) >> 6;
    int ntiles = (ntiles_c < ntiles_v) ? ntiles_c : ntiles_v;

    auto issue = [&](int j, int s) {
        uint32_t st = base + (uint32_t)s * 32768u;
        size_t goff = ((size_t)bh * LL + j * 64) * HDIM;
        #pragma unroll
        for (int it = 0; it < 2; it++) {
            int c = it * 256 + tid;
            int row = c >> 3, col16 = c & 7;
            uint32_t sw = sw128((uint32_t)(row * 128 + col16 * 16));
            size_t so = goff + row * HDIM + col16 * 8;
            CP_ASYNC16(st + sw,          g_kHi + so);
            CP_ASYNC16(st + 8192u + sw,  g_kLo + so);
            CP_ASYNC16(st + 16384u + sw, g_vHi + so);
            CP_ASYNC16(st + 24576u + sw, g_vLo + so);
        }
        if (tid < 64) s_mk[s][tid] = g_mask[b * LL + j * 64 + tid];
        CP_COMMIT();
    };

    float o[8][4];
    #pragma unroll
    for (int nt = 0; nt < 8; nt++)
        #pragma unroll
        for (int q = 0; q < 4; q++) o[nt][q] = 0.f;
    float m0 = -1e30f, m1 = -1e30f, l0 = 0.f, l1 = 0.f;

    const float cs = 0.125f * 1.4426950408889634f;
    int qg0 = qbase + wid * 16 + gid;
    int qg1 = qg0 + 8;

    issue(0, 0);
    int issued = 1;
    if (ntiles > 1) { issue(1, 1); issued = 2; }

    int kRow = (lane >> 4) * 8 + (lane & 7);
    int kHalf = (lane >> 3) & 1;
    int vRowL = lane & 15;
    int vHalf = lane >> 4;

    for (int j = 0; j < ntiles; j++) {
        int s = j & 1;
        if (issued > j + 1) { CP_WAIT1(); } else { CP_WAIT0(); }
        __syncthreads();

        uint32_t stK = base + (uint32_t)s * 32768u;
        uint32_t stV = stK + 16384u;

        float sa[8][4];
        #pragma unroll
        for (int nt = 0; nt < 8; nt++)
            #pragma unroll
            for (int q = 0; q < 4; q++) sa[nt][q] = 0.f;

        #pragma unroll
        for (int ks = 0; ks < 4; ks++) {
            uint32_t kf[8][2];
            #pragma unroll
            for (int j2 = 0; j2 < 4; j2++) {
                uint32_t off = (uint32_t)((kRow + j2 * 16) * 128 + (ks * 2 + kHalf) * 16);
                uint32_t r0, r1, r2, r3;
                ldsm_x4(r0, r1, r2, r3, stK + sw128(off));
                kf[j2 * 2][0] = r0; kf[j2 * 2][1] = r1;
                kf[j2 * 2 + 1][0] = r2; kf[j2 * 2 + 1][1] = r3;
            }
            #pragma unroll
            for (int nt = 0; nt < 8; nt++) {
                mma16816(sa[nt], qh[ks], kf[nt]);
                mma16816(sa[nt], ql[ks], kf[nt]);
            }
            #pragma unroll
            for (int j2 = 0; j2 < 4; j2++) {
                uint32_t off = (uint32_t)((kRow + j2 * 16) * 128 + (ks * 2 + kHalf) * 16);
                uint32_t r0, r1, r2, r3;
                ldsm_x4(r0, r1, r2, r3, stK + 8192u + sw128(off));
                kf[j2 * 2][0] = r0; kf[j2 * 2][1] = r1;
                kf[j2 * 2 + 1][0] = r2; kf[j2 * 2 + 1][1] = r3;
            }
            #pragma unroll
            for (int nt = 0; nt < 8; nt++)
                mma16816(sa[nt], qh[ks], kf[nt]);
        }

        // ---- scale (+ masks only on boundary tiles) ----
        int jbase = j * 64;
        bool interior = (jbase + 64 <= qbase) && (jbase + 64 <= len);
        if (interior) {
            #pragma unroll
            for (int nt = 0; nt < 8; nt++) {
                sa[nt][0] *= cs; sa[nt][1] *= cs;
                sa[nt][2] *= cs; sa[nt][3] *= cs;
            }
        } else {
            #pragma unroll
            for (int nt = 0; nt < 8; nt++) {
                int cl = nt * 8 + tig * 2;
                int kg = jbase + cl;
                int msk0 = s_mk[s][cl];
                int msk1 = s_mk[s][cl + 1];
                float v0 = sa[nt][0] * cs, v1 = sa[nt][1] * cs;
                float v2 = sa[nt][2] * cs, v3 = sa[nt][3] * cs;
                if (kg > qg0 || msk0)     v0 = -1e30f;
                if (kg + 1 > qg0 || msk1) v1 = -1e30f;
                if (kg > qg1 || msk0)     v2 = -1e30f;
                if (kg + 1 > qg1 || msk1) v3 = -1e30f;
                sa[nt][0] = v0; sa[nt][1] = v1; sa[nt][2] = v2; sa[nt][3] = v3;
            }
        }

        float rmax0 = -1e30f, rmax1 = -1e30f;
        #pragma unroll
        for (int nt = 0; nt < 8; nt++) {
            rmax0 = fmaxf(rmax0, fmaxf(sa[nt][0], sa[nt][1]));
            rmax1 = fmaxf(rmax1, fmaxf(sa[nt][2], sa[nt][3]));
        }
        rmax0 = fmaxf(rmax0, __shfl_xor_sync(0xffffffffu, rmax0, 1));
        rmax0 = fmaxf(rmax0, __shfl_xor_sync(0xffffffffu, rmax0, 2));
        rmax1 = fmaxf(rmax1, __shfl_xor_sync(0xffffffffu, rmax1, 1));
        rmax1 = fmaxf(rmax1, __shfl_xor_sync(0xffffffffu, rmax1, 2));
        float mn0 = fmaxf(m0, rmax0), mn1 = fmaxf(m1, rmax1);
        float f0 = ex2(m0 - mn0), f1 = ex2(m1 - mn1);
        float ps0 = 0.f, ps1 = 0.f;
        #pragma unroll
        for (int nt = 0; nt < 8; nt++) {
            float p0 = ex2(sa[nt][0] - mn0);
            float p1 = ex2(sa[nt][1] - mn0);
            float p2 = ex2(sa[nt][2] - mn1);
            float p3 = ex2(sa[nt][3] - mn1);
            ps0 += p0 + p1; ps1 += p2 + p3;
            sa[nt][0] = p0; sa[nt][1] = p1; sa[nt][2] = p2; sa[nt][3] = p3;
        }
        ps0 += __shfl_xor_sync(0xffffffffu, ps0, 1);
        ps0 += __shfl_xor_sync(0xffffffffu, ps0, 2);
        ps1 += __shfl_xor_sync(0xffffffffu, ps1, 1);
        ps1 += __shfl_xor_sync(0xffffffffu, ps1, 2);
        l0 = l0 * f0 + ps0; m0 = mn0;
        l1 = l1 * f1 + ps1; m1 = mn1;
        #pragma unroll
        for (int nt = 0; nt < 8; nt++) {
            o[nt][0] *= f0; o[nt][1] *= f0;
            o[nt][2] *= f1; o[nt][3] *= f1;
        }

        uint32_t phi[4][4], plo[4][4];
        #pragma unroll
        for (int ks = 0; ks < 4; ks++) {
            split2(sa[2 * ks][0],     sa[2 * ks][1],     phi[ks][0], plo[ks][0]);
            split2(sa[2 * ks][2],     sa[2 * ks][3],     phi[ks][1], plo[ks][1]);
            split2(sa[2 * ks + 1][0], sa[2 * ks + 1][1], phi[ks][2], plo[ks][2]);
            split2(sa[2 * ks + 1][2], sa[2 * ks + 1][3], phi[ks][3], plo[ks][3]);
        }

        #pragma unroll
        for (int ks = 0; ks < 4; ks++) {
            int vrow = ks * 16 + vRowL;
            uint32_t vf[8][2];
            #pragma unroll
            for (int g = 0; g < 4; g++) {
                uint32_t off = (uint32_t)(vrow * 128 + g * 32 + vHalf * 16);
                uint32_t r0, r1, r2, r3;
                ldsm_x4t(r0, r1, r2, r3, stV + sw128(off));
                vf[g * 2][0] = r0; vf[g * 2][1] = r1;
                vf[g * 2 + 1][0] = r2; vf[g * 2 + 1][1] = r3;
            }
            #pragma unroll
            for (int nt = 0; nt < 8; nt++) {
                mma16816(o[nt], phi[ks], vf[nt]);
                mma16816(o[nt], plo[ks], vf[nt]);
            }
            #pragma unroll
            for (int g = 0; g < 4; g++) {
                uint32_t off = (uint32_t)(vrow * 128 + g * 32 + vHalf * 16);
                uint32_t r0, r1, r2, r3;
                ldsm_x4t(r0, r1, r2, r3, stV + 8192u + sw128(off));
                vf[g * 2][0] = r0; vf[g * 2][1] = r1;
                vf[g * 2 + 1][0] = r2; vf[g * 2 + 1][1] = r3;
            }
            #pragma unroll
            for (int nt = 0; nt < 8; nt++)
                mma16816(o[nt], phi[ks], vf[nt]);
        }

        __syncthreads();
        if (j + 2 < ntiles) { issue(j + 2, s); issued++; }
    }

    float inv0 = 1.0f / l0, inv1 = 1.0f / l1;
    #pragma unroll
    for (int nt = 0; nt < 8; nt++) {
        int d = nt * 8 + tig * 2;
        int col = h * HDIM + d;
        size_t i0 = ((size_t)b * LL + qg0) * DD + col;
        size_t i1 = ((size_t)b * LL + qg1) * DD + col;
        uint32_t hi2, lo2;
        split2(o[nt][0] * inv0, o[nt][1] * inv0, hi2, lo2);
        *(uint32_t*)(g_aHi + i0) = hi2;
        *(uint32_t*)(g_aLo + i0) = lo2;
        split2(o[nt][2] * inv1, o[nt][3] * inv1, hi2, lo2);
        *(uint32_t*)(g_aHi + i1) = hi2;
        *(uint32_t*)(g_aLo + i1) = lo2;
    }
}

// ---------------- launch ----------------
extern "C" void kernel_launch(void* const* d_in, const int* in_sizes, int n_in,
                              void* d_out, int out_size) {
    const float* x  = (const float*)d_in[0];
    const unsigned char* pm = (const unsigned char*)d_in[1];
    const float* Wq = (const float*)d_in[3];
    const float* bq = (const float*)d_in[4];
    const float* Wk = (const float*)d_in[5];
    const float* bk = (const float*)d_in[6];
    const float* Wv = (const float*)d_in[7];
    const float* bv = (const float*)d_in[8];
    const float* Wo = (const float*)d_in[9];
    const float* bo = (const float*)d_in[10];
    const float* g_pre = (const float*)d_in[11];
    const float* b_pre = (const float*)d_in[12];
    const float* g_ln  = (const float*)d_in[13];
    const float* b_ln  = (const float*)d_in[14];
    float* out = (float*)d_out;

    float *py;
    __nv_bfloat16 *phHi, *phLo, *paHi, *paLo, *pwHi, *pwLo;
    __nv_bfloat16 *pqHi, *pqLo, *pkHi, *pkLo, *pvHi, *pvLo;
    cudaGetSymbolAddress((void**)&py,   g_y);
    cudaGetSymbolAddress((void**)&phHi, g_hHi);
    cudaGetSymbolAddress((void**)&phLo, g_hLo);
    cudaGetSymbolAddress((void**)&paHi, g_aHi);
    cudaGetSymbolAddress((void**)&paLo, g_aLo);
    cudaGetSymbolAddress((void**)&pwHi, g_wHi);
    cudaGetSymbolAddress((void**)&pwLo, g_wLo);
    cudaGetSymbolAddress((void**)&pqHi, g_qHi);
    cudaGetSymbolAddress((void**)&pqLo, g_qLo);
    cudaGetSymbolAddress((void**)&pkHi, g_kHi);
    cudaGetSymbolAddress((void**)&pkLo, g_kLo);
    cudaGetSymbolAddress((void**)&pvHi, g_vHi);
    cudaGetSymbolAddress((void**)&pvLo, g_vLo);

    cudaFuncSetAttribute(gemm_mma<0>, cudaFuncAttributeMaxDynamicSharedMemorySize, GSMEM);
    cudaFuncSetAttribute(gemm_mma<1>, cudaFuncAttributeMaxDynamicSharedMemorySize, GSMEM);
    cudaFuncSetAttribute(attn_mma, cudaFuncAttributeMaxDynamicSharedMemorySize, ASMEM);

    convert_mask_kernel<<<1, 256>>>(pm);

    // pre-LN: write ONLY bf16 hi/lo (residual reconstructed later from hi+lo)
    ln_kernel<<<NROWS, 256>>>(x, nullptr, nullptr, g_pre, b_pre, nullptr, phHi, phLo);

    // weight splits, single launch
    const int nW = DD * DD;
    split_w_kernel<<<dim3(nW / 1024, 4), 256>>>(Wq, Wk, Wv, Wo, pwHi, pwLo);

    // QKV projections -> bf16 hi/lo (B,H,L,HD), single launch over z = {q,k,v}
    dim3 gqkv(DD / 128, NROWS / 128, 3);
    gemm_mma<1><<<gqkv, 256, GSMEM>>>(phHi, phLo, pwHi, pwLo,
                                      bq, bk, bv, nullptr,
                                      pqHi, pqLo, pkHi, pkLo, pvHi, pvLo);

    // tensor-core flash attention
    attn_mma<<<dim3(LL / 128, BB * HH), 256, ASMEM>>>();

    // output projection
    dim3 gproj(DD / 128, NROWS / 128, 1);
    gemm_mma<0><<<gproj, 256, GSMEM>>>(paHi, paLo, pwHi + 3 * (size_t)nW, pwLo + 3 * (size_t)nW,
                                       bo, bo, bo, py,
                                       nullptr, nullptr, nullptr, nullptr, nullptr, nullptr);

    // residual (hi+lo reconstruct) + final LN
    ln_kernel<<<NROWS, 256>>>(py, phHi, phLo, g_ln, b_ln, out, nullptr, nullptr);
}